// round 9
// baseline (speedup 1.0000x reference)
#include <cuda_runtime.h>
#include <cuda_bf16.h>
#include <math.h>
#include <stdint.h>

#define MTOK 4096      // B*S
#define HID  2048
#define INTER 8192

// ======================= device scratch (no allocations) ====================
__device__ __nv_bfloat16 w_q_hi[HID*HID],  w_q_lo[HID*HID];
__device__ __nv_bfloat16 w_k_hi[HID*HID],  w_k_lo[HID*HID];
__device__ __nv_bfloat16 w_v_hi[HID*HID],  w_v_lo[HID*HID];
__device__ __nv_bfloat16 w_o_hi[HID*HID],  w_o_lo[HID*HID];
__device__ __nv_bfloat16 w_g_hi[(size_t)INTER*HID], w_g_lo[(size_t)INTER*HID];
__device__ __nv_bfloat16 w_u_hi[(size_t)INTER*HID], w_u_lo[(size_t)INTER*HID];
__device__ __nv_bfloat16 w_d_hi[(size_t)HID*INTER], w_d_lo[(size_t)HID*INTER];
__device__ __nv_bfloat16 a_x_hi[MTOK*HID],  a_x_lo[MTOK*HID];
__device__ __nv_bfloat16 a_at_hi[MTOK*HID], a_at_lo[MTOK*HID];
__device__ __nv_bfloat16 a_m_hi[(size_t)MTOK*INTER], a_m_lo[(size_t)MTOK*INTER];
__device__ __nv_bfloat16 q_bhi[MTOK*HID], q_blo[MTOK*HID];
__device__ __nv_bfloat16 k_bhi[MTOK*HID], k_blo[MTOK*HID];
__device__ __nv_bfloat16 v_bhi[MTOK*HID], v_blo[MTOK*HID];
__device__ __nv_bfloat16 vt_hi[MTOK*HID], vt_lo[MTOK*HID];   // [b*16+h][hd][kv]
__device__ float s_h1[MTOK*HID];
__device__ float s_g [(size_t)MTOK*INTER];
__device__ float s_u [(size_t)MTOK*INTER];

// ======================= helpers ============================================
__device__ __forceinline__ uint32_t smem_u32(const void* p) {
    uint32_t a;
    asm("{ .reg .u64 t; cvta.to.shared.u64 t, %1; cvt.u32.u64 %0, t; }" : "=r"(a) : "l"(p));
    return a;
}
__device__ __forceinline__ void cp16(uint32_t s, const void* g) {
    asm volatile("cp.async.cg.shared.global [%0], [%1], 16;" :: "r"(s), "l"(g));
}
#define CP_COMMIT() asm volatile("cp.async.commit_group;")
#define CP_WAIT(N)  asm volatile("cp.async.wait_group %0;" :: "n"(N))

__device__ __forceinline__ void mma_bf16(float* c, const uint32_t* a, const uint32_t* b) {
    asm volatile(
        "mma.sync.aligned.m16n8k16.row.col.f32.bf16.bf16.f32 "
        "{%0,%1,%2,%3}, {%4,%5,%6,%7}, {%8,%9}, {%0,%1,%2,%3};"
        : "+f"(c[0]), "+f"(c[1]), "+f"(c[2]), "+f"(c[3])
        : "r"(a[0]), "r"(a[1]), "r"(a[2]), "r"(a[3]), "r"(b[0]), "r"(b[1]));
}
__device__ __forceinline__ void split2(float x, float y, uint32_t& hi, uint32_t& lo) {
    __nv_bfloat162 h;
    h.x = __float2bfloat16(x); h.y = __float2bfloat16(y);
    __nv_bfloat162 l;
    l.x = __float2bfloat16(x - __bfloat162float(h.x));
    l.y = __float2bfloat16(y - __bfloat162float(h.y));
    hi = *reinterpret_cast<uint32_t*>(&h);
    lo = *reinterpret_cast<uint32_t*>(&l);
}

// ======================= bf16x3 mma.sync GEMM (round-8 core) ================
// OM: 0 = fp32 out, 1 = fp32 out + residual, 2 = bf16 hi/lo out (scaled)
// Block tile 256x128, BK=64, 256 threads (8 warps: 4 M x 2 N), warp tile 64x64.
#define RB    144
#define ATILE (256*RB)
#define BTILE (128*RB)
#define STG   (2*ATILE + 2*BTILE)  // 110592
#define GEMM_SMEM (2*STG)          // 221184

template<int OM>
__global__ __launch_bounds__(256) void gemm3bf(
    const __nv_bfloat16* __restrict__ Ahi, const __nv_bfloat16* __restrict__ Alo,
    const __nv_bfloat16* __restrict__ Bhi, const __nv_bfloat16* __restrict__ Blo,
    const float* __restrict__ R, float* __restrict__ C,
    __nv_bfloat16* __restrict__ Ch, __nv_bfloat16* __restrict__ Cl,
    float scale, int M, int N, int K)
{
    extern __shared__ char sm[];
    const uint32_t sbase = smem_u32(sm);

    const int tid = threadIdx.x;
    const int lane = tid & 31;
    const int wid = tid >> 5;
    const int g = lane >> 2, tig = lane & 3;
    const int warp_m = wid & 3;
    const int warp_n = wid >> 2;
    const int bm = blockIdx.y * 256;
    const int bn = blockIdx.x * 128;

    const int crow = tid >> 3;
    const int ccolB = (tid & 7) * 16;

    const int S = K >> 6;

    auto load_stage = [&](int s) {
        const uint32_t b = sbase + (uint32_t)(s & 1) * STG;
        const int k0 = s << 6;
        const size_t ga = ((size_t)(bm + crow) * K + k0) * 2 + ccolB;
        const size_t gb = ((size_t)(bn + crow) * K + k0) * 2 + ccolB;
        const size_t rstep = (size_t)32 * K * 2;
        const char* pah = (const char*)Ahi + ga;
        const char* pal = (const char*)Alo + ga;
        const char* pbh = (const char*)Bhi + gb;
        const char* pbl = (const char*)Blo + gb;
        #pragma unroll
        for (int i = 0; i < 8; i++) {
            const uint32_t so = (uint32_t)((crow + 32*i) * RB + ccolB);
            cp16(b + so,         pah); pah += rstep;
            cp16(b + ATILE + so, pal); pal += rstep;
        }
        #pragma unroll
        for (int i = 0; i < 4; i++) {
            const uint32_t so = (uint32_t)((crow + 32*i) * RB + ccolB);
            cp16(b + 2*ATILE + so,         pbh); pbh += rstep;
            cp16(b + 2*ATILE + BTILE + so, pbl); pbl += rstep;
        }
        CP_COMMIT();
    };

    load_stage(0);
    if (S > 1) load_stage(1);

    float acc[4][8][4];
    #pragma unroll
    for (int mt = 0; mt < 4; mt++)
        #pragma unroll
        for (int nt = 0; nt < 8; nt++)
            #pragma unroll
            for (int e = 0; e < 4; e++) acc[mt][nt][e] = 0.f;

    const int arow0 = warp_m * 64 + g;
    const int brow0 = warp_n * 64 + g;

    for (int s = 0; s < S; ++s) {
        if (s + 1 < S) { CP_WAIT(1); } else { CP_WAIT(0); }
        __syncthreads();
        const char* b = sm + (size_t)(s & 1) * STG;

        #pragma unroll
        for (int ks = 0; ks < 4; ++ks) {
            const int kb = ks * 32 + tig * 4;

            uint32_t bhf[8][2], blf[8][2];
            #pragma unroll
            for (int nt = 0; nt < 8; nt++) {
                const char* rb = b + 2*ATILE + (brow0 + nt*8) * RB + kb;
                bhf[nt][0] = *(const uint32_t*)(rb);
                bhf[nt][1] = *(const uint32_t*)(rb + 16);
                blf[nt][0] = *(const uint32_t*)(rb + BTILE);
                blf[nt][1] = *(const uint32_t*)(rb + BTILE + 16);
            }

            #pragma unroll
            for (int mt = 0; mt < 4; mt++) {
                uint32_t ah[4], al[4];
                const char* ra = b + (arow0 + mt*16) * RB + kb;
                ah[0] = *(const uint32_t*)(ra);
                ah[1] = *(const uint32_t*)(ra + 8*RB);
                ah[2] = *(const uint32_t*)(ra + 16);
                ah[3] = *(const uint32_t*)(ra + 8*RB + 16);
                al[0] = *(const uint32_t*)(ra + ATILE);
                al[1] = *(const uint32_t*)(ra + ATILE + 8*RB);
                al[2] = *(const uint32_t*)(ra + ATILE + 16);
                al[3] = *(const uint32_t*)(ra + ATILE + 8*RB + 16);

                #pragma unroll
                for (int nt = 0; nt < 8; nt++)
                    mma_bf16(acc[mt][nt], ah, bhf[nt]);
                #pragma unroll
                for (int nt = 0; nt < 8; nt++)
                    mma_bf16(acc[mt][nt], ah, blf[nt]);
                #pragma unroll
                for (int nt = 0; nt < 8; nt++)
                    mma_bf16(acc[mt][nt], al, bhf[nt]);
            }
        }
        __syncthreads();
        if (s + 2 < S) load_stage(s + 2);
    }

    const int row0 = bm + warp_m*64 + g;
    const int col0 = bn + warp_n*64 + tig*2;
    #pragma unroll
    for (int mt = 0; mt < 4; mt++) {
        #pragma unroll
        for (int nt = 0; nt < 8; nt++) {
            const int r = row0 + mt*16;
            const int c = col0 + nt*8;
            if (OM == 2) {
                uint32_t h0, l0u, h1, l1u;
                split2(acc[mt][nt][0]*scale, acc[mt][nt][1]*scale, h0, l0u);
                split2(acc[mt][nt][2]*scale, acc[mt][nt][3]*scale, h1, l1u);
                *(uint32_t*)(Ch + (size_t)r * N + c)     = h0;
                *(uint32_t*)(Cl + (size_t)r * N + c)     = l0u;
                *(uint32_t*)(Ch + (size_t)(r+8) * N + c) = h1;
                *(uint32_t*)(Cl + (size_t)(r+8) * N + c) = l1u;
            } else {
                float2 v0 = make_float2(acc[mt][nt][0], acc[mt][nt][1]);
                float2 v1 = make_float2(acc[mt][nt][2], acc[mt][nt][3]);
                if (OM == 1) {
                    const float2 r0 = *(const float2*)(R + (size_t)r * N + c);
                    const float2 r1 = *(const float2*)(R + (size_t)(r+8) * N + c);
                    v0.x += r0.x; v0.y += r0.y;
                    v1.x += r1.x; v1.y += r1.y;
                }
                *(float2*)(C + (size_t)r * N + c)     = v0;
                *(float2*)(C + (size_t)(r+8) * N + c) = v1;
            }
        }
    }
}

// ======================= tensor-core causal flash attention =================
// (verbatim round 4/8)
#define RBQ 272
#define RBV 144
#define QT_BYTES (128*RBQ)
#define KT_BYTES (64*RBQ)
#define VT_BYTES (128*RBV)
#define STAGE_B  (2*KT_BYTES + 2*VT_BYTES)
#define ATTN_SMEM (2*QT_BYTES + 2*STAGE_B)

__global__ __launch_bounds__(256) void attn_mma_k(
    const __nv_bfloat16* __restrict__ qh, const __nv_bfloat16* __restrict__ ql,
    const __nv_bfloat16* __restrict__ kh, const __nv_bfloat16* __restrict__ kl,
    const __nv_bfloat16* __restrict__ vh, const __nv_bfloat16* __restrict__ vl,
    __nv_bfloat16* __restrict__ Oh, __nv_bfloat16* __restrict__ Ol)
{
    extern __shared__ char sm[];
    const uint32_t sb = smem_u32(sm);

    const int tid = threadIdx.x, lane = tid & 31, wid = tid >> 5;
    const int g = lane >> 2, tig = lane & 3;
    const int qt = 15 - blockIdx.x, h = blockIdx.y, b = blockIdx.z;
    const int ntiles = 2 * (qt + 1);

    {
        const size_t gq = ((size_t)(b*2048 + qt*128) * 2048 + h*128) * 2;
        #pragma unroll
        for (int i = 0; i < 16; i++) {
            const int c = tid + i*256;
            const int t = c >> 11;
            const int cc = c & 2047;
            const int row = cc >> 4, col = cc & 15;
            const char* gp = (const char*)(t ? ql : qh) + gq + (size_t)row*4096 + col*16;
            cp16(sb + (t ? QT_BYTES : 0) + row*RBQ + col*16, gp);
        }
        CP_COMMIT();
    }

    auto load_stage = [&](int kt) {
        const uint32_t base = sb + 2*QT_BYTES + (uint32_t)(kt & 1) * STAGE_B;
        const size_t gk = ((size_t)(b*2048 + kt*64) * 2048 + h*128) * 2;
        const size_t gv = (((size_t)((b*16 + h)*128)) * 2048 + kt*64) * 2;
        #pragma unroll
        for (int i = 0; i < 16; i++) {
            const int c = tid + i*256;
            const int sel = c >> 10;
            const int cc = c & 1023;
            if (sel < 2) {
                const int row = cc >> 4, col = cc & 15;
                const char* gp = (const char*)(sel ? kl : kh) + gk + (size_t)row*4096 + col*16;
                cp16(base + (sel ? KT_BYTES : 0) + row*RBQ + col*16, gp);
            } else {
                const int row = cc >> 3, col = cc & 7;
                const char* gp = (const char*)(sel == 3 ? vl : vh) + gv + (size_t)row*4096 + col*16;
                cp16(base + 2*KT_BYTES + (sel == 3 ? VT_BYTES : 0) + row*RBV + col*16, gp);
            }
        }
        CP_COMMIT();
    };

    load_stage(0);
    load_stage(1);

    float accO[16][4];
    #pragma unroll
    for (int nt = 0; nt < 16; nt++)
        #pragma unroll
        for (int e = 0; e < 4; e++) accO[nt][e] = 0.f;
    float m0 = -INFINITY, m1 = -INFINITY, l0 = 0.f, l1 = 0.f;

    const int row0 = wid * 16;
    const int qrow0 = qt*128 + row0 + g;

    for (int s = 0; s < ntiles; s++) {
        if (s + 1 < ntiles) { CP_WAIT(1); } else { CP_WAIT(0); }
        __syncthreads();
        const char* stg = sm + 2*QT_BYTES + (size_t)(s & 1) * STAGE_B;

        float accS[8][4];
        #pragma unroll
        for (int nt = 0; nt < 8; nt++)
            #pragma unroll
            for (int e = 0; e < 4; e++) accS[nt][e] = 0.f;

        #pragma unroll
        for (int ks = 0; ks < 8; ks++) {
            const int kb = ks*32 + tig*4;
            uint32_t ah[4], al[4], bh2[8][2], bl2[8][2];
            const char* ra = sm + (row0 + g)*RBQ + kb;
            ah[0] = *(const uint32_t*)(ra);
            ah[1] = *(const uint32_t*)(ra + 8*RBQ);
            ah[2] = *(const uint32_t*)(ra + 16);
            ah[3] = *(const uint32_t*)(ra + 8*RBQ + 16);
            al[0] = *(const uint32_t*)(ra + QT_BYTES);
            al[1] = *(const uint32_t*)(ra + QT_BYTES + 8*RBQ);
            al[2] = *(const uint32_t*)(ra + QT_BYTES + 16);
            al[3] = *(const uint32_t*)(ra + QT_BYTES + 8*RBQ + 16);
            #pragma unroll
            for (int nt = 0; nt < 8; nt++) {
                const char* rb = stg + (nt*8 + g)*RBQ + kb;
                bh2[nt][0] = *(const uint32_t*)(rb);
                bh2[nt][1] = *(const uint32_t*)(rb + 16);
                bl2[nt][0] = *(const uint32_t*)(rb + KT_BYTES);
                bl2[nt][1] = *(const uint32_t*)(rb + KT_BYTES + 16);
            }
            #pragma unroll
            for (int nt = 0; nt < 8; nt++) mma_bf16(accS[nt], ah, bh2[nt]);
            #pragma unroll
            for (int nt = 0; nt < 8; nt++) mma_bf16(accS[nt], ah, bl2[nt]);
            #pragma unroll
            for (int nt = 0; nt < 8; nt++) mma_bf16(accS[nt], al, bh2[nt]);
        }

        if (s >= ntiles - 2) {
            #pragma unroll
            for (int nt = 0; nt < 8; nt++) {
                const int col = s*64 + nt*8 + tig*2;
                if (col     > qrow0)     accS[nt][0] = -INFINITY;
                if (col + 1 > qrow0)     accS[nt][1] = -INFINITY;
                if (col     > qrow0 + 8) accS[nt][2] = -INFINITY;
                if (col + 1 > qrow0 + 8) accS[nt][3] = -INFINITY;
            }
        }

        float mt0 = -INFINITY, mt1 = -INFINITY;
        #pragma unroll
        for (int nt = 0; nt < 8; nt++) {
            mt0 = fmaxf(mt0, fmaxf(accS[nt][0], accS[nt][1]));
            mt1 = fmaxf(mt1, fmaxf(accS[nt][2], accS[nt][3]));
        }
        mt0 = fmaxf(mt0, __shfl_xor_sync(0xffffffffu, mt0, 1));
        mt0 = fmaxf(mt0, __shfl_xor_sync(0xffffffffu, mt0, 2));
        mt1 = fmaxf(mt1, __shfl_xor_sync(0xffffffffu, mt1, 1));
        mt1 = fmaxf(mt1, __shfl_xor_sync(0xffffffffu, mt1, 2));

        const float mn0 = fmaxf(m0, mt0), mn1 = fmaxf(m1, mt1);
        const float sc0 = __expf(m0 - mn0), sc1 = __expf(m1 - mn1);
        m0 = mn0; m1 = mn1;

        float rs0 = 0.f, rs1 = 0.f;
        #pragma unroll
        for (int nt = 0; nt < 8; nt++) {
            accS[nt][0] = __expf(accS[nt][0] - mn0);
            accS[nt][1] = __expf(accS[nt][1] - mn0);
            accS[nt][2] = __expf(accS[nt][2] - mn1);
            accS[nt][3] = __expf(accS[nt][3] - mn1);
            rs0 += accS[nt][0] + accS[nt][1];
            rs1 += accS[nt][2] + accS[nt][3];
        }
        rs0 += __shfl_xor_sync(0xffffffffu, rs0, 1);
        rs0 += __shfl_xor_sync(0xffffffffu, rs0, 2);
        rs1 += __shfl_xor_sync(0xffffffffu, rs1, 1);
        rs1 += __shfl_xor_sync(0xffffffffu, rs1, 2);
        l0 = l0*sc0 + rs0;
        l1 = l1*sc1 + rs1;

        #pragma unroll
        for (int nt = 0; nt < 16; nt++) {
            accO[nt][0] *= sc0; accO[nt][1] *= sc0;
            accO[nt][2] *= sc1; accO[nt][3] *= sc1;
        }

        #pragma unroll
        for (int kk = 0; kk < 4; kk++) {
            uint32_t ph[4], pl[4];
            split2(accS[2*kk][0],   accS[2*kk][1],   ph[0], pl[0]);
            split2(accS[2*kk][2],   accS[2*kk][3],   ph[1], pl[1]);
            split2(accS[2*kk+1][0], accS[2*kk+1][1], ph[2], pl[2]);
            split2(accS[2*kk+1][2], accS[2*kk+1][3], ph[3], pl[3]);
            const int kb = kk*32 + tig*4;
            #pragma unroll
            for (int nt = 0; nt < 16; nt++) {
                const char* rv = stg + 2*KT_BYTES + (nt*8 + g)*RBV + kb;
                uint32_t vbh[2], vbl[2];
                vbh[0] = *(const uint32_t*)(rv);
                vbh[1] = *(const uint32_t*)(rv + 16);
                vbl[0] = *(const uint32_t*)(rv + VT_BYTES);
                vbl[1] = *(const uint32_t*)(rv + VT_BYTES + 16);
                mma_bf16(accO[nt], ph, vbh);
                mma_bf16(accO[nt], ph, vbl);
                mma_bf16(accO[nt], pl, vbh);
            }
        }

        __syncthreads();
        if (s + 2 < ntiles) load_stage(s + 2);
    }

    const float inv0 = 1.f / l0, inv1 = 1.f / l1;
    const size_t ob = ((size_t)(b*2048 + qt*128 + row0 + g)) * 2048 + h*128;
    #pragma unroll
    for (int nt = 0; nt < 16; nt++) {
        const int c = nt*8 + tig*2;
        uint32_t h0, l0u, h1, l1u;
        split2(accO[nt][0]*inv0, accO[nt][1]*inv0, h0, l0u);
        split2(accO[nt][2]*inv1, accO[nt][3]*inv1, h1, l1u);
        *(uint32_t*)(Oh + ob + c)           = h0;
        *(uint32_t*)(Ol + ob + c)           = l0u;
        *(uint32_t*)(Oh + ob + 8*2048 + c)  = h1;
        *(uint32_t*)(Ol + ob + 8*2048 + c)  = l1u;
    }
}

// ======================= weight transpose + split (vectorized) ==============
// W[K][N] fp32 -> Thi/Tlo[N][K] bf16. Tile: 64 k x 32 n. Each thread writes
// one uint32 (two consecutive-k bf16) per output row -> coalesced 128B stores.
__global__ void transconv_k(const float* __restrict__ W,
                            __nv_bfloat16* __restrict__ Thi, __nv_bfloat16* __restrict__ Tlo,
                            int K, int N)
{
    __shared__ float t[64][33];
    const int n0 = blockIdx.x * 32, k0 = blockIdx.y * 64;
    const int tx = threadIdx.x, ty = threadIdx.y;
    #pragma unroll
    for (int r = ty; r < 64; r += 8)
        t[r][tx] = W[(size_t)(k0 + r) * N + n0 + tx];
    __syncthreads();
    #pragma unroll
    for (int i = ty; i < 32; i += 8) {
        const float v0 = t[2*tx][i];
        const float v1 = t[2*tx + 1][i];
        uint32_t hi, lo;
        split2(v0, v1, hi, lo);
        const size_t o = (size_t)(n0 + i) * K + k0 + 2*tx;   // even, uint32-aligned
        *(uint32_t*)(Thi + o) = hi;
        *(uint32_t*)(Tlo + o) = lo;
    }
}

// ======================= V transpose (bf16 hi/lo pair) ======================
// Vh/Vl: [tok][2048] -> Th/Tl: [b*16+h][hd][kv=2048]
__global__ void vtrans_bf_k(const __nv_bfloat16* __restrict__ Vh,
                            const __nv_bfloat16* __restrict__ Vl,
                            __nv_bfloat16* __restrict__ Th, __nv_bfloat16* __restrict__ Tl)
{
    __shared__ __nv_bfloat16 th[32][33], tl[32][33];
    const int kv0 = blockIdx.x * 32, hd0 = blockIdx.y * 32, bh = blockIdx.z;
    const int b = bh >> 4, h = bh & 15;
    const int tx = threadIdx.x, ty = threadIdx.y;
    #pragma unroll
    for (int i = ty; i < 32; i += 8) {
        const size_t src = (size_t)(b*2048 + kv0 + i) * 2048 + h*128 + hd0 + tx;
        th[i][tx] = Vh[src];
        tl[i][tx] = Vl[src];
    }
    __syncthreads();
    #pragma unroll
    for (int i = ty; i < 32; i += 8) {
        const size_t o = ((size_t)(bh*128 + hd0 + i)) * 2048 + kv0 + tx;
        Th[o] = th[tx][i];
        Tl[o] = tl[tx][i];
    }
}

// ======================= RMSNorm -> bf16 hi/lo ==============================
__global__ __launch_bounds__(256) void rmsnorm_conv_k(
    const float* __restrict__ x, const float* __restrict__ w,
    __nv_bfloat16* __restrict__ yh, __nv_bfloat16* __restrict__ yl)
{
    const int row = blockIdx.x;
    const float4* xr = (const float4*)(x + (size_t)row * HID);
    const float4* w4 = (const float4*)w;

    float4 v0 = xr[threadIdx.x];
    float4 v1 = xr[threadIdx.x + 256];
    float ss = v0.x*v0.x + v0.y*v0.y + v0.z*v0.z + v0.w*v0.w
             + v1.x*v1.x + v1.y*v1.y + v1.z*v1.z + v1.w*v1.w;
    #pragma unroll
    for (int off = 16; off > 0; off >>= 1) ss += __shfl_xor_sync(0xffffffffu, ss, off);

    __shared__ float red[8]; __shared__ float s_inv;
    if ((threadIdx.x & 31) == 0) red[threadIdx.x >> 5] = ss;
    __syncthreads();
    if (threadIdx.x == 0) {
        float t = 0.f;
        #pragma unroll
        for (int i = 0; i < 8; i++) t += red[i];
        s_inv = rsqrtf(t * (1.f / (float)HID) + 1e-6f);
    }
    __syncthreads();
    const float inv = s_inv;

    const float4 w0 = w4[threadIdx.x], w1 = w4[threadIdx.x + 256];
    float o[8] = { v0.x*inv*w0.x, v0.y*inv*w0.y, v0.z*inv*w0.z, v0.w*inv*w0.w,
                   v1.x*inv*w1.x, v1.y*inv*w1.y, v1.z*inv*w1.z, v1.w*inv*w1.w };
    const size_t b0 = (size_t)row * HID + threadIdx.x * 4;
    const size_t b1 = (size_t)row * HID + (threadIdx.x + 256) * 4;
    #pragma unroll
    for (int j = 0; j < 4; j++) {
        __nv_bfloat16 h = __float2bfloat16(o[j]);
        yh[b0 + j] = h; yl[b0 + j] = __float2bfloat16(o[j] - __bfloat162float(h));
    }
    #pragma unroll
    for (int j = 0; j < 4; j++) {
        __nv_bfloat16 h = __float2bfloat16(o[4 + j]);
        yh[b1 + j] = h; yl[b1 + j] = __float2bfloat16(o[4 + j] - __bfloat162float(h));
    }
}

// ======================= silu(g)*u -> bf16 hi/lo ============================
__global__ void silu_conv_k(const float* __restrict__ g, const float* __restrict__ u,
                            __nv_bfloat16* __restrict__ mh, __nv_bfloat16* __restrict__ ml,
                            int n4)
{
    int i = blockIdx.x * 256 + threadIdx.x;
    if (i < n4) {
        float4 gv = ((const float4*)g)[i];
        float4 uv = ((const float4*)u)[i];
        float r[4];
        r[0] = gv.x / (1.f + __expf(-gv.x)) * uv.x;
        r[1] = gv.y / (1.f + __expf(-gv.y)) * uv.y;
        r[2] = gv.z / (1.f + __expf(-gv.z)) * uv.z;
        r[3] = gv.w / (1.f + __expf(-gv.w)) * uv.w;
        const size_t b = (size_t)i * 4;
        #pragma unroll
        for (int j = 0; j < 4; j++) {
            __nv_bfloat16 h = __float2bfloat16(r[j]);
            mh[b + j] = h; ml[b + j] = __float2bfloat16(r[j] - __bfloat162float(h));
        }
    }
}

// ======================= launch =============================================
extern "C" void kernel_launch(void* const* d_in, const int* in_sizes, int n_in,
                              void* d_out, int out_size)
{
    const float* hidden = (const float*)d_in[0];
    const float* wq  = (const float*)d_in[1];
    const float* wk  = (const float*)d_in[2];
    const float* wv  = (const float*)d_in[3];
    const float* wo  = (const float*)d_in[4];
    const float* wg  = (const float*)d_in[5];
    const float* wu  = (const float*)d_in[6];
    const float* wd  = (const float*)d_in[7];
    const float* ln1 = (const float*)d_in[8];
    const float* ln2 = (const float*)d_in[9];

    __nv_bfloat16 *pwq_h,*pwq_l,*pwk_h,*pwk_l,*pwv_h,*pwv_l,*pwo_h,*pwo_l;
    __nv_bfloat16 *pwg_h,*pwg_l,*pwu_h,*pwu_l,*pwd_h,*pwd_l;
    __nv_bfloat16 *px_h,*px_l,*pat_h,*pat_l,*pm_h,*pm_l;
    __nv_bfloat16 *pq_h,*pq_l,*pk_h,*pk_l,*pv_h,*pv_l,*pvt_h,*pvt_l;
    float *h1,*g,*u;
    cudaGetSymbolAddress((void**)&pwq_h, w_q_hi); cudaGetSymbolAddress((void**)&pwq_l, w_q_lo);
    cudaGetSymbolAddress((void**)&pwk_h, w_k_hi); cudaGetSymbolAddress((void**)&pwk_l, w_k_lo);
    cudaGetSymbolAddress((void**)&pwv_h, w_v_hi); cudaGetSymbolAddress((void**)&pwv_l, w_v_lo);
    cudaGetSymbolAddress((void**)&pwo_h, w_o_hi); cudaGetSymbolAddress((void**)&pwo_l, w_o_lo);
    cudaGetSymbolAddress((void**)&pwg_h, w_g_hi); cudaGetSymbolAddress((void**)&pwg_l, w_g_lo);
    cudaGetSymbolAddress((void**)&pwu_h, w_u_hi); cudaGetSymbolAddress((void**)&pwu_l, w_u_lo);
    cudaGetSymbolAddress((void**)&pwd_h, w_d_hi); cudaGetSymbolAddress((void**)&pwd_l, w_d_lo);
    cudaGetSymbolAddress((void**)&px_h,  a_x_hi); cudaGetSymbolAddress((void**)&px_l,  a_x_lo);
    cudaGetSymbolAddress((void**)&pat_h, a_at_hi);cudaGetSymbolAddress((void**)&pat_l, a_at_lo);
    cudaGetSymbolAddress((void**)&pm_h,  a_m_hi); cudaGetSymbolAddress((void**)&pm_l,  a_m_lo);
    cudaGetSymbolAddress((void**)&pq_h,  q_bhi);  cudaGetSymbolAddress((void**)&pq_l,  q_blo);
    cudaGetSymbolAddress((void**)&pk_h,  k_bhi);  cudaGetSymbolAddress((void**)&pk_l,  k_blo);
    cudaGetSymbolAddress((void**)&pv_h,  v_bhi);  cudaGetSymbolAddress((void**)&pv_l,  v_blo);
    cudaGetSymbolAddress((void**)&pvt_h, vt_hi);  cudaGetSymbolAddress((void**)&pvt_l, vt_lo);
    cudaGetSymbolAddress((void**)&h1, s_h1);
    cudaGetSymbolAddress((void**)&g,  s_g);  cudaGetSymbolAddress((void**)&u,  s_u);

    cudaFuncSetAttribute(gemm3bf<0>, cudaFuncAttributeMaxDynamicSharedMemorySize, GEMM_SMEM);
    cudaFuncSetAttribute(gemm3bf<1>, cudaFuncAttributeMaxDynamicSharedMemorySize, GEMM_SMEM);
    cudaFuncSetAttribute(gemm3bf<2>, cudaFuncAttributeMaxDynamicSharedMemorySize, GEMM_SMEM);
    cudaFuncSetAttribute(attn_mma_k, cudaFuncAttributeMaxDynamicSharedMemorySize, ATTN_SMEM);

    // weight transpose+split (vectorized: grid.y = K/64 now)
    dim3 tb(32, 8);
    transconv_k<<<dim3(HID/32,  HID/64),  tb>>>(wq, pwq_h, pwq_l, HID, HID);
    transconv_k<<<dim3(HID/32,  HID/64),  tb>>>(wk, pwk_h, pwk_l, HID, HID);
    transconv_k<<<dim3(HID/32,  HID/64),  tb>>>(wv, pwv_h, pwv_l, HID, HID);
    transconv_k<<<dim3(HID/32,  HID/64),  tb>>>(wo, pwo_h, pwo_l, HID, HID);
    transconv_k<<<dim3(INTER/32,HID/64),  tb>>>(wg, pwg_h, pwg_l, HID, INTER);
    transconv_k<<<dim3(INTER/32,HID/64),  tb>>>(wu, pwu_h, pwu_l, HID, INTER);
    transconv_k<<<dim3(HID/32,  INTER/64),tb>>>(wd, pwd_h, pwd_l, INTER, HID);

    // 1) rmsnorm -> bf16 hi/lo
    rmsnorm_conv_k<<<MTOK, 256>>>(hidden, ln1, px_h, px_l);

    // 2) QKV projections (block 256x128); all emit bf16 hi/lo
    const float sc = 0.08838834764831845f;
    dim3 gHH(HID/128, MTOK/256);   // (16, 16)
    gemm3bf<2><<<gHH, 256, GEMM_SMEM>>>(px_h, px_l, pwq_h, pwq_l, nullptr, nullptr,
                                        pq_h, pq_l, sc, MTOK, HID, HID);
    gemm3bf<2><<<gHH, 256, GEMM_SMEM>>>(px_h, px_l, pwk_h, pwk_l, nullptr, nullptr,
                                        pk_h, pk_l, 1.f, MTOK, HID, HID);
    gemm3bf<2><<<gHH, 256, GEMM_SMEM>>>(px_h, px_l, pwv_h, pwv_l, nullptr, nullptr,
                                        pv_h, pv_l, 1.f, MTOK, HID, HID);
    vtrans_bf_k<<<dim3(64, 4, 32), tb>>>(pv_h, pv_l, pvt_h, pvt_l);

    // 3) tensor-core attention -> bf16 hi/lo
    attn_mma_k<<<dim3(16, 16, 2), 256, ATTN_SMEM>>>(pq_h, pq_l, pk_h, pk_l,
                                                    pvt_h, pvt_l, pat_h, pat_l);

    // 4) O-proj + residual
    gemm3bf<1><<<gHH, 256, GEMM_SMEM>>>(pat_h, pat_l, pwo_h, pwo_l, hidden, h1,
                                        nullptr, nullptr, 1.f, MTOK, HID, HID);

    // 5) rmsnorm2 -> bf16 hi/lo
    rmsnorm_conv_k<<<MTOK, 256>>>(h1, ln2, px_h, px_l);

    // 6) MLP
    dim3 gHI(INTER/128, MTOK/256); // (64, 16)
    gemm3bf<0><<<gHI, 256, GEMM_SMEM>>>(px_h, px_l, pwg_h, pwg_l, nullptr, g,
                                        nullptr, nullptr, 1.f, MTOK, INTER, HID);
    gemm3bf<0><<<gHI, 256, GEMM_SMEM>>>(px_h, px_l, pwu_h, pwu_l, nullptr, u,
                                        nullptr, nullptr, 1.f, MTOK, INTER, HID);

    const int n4 = (int)(((size_t)MTOK * INTER) / 4);
    silu_conv_k<<<(n4 + 255)/256, 256>>>(g, u, pm_h, pm_l, n4);

    gemm3bf<1><<<gHH, 256, GEMM_SMEM>>>(pm_h, pm_l, pwd_h, pwd_l, h1, (float*)d_out,
                                        nullptr, nullptr, 1.f, MTOK, HID, INTER);
}

// round 10
// speedup vs baseline: 1.0036x; 1.0036x over previous
#include <cuda_runtime.h>
#include <cuda_bf16.h>
#include <math.h>
#include <stdint.h>

#define MTOK 4096      // B*S
#define HID  2048
#define INTER 8192

// ======================= device scratch (no allocations) ====================
__device__ __nv_bfloat16 w_q_hi[HID*HID],  w_q_lo[HID*HID];
__device__ __nv_bfloat16 w_k_hi[HID*HID],  w_k_lo[HID*HID];
__device__ __nv_bfloat16 w_v_hi[HID*HID],  w_v_lo[HID*HID];
__device__ __nv_bfloat16 w_o_hi[HID*HID],  w_o_lo[HID*HID];
__device__ __nv_bfloat16 w_gu_hi[(size_t)2*INTER*HID], w_gu_lo[(size_t)2*INTER*HID]; // interleaved: row 2j=gate j, 2j+1=up j
__device__ __nv_bfloat16 w_d_hi[(size_t)HID*INTER], w_d_lo[(size_t)HID*INTER];
__device__ __nv_bfloat16 a_x_hi[MTOK*HID],  a_x_lo[MTOK*HID];
__device__ __nv_bfloat16 a_at_hi[MTOK*HID], a_at_lo[MTOK*HID];
__device__ __nv_bfloat16 a_m_hi[(size_t)MTOK*INTER], a_m_lo[(size_t)MTOK*INTER];
__device__ __nv_bfloat16 q_bhi[MTOK*HID], q_blo[MTOK*HID];
__device__ __nv_bfloat16 k_bhi[MTOK*HID], k_blo[MTOK*HID];
__device__ __nv_bfloat16 v_bhi[MTOK*HID], v_blo[MTOK*HID];
__device__ __nv_bfloat16 vt_hi[MTOK*HID], vt_lo[MTOK*HID];   // [b*16+h][hd][kv]
__device__ float s_h1[MTOK*HID];

// ======================= helpers ============================================
__device__ __forceinline__ uint32_t smem_u32(const void* p) {
    uint32_t a;
    asm("{ .reg .u64 t; cvta.to.shared.u64 t, %1; cvt.u32.u64 %0, t; }" : "=r"(a) : "l"(p));
    return a;
}
__device__ __forceinline__ void cp16(uint32_t s, const void* g) {
    asm volatile("cp.async.cg.shared.global [%0], [%1], 16;" :: "r"(s), "l"(g));
}
#define CP_COMMIT() asm volatile("cp.async.commit_group;")
#define CP_WAIT(N)  asm volatile("cp.async.wait_group %0;" :: "n"(N))

__device__ __forceinline__ void mma_bf16(float* c, const uint32_t* a, const uint32_t* b) {
    asm volatile(
        "mma.sync.aligned.m16n8k16.row.col.f32.bf16.bf16.f32 "
        "{%0,%1,%2,%3}, {%4,%5,%6,%7}, {%8,%9}, {%0,%1,%2,%3};"
        : "+f"(c[0]), "+f"(c[1]), "+f"(c[2]), "+f"(c[3])
        : "r"(a[0]), "r"(a[1]), "r"(a[2]), "r"(a[3]), "r"(b[0]), "r"(b[1]));
}
__device__ __forceinline__ void split2(float x, float y, uint32_t& hi, uint32_t& lo) {
    __nv_bfloat162 h;
    h.x = __float2bfloat16(x); h.y = __float2bfloat16(y);
    __nv_bfloat162 l;
    l.x = __float2bfloat16(x - __bfloat162float(h.x));
    l.y = __float2bfloat16(y - __bfloat162float(h.y));
    hi = *reinterpret_cast<uint32_t*>(&h);
    lo = *reinterpret_cast<uint32_t*>(&l);
}

// ======================= bf16x3 mma.sync GEMM (round-8 core) ================
// OM: 0 = fp32 out, 1 = fp32 out + residual, 2 = bf16 hi/lo out (scaled),
//     3 = fused silu(even)*odd -> bf16 hi/lo out at column c/2 (Nout = N/2)
// Block tile 256x128, BK=64, 256 threads (8 warps: 4 M x 2 N), warp tile 64x64.
#define RB    144
#define ATILE (256*RB)
#define BTILE (128*RB)
#define STG   (2*ATILE + 2*BTILE)  // 110592
#define GEMM_SMEM (2*STG)          // 221184

template<int OM>
__global__ __launch_bounds__(256) void gemm3bf(
    const __nv_bfloat16* __restrict__ Ahi, const __nv_bfloat16* __restrict__ Alo,
    const __nv_bfloat16* __restrict__ Bhi, const __nv_bfloat16* __restrict__ Blo,
    const float* __restrict__ R, float* __restrict__ C,
    __nv_bfloat16* __restrict__ Ch, __nv_bfloat16* __restrict__ Cl,
    float scale, int M, int N, int K)
{
    extern __shared__ char sm[];
    const uint32_t sbase = smem_u32(sm);

    const int tid = threadIdx.x;
    const int lane = tid & 31;
    const int wid = tid >> 5;
    const int g = lane >> 2, tig = lane & 3;
    const int warp_m = wid & 3;
    const int warp_n = wid >> 2;
    const int bm = blockIdx.y * 256;
    const int bn = blockIdx.x * 128;

    const int crow = tid >> 3;
    const int ccolB = (tid & 7) * 16;

    const int S = K >> 6;

    auto load_stage = [&](int s) {
        const uint32_t b = sbase + (uint32_t)(s & 1) * STG;
        const int k0 = s << 6;
        const size_t ga = ((size_t)(bm + crow) * K + k0) * 2 + ccolB;
        const size_t gb = ((size_t)(bn + crow) * K + k0) * 2 + ccolB;
        const size_t rstep = (size_t)32 * K * 2;
        const char* pah = (const char*)Ahi + ga;
        const char* pal = (const char*)Alo + ga;
        const char* pbh = (const char*)Bhi + gb;
        const char* pbl = (const char*)Blo + gb;
        #pragma unroll
        for (int i = 0; i < 8; i++) {
            const uint32_t so = (uint32_t)((crow + 32*i) * RB + ccolB);
            cp16(b + so,         pah); pah += rstep;
            cp16(b + ATILE + so, pal); pal += rstep;
        }
        #pragma unroll
        for (int i = 0; i < 4; i++) {
            const uint32_t so = (uint32_t)((crow + 32*i) * RB + ccolB);
            cp16(b + 2*ATILE + so,         pbh); pbh += rstep;
            cp16(b + 2*ATILE + BTILE + so, pbl); pbl += rstep;
        }
        CP_COMMIT();
    };

    load_stage(0);
    if (S > 1) load_stage(1);

    float acc[4][8][4];
    #pragma unroll
    for (int mt = 0; mt < 4; mt++)
        #pragma unroll
        for (int nt = 0; nt < 8; nt++)
            #pragma unroll
            for (int e = 0; e < 4; e++) acc[mt][nt][e] = 0.f;

    const int arow0 = warp_m * 64 + g;
    const int brow0 = warp_n * 64 + g;

    for (int s = 0; s < S; ++s) {
        if (s + 1 < S) { CP_WAIT(1); } else { CP_WAIT(0); }
        __syncthreads();
        const char* b = sm + (size_t)(s & 1) * STG;

        #pragma unroll
        for (int ks = 0; ks < 4; ++ks) {
            const int kb = ks * 32 + tig * 4;

            uint32_t bhf[8][2], blf[8][2];
            #pragma unroll
            for (int nt = 0; nt < 8; nt++) {
                const char* rb = b + 2*ATILE + (brow0 + nt*8) * RB + kb;
                bhf[nt][0] = *(const uint32_t*)(rb);
                bhf[nt][1] = *(const uint32_t*)(rb + 16);
                blf[nt][0] = *(const uint32_t*)(rb + BTILE);
                blf[nt][1] = *(const uint32_t*)(rb + BTILE + 16);
            }

            #pragma unroll
            for (int mt = 0; mt < 4; mt++) {
                uint32_t ah[4], al[4];
                const char* ra = b + (arow0 + mt*16) * RB + kb;
                ah[0] = *(const uint32_t*)(ra);
                ah[1] = *(const uint32_t*)(ra + 8*RB);
                ah[2] = *(const uint32_t*)(ra + 16);
                ah[3] = *(const uint32_t*)(ra + 8*RB + 16);
                al[0] = *(const uint32_t*)(ra + ATILE);
                al[1] = *(const uint32_t*)(ra + ATILE + 8*RB);
                al[2] = *(const uint32_t*)(ra + ATILE + 16);
                al[3] = *(const uint32_t*)(ra + ATILE + 8*RB + 16);

                #pragma unroll
                for (int nt = 0; nt < 8; nt++)
                    mma_bf16(acc[mt][nt], ah, bhf[nt]);
                #pragma unroll
                for (int nt = 0; nt < 8; nt++)
                    mma_bf16(acc[mt][nt], ah, blf[nt]);
                #pragma unroll
                for (int nt = 0; nt < 8; nt++)
                    mma_bf16(acc[mt][nt], al, bhf[nt]);
            }
        }
        __syncthreads();
        if (s + 2 < S) load_stage(s + 2);
    }

    const int row0 = bm + warp_m*64 + g;
    const int col0 = bn + warp_n*64 + tig*2;
    #pragma unroll
    for (int mt = 0; mt < 4; mt++) {
        #pragma unroll
        for (int nt = 0; nt < 8; nt++) {
            const int r = row0 + mt*16;
            const int c = col0 + nt*8;
            if (OM == 3) {
                // c is even; acc[0]=gate(r,c), acc[1]=up(r,c+1->same logical col),
                // acc[2]/acc[3] same for row r+8. Output col = c/2, Nout = N/2.
                const int Nout = N >> 1;
                const int cc = c >> 1;
                const float g0 = acc[mt][nt][0], u0 = acc[mt][nt][1];
                const float g1 = acc[mt][nt][2], u1 = acc[mt][nt][3];
                const float r0 = g0 / (1.f + __expf(-g0)) * u0;
                const float r1 = g1 / (1.f + __expf(-g1)) * u1;
                const __nv_bfloat16 h0 = __float2bfloat16(r0);
                const __nv_bfloat16 h1 = __float2bfloat16(r1);
                Ch[(size_t)r * Nout + cc]     = h0;
                Cl[(size_t)r * Nout + cc]     = __float2bfloat16(r0 - __bfloat162float(h0));
                Ch[(size_t)(r+8) * Nout + cc] = h1;
                Cl[(size_t)(r+8) * Nout + cc] = __float2bfloat16(r1 - __bfloat162float(h1));
            } else if (OM == 2) {
                uint32_t h0, l0u, h1, l1u;
                split2(acc[mt][nt][0]*scale, acc[mt][nt][1]*scale, h0, l0u);
                split2(acc[mt][nt][2]*scale, acc[mt][nt][3]*scale, h1, l1u);
                *(uint32_t*)(Ch + (size_t)r * N + c)     = h0;
                *(uint32_t*)(Cl + (size_t)r * N + c)     = l0u;
                *(uint32_t*)(Ch + (size_t)(r+8) * N + c) = h1;
                *(uint32_t*)(Cl + (size_t)(r+8) * N + c) = l1u;
            } else {
                float2 v0 = make_float2(acc[mt][nt][0], acc[mt][nt][1]);
                float2 v1 = make_float2(acc[mt][nt][2], acc[mt][nt][3]);
                if (OM == 1) {
                    const float2 r0 = *(const float2*)(R + (size_t)r * N + c);
                    const float2 r1 = *(const float2*)(R + (size_t)(r+8) * N + c);
                    v0.x += r0.x; v0.y += r0.y;
                    v1.x += r1.x; v1.y += r1.y;
                }
                *(float2*)(C + (size_t)r * N + c)     = v0;
                *(float2*)(C + (size_t)(r+8) * N + c) = v1;
            }
        }
    }
}

// ======================= tensor-core causal flash attention =================
// (verbatim round 4/8)
#define RBQ 272
#define RBV 144
#define QT_BYTES (128*RBQ)
#define KT_BYTES (64*RBQ)
#define VT_BYTES (128*RBV)
#define STAGE_B  (2*KT_BYTES + 2*VT_BYTES)
#define ATTN_SMEM (2*QT_BYTES + 2*STAGE_B)

__global__ __launch_bounds__(256) void attn_mma_k(
    const __nv_bfloat16* __restrict__ qh, const __nv_bfloat16* __restrict__ ql,
    const __nv_bfloat16* __restrict__ kh, const __nv_bfloat16* __restrict__ kl,
    const __nv_bfloat16* __restrict__ vh, const __nv_bfloat16* __restrict__ vl,
    __nv_bfloat16* __restrict__ Oh, __nv_bfloat16* __restrict__ Ol)
{
    extern __shared__ char sm[];
    const uint32_t sb = smem_u32(sm);

    const int tid = threadIdx.x, lane = tid & 31, wid = tid >> 5;
    const int g = lane >> 2, tig = lane & 3;
    const int qt = 15 - blockIdx.x, h = blockIdx.y, b = blockIdx.z;
    const int ntiles = 2 * (qt + 1);

    {
        const size_t gq = ((size_t)(b*2048 + qt*128) * 2048 + h*128) * 2;
        #pragma unroll
        for (int i = 0; i < 16; i++) {
            const int c = tid + i*256;
            const int t = c >> 11;
            const int cc = c & 2047;
            const int row = cc >> 4, col = cc & 15;
            const char* gp = (const char*)(t ? ql : qh) + gq + (size_t)row*4096 + col*16;
            cp16(sb + (t ? QT_BYTES : 0) + row*RBQ + col*16, gp);
        }
        CP_COMMIT();
    }

    auto load_stage = [&](int kt) {
        const uint32_t base = sb + 2*QT_BYTES + (uint32_t)(kt & 1) * STAGE_B;
        const size_t gk = ((size_t)(b*2048 + kt*64) * 2048 + h*128) * 2;
        const size_t gv = (((size_t)((b*16 + h)*128)) * 2048 + kt*64) * 2;
        #pragma unroll
        for (int i = 0; i < 16; i++) {
            const int c = tid + i*256;
            const int sel = c >> 10;
            const int cc = c & 1023;
            if (sel < 2) {
                const int row = cc >> 4, col = cc & 15;
                const char* gp = (const char*)(sel ? kl : kh) + gk + (size_t)row*4096 + col*16;
                cp16(base + (sel ? KT_BYTES : 0) + row*RBQ + col*16, gp);
            } else {
                const int row = cc >> 3, col = cc & 7;
                const char* gp = (const char*)(sel == 3 ? vl : vh) + gv + (size_t)row*4096 + col*16;
                cp16(base + 2*KT_BYTES + (sel == 3 ? VT_BYTES : 0) + row*RBV + col*16, gp);
            }
        }
        CP_COMMIT();
    };

    load_stage(0);
    load_stage(1);

    float accO[16][4];
    #pragma unroll
    for (int nt = 0; nt < 16; nt++)
        #pragma unroll
        for (int e = 0; e < 4; e++) accO[nt][e] = 0.f;
    float m0 = -INFINITY, m1 = -INFINITY, l0 = 0.f, l1 = 0.f;

    const int row0 = wid * 16;
    const int qrow0 = qt*128 + row0 + g;

    for (int s = 0; s < ntiles; s++) {
        if (s + 1 < ntiles) { CP_WAIT(1); } else { CP_WAIT(0); }
        __syncthreads();
        const char* stg = sm + 2*QT_BYTES + (size_t)(s & 1) * STAGE_B;

        float accS[8][4];
        #pragma unroll
        for (int nt = 0; nt < 8; nt++)
            #pragma unroll
            for (int e = 0; e < 4; e++) accS[nt][e] = 0.f;

        #pragma unroll
        for (int ks = 0; ks < 8; ks++) {
            const int kb = ks*32 + tig*4;
            uint32_t ah[4], al[4], bh2[8][2], bl2[8][2];
            const char* ra = sm + (row0 + g)*RBQ + kb;
            ah[0] = *(const uint32_t*)(ra);
            ah[1] = *(const uint32_t*)(ra + 8*RBQ);
            ah[2] = *(const uint32_t*)(ra + 16);
            ah[3] = *(const uint32_t*)(ra + 8*RBQ + 16);
            al[0] = *(const uint32_t*)(ra + QT_BYTES);
            al[1] = *(const uint32_t*)(ra + QT_BYTES + 8*RBQ);
            al[2] = *(const uint32_t*)(ra + QT_BYTES + 16);
            al[3] = *(const uint32_t*)(ra + QT_BYTES + 8*RBQ + 16);
            #pragma unroll
            for (int nt = 0; nt < 8; nt++) {
                const char* rb = stg + (nt*8 + g)*RBQ + kb;
                bh2[nt][0] = *(const uint32_t*)(rb);
                bh2[nt][1] = *(const uint32_t*)(rb + 16);
                bl2[nt][0] = *(const uint32_t*)(rb + KT_BYTES);
                bl2[nt][1] = *(const uint32_t*)(rb + KT_BYTES + 16);
            }
            #pragma unroll
            for (int nt = 0; nt < 8; nt++) mma_bf16(accS[nt], ah, bh2[nt]);
            #pragma unroll
            for (int nt = 0; nt < 8; nt++) mma_bf16(accS[nt], ah, bl2[nt]);
            #pragma unroll
            for (int nt = 0; nt < 8; nt++) mma_bf16(accS[nt], al, bh2[nt]);
        }

        if (s >= ntiles - 2) {
            #pragma unroll
            for (int nt = 0; nt < 8; nt++) {
                const int col = s*64 + nt*8 + tig*2;
                if (col     > qrow0)     accS[nt][0] = -INFINITY;
                if (col + 1 > qrow0)     accS[nt][1] = -INFINITY;
                if (col     > qrow0 + 8) accS[nt][2] = -INFINITY;
                if (col + 1 > qrow0 + 8) accS[nt][3] = -INFINITY;
            }
        }

        float mt0 = -INFINITY, mt1 = -INFINITY;
        #pragma unroll
        for (int nt = 0; nt < 8; nt++) {
            mt0 = fmaxf(mt0, fmaxf(accS[nt][0], accS[nt][1]));
            mt1 = fmaxf(mt1, fmaxf(accS[nt][2], accS[nt][3]));
        }
        mt0 = fmaxf(mt0, __shfl_xor_sync(0xffffffffu, mt0, 1));
        mt0 = fmaxf(mt0, __shfl_xor_sync(0xffffffffu, mt0, 2));
        mt1 = fmaxf(mt1, __shfl_xor_sync(0xffffffffu, mt1, 1));
        mt1 = fmaxf(mt1, __shfl_xor_sync(0xffffffffu, mt1, 2));

        const float mn0 = fmaxf(m0, mt0), mn1 = fmaxf(m1, mt1);
        const float sc0 = __expf(m0 - mn0), sc1 = __expf(m1 - mn1);
        m0 = mn0; m1 = mn1;

        float rs0 = 0.f, rs1 = 0.f;
        #pragma unroll
        for (int nt = 0; nt < 8; nt++) {
            accS[nt][0] = __expf(accS[nt][0] - mn0);
            accS[nt][1] = __expf(accS[nt][1] - mn0);
            accS[nt][2] = __expf(accS[nt][2] - mn1);
            accS[nt][3] = __expf(accS[nt][3] - mn1);
            rs0 += accS[nt][0] + accS[nt][1];
            rs1 += accS[nt][2] + accS[nt][3];
        }
        rs0 += __shfl_xor_sync(0xffffffffu, rs0, 1);
        rs0 += __shfl_xor_sync(0xffffffffu, rs0, 2);
        rs1 += __shfl_xor_sync(0xffffffffu, rs1, 1);
        rs1 += __shfl_xor_sync(0xffffffffu, rs1, 2);
        l0 = l0*sc0 + rs0;
        l1 = l1*sc1 + rs1;

        #pragma unroll
        for (int nt = 0; nt < 16; nt++) {
            accO[nt][0] *= sc0; accO[nt][1] *= sc0;
            accO[nt][2] *= sc1; accO[nt][3] *= sc1;
        }

        #pragma unroll
        for (int kk = 0; kk < 4; kk++) {
            uint32_t ph[4], pl[4];
            split2(accS[2*kk][0],   accS[2*kk][1],   ph[0], pl[0]);
            split2(accS[2*kk][2],   accS[2*kk][3],   ph[1], pl[1]);
            split2(accS[2*kk+1][0], accS[2*kk+1][1], ph[2], pl[2]);
            split2(accS[2*kk+1][2], accS[2*kk+1][3], ph[3], pl[3]);
            const int kb = kk*32 + tig*4;
            #pragma unroll
            for (int nt = 0; nt < 16; nt++) {
                const char* rv = stg + 2*KT_BYTES + (nt*8 + g)*RBV + kb;
                uint32_t vbh[2], vbl[2];
                vbh[0] = *(const uint32_t*)(rv);
                vbh[1] = *(const uint32_t*)(rv + 16);
                vbl[0] = *(const uint32_t*)(rv + VT_BYTES);
                vbl[1] = *(const uint32_t*)(rv + VT_BYTES + 16);
                mma_bf16(accO[nt], ph, vbh);
                mma_bf16(accO[nt], ph, vbl);
                mma_bf16(accO[nt], pl, vbh);
            }
        }

        __syncthreads();
        if (s + 2 < ntiles) load_stage(s + 2);
    }

    const float inv0 = 1.f / l0, inv1 = 1.f / l1;
    const size_t ob = ((size_t)(b*2048 + qt*128 + row0 + g)) * 2048 + h*128;
    #pragma unroll
    for (int nt = 0; nt < 16; nt++) {
        const int c = nt*8 + tig*2;
        uint32_t h0, l0u, h1, l1u;
        split2(accO[nt][0]*inv0, accO[nt][1]*inv0, h0, l0u);
        split2(accO[nt][2]*inv1, accO[nt][3]*inv1, h1, l1u);
        *(uint32_t*)(Oh + ob + c)           = h0;
        *(uint32_t*)(Ol + ob + c)           = l0u;
        *(uint32_t*)(Oh + ob + 8*2048 + c)  = h1;
        *(uint32_t*)(Ol + ob + 8*2048 + c)  = l1u;
    }
}

// ======================= weight transpose + split (vectorized) ==============
// W[K][N] fp32 -> Thi/Tlo[n*rowStride+rowOff][K] bf16. Tile: 64 k x 32 n.
__global__ void transconv_k(const float* __restrict__ W,
                            __nv_bfloat16* __restrict__ Thi, __nv_bfloat16* __restrict__ Tlo,
                            int K, int N, int rowStride, int rowOff)
{
    __shared__ float t[64][33];
    const int n0 = blockIdx.x * 32, k0 = blockIdx.y * 64;
    const int tx = threadIdx.x, ty = threadIdx.y;
    #pragma unroll
    for (int r = ty; r < 64; r += 8)
        t[r][tx] = W[(size_t)(k0 + r) * N + n0 + tx];
    __syncthreads();
    #pragma unroll
    for (int i = ty; i < 32; i += 8) {
        const float v0 = t[2*tx][i];
        const float v1 = t[2*tx + 1][i];
        uint32_t hi, lo;
        split2(v0, v1, hi, lo);
        const size_t o = ((size_t)(n0 + i) * rowStride + rowOff) * K + k0 + 2*tx;
        *(uint32_t*)(Thi + o) = hi;
        *(uint32_t*)(Tlo + o) = lo;
    }
}

// ======================= V transpose (bf16 hi/lo pair) ======================
__global__ void vtrans_bf_k(const __nv_bfloat16* __restrict__ Vh,
                            const __nv_bfloat16* __restrict__ Vl,
                            __nv_bfloat16* __restrict__ Th, __nv_bfloat16* __restrict__ Tl)
{
    __shared__ __nv_bfloat16 th[32][33], tl[32][33];
    const int kv0 = blockIdx.x * 32, hd0 = blockIdx.y * 32, bh = blockIdx.z;
    const int b = bh >> 4, h = bh & 15;
    const int tx = threadIdx.x, ty = threadIdx.y;
    #pragma unroll
    for (int i = ty; i < 32; i += 8) {
        const size_t src = (size_t)(b*2048 + kv0 + i) * 2048 + h*128 + hd0 + tx;
        th[i][tx] = Vh[src];
        tl[i][tx] = Vl[src];
    }
    __syncthreads();
    #pragma unroll
    for (int i = ty; i < 32; i += 8) {
        const size_t o = ((size_t)(bh*128 + hd0 + i)) * 2048 + kv0 + tx;
        Th[o] = th[tx][i];
        Tl[o] = tl[tx][i];
    }
}

// ======================= RMSNorm -> bf16 hi/lo ==============================
__global__ __launch_bounds__(256) void rmsnorm_conv_k(
    const float* __restrict__ x, const float* __restrict__ w,
    __nv_bfloat16* __restrict__ yh, __nv_bfloat16* __restrict__ yl)
{
    const int row = blockIdx.x;
    const float4* xr = (const float4*)(x + (size_t)row * HID);
    const float4* w4 = (const float4*)w;

    float4 v0 = xr[threadIdx.x];
    float4 v1 = xr[threadIdx.x + 256];
    float ss = v0.x*v0.x + v0.y*v0.y + v0.z*v0.z + v0.w*v0.w
             + v1.x*v1.x + v1.y*v1.y + v1.z*v1.z + v1.w*v1.w;
    #pragma unroll
    for (int off = 16; off > 0; off >>= 1) ss += __shfl_xor_sync(0xffffffffu, ss, off);

    __shared__ float red[8]; __shared__ float s_inv;
    if ((threadIdx.x & 31) == 0) red[threadIdx.x >> 5] = ss;
    __syncthreads();
    if (threadIdx.x == 0) {
        float t = 0.f;
        #pragma unroll
        for (int i = 0; i < 8; i++) t += red[i];
        s_inv = rsqrtf(t * (1.f / (float)HID) + 1e-6f);
    }
    __syncthreads();
    const float inv = s_inv;

    const float4 w0 = w4[threadIdx.x], w1 = w4[threadIdx.x + 256];
    float o[8] = { v0.x*inv*w0.x, v0.y*inv*w0.y, v0.z*inv*w0.z, v0.w*inv*w0.w,
                   v1.x*inv*w1.x, v1.y*inv*w1.y, v1.z*inv*w1.z, v1.w*inv*w1.w };
    const size_t b0 = (size_t)row * HID + threadIdx.x * 4;
    const size_t b1 = (size_t)row * HID + (threadIdx.x + 256) * 4;
    #pragma unroll
    for (int j = 0; j < 4; j++) {
        __nv_bfloat16 h = __float2bfloat16(o[j]);
        yh[b0 + j] = h; yl[b0 + j] = __float2bfloat16(o[j] - __bfloat162float(h));
    }
    #pragma unroll
    for (int j = 0; j < 4; j++) {
        __nv_bfloat16 h = __float2bfloat16(o[4 + j]);
        yh[b1 + j] = h; yl[b1 + j] = __float2bfloat16(o[4 + j] - __bfloat162float(h));
    }
}

// ======================= launch =============================================
extern "C" void kernel_launch(void* const* d_in, const int* in_sizes, int n_in,
                              void* d_out, int out_size)
{
    const float* hidden = (const float*)d_in[0];
    const float* wq  = (const float*)d_in[1];
    const float* wk  = (const float*)d_in[2];
    const float* wv  = (const float*)d_in[3];
    const float* wo  = (const float*)d_in[4];
    const float* wg  = (const float*)d_in[5];
    const float* wu  = (const float*)d_in[6];
    const float* wd  = (const float*)d_in[7];
    const float* ln1 = (const float*)d_in[8];
    const float* ln2 = (const float*)d_in[9];

    __nv_bfloat16 *pwq_h,*pwq_l,*pwk_h,*pwk_l,*pwv_h,*pwv_l,*pwo_h,*pwo_l;
    __nv_bfloat16 *pwgu_h,*pwgu_l,*pwd_h,*pwd_l;
    __nv_bfloat16 *px_h,*px_l,*pat_h,*pat_l,*pm_h,*pm_l;
    __nv_bfloat16 *pq_h,*pq_l,*pk_h,*pk_l,*pv_h,*pv_l,*pvt_h,*pvt_l;
    float *h1;
    cudaGetSymbolAddress((void**)&pwq_h, w_q_hi); cudaGetSymbolAddress((void**)&pwq_l, w_q_lo);
    cudaGetSymbolAddress((void**)&pwk_h, w_k_hi); cudaGetSymbolAddress((void**)&pwk_l, w_k_lo);
    cudaGetSymbolAddress((void**)&pwv_h, w_v_hi); cudaGetSymbolAddress((void**)&pwv_l, w_v_lo);
    cudaGetSymbolAddress((void**)&pwo_h, w_o_hi); cudaGetSymbolAddress((void**)&pwo_l, w_o_lo);
    cudaGetSymbolAddress((void**)&pwgu_h, w_gu_hi); cudaGetSymbolAddress((void**)&pwgu_l, w_gu_lo);
    cudaGetSymbolAddress((void**)&pwd_h, w_d_hi); cudaGetSymbolAddress((void**)&pwd_l, w_d_lo);
    cudaGetSymbolAddress((void**)&px_h,  a_x_hi); cudaGetSymbolAddress((void**)&px_l,  a_x_lo);
    cudaGetSymbolAddress((void**)&pat_h, a_at_hi);cudaGetSymbolAddress((void**)&pat_l, a_at_lo);
    cudaGetSymbolAddress((void**)&pm_h,  a_m_hi); cudaGetSymbolAddress((void**)&pm_l,  a_m_lo);
    cudaGetSymbolAddress((void**)&pq_h,  q_bhi);  cudaGetSymbolAddress((void**)&pq_l,  q_blo);
    cudaGetSymbolAddress((void**)&pk_h,  k_bhi);  cudaGetSymbolAddress((void**)&pk_l,  k_blo);
    cudaGetSymbolAddress((void**)&pv_h,  v_bhi);  cudaGetSymbolAddress((void**)&pv_l,  v_blo);
    cudaGetSymbolAddress((void**)&pvt_h, vt_hi);  cudaGetSymbolAddress((void**)&pvt_l, vt_lo);
    cudaGetSymbolAddress((void**)&h1, s_h1);

    cudaFuncSetAttribute(gemm3bf<0>, cudaFuncAttributeMaxDynamicSharedMemorySize, GEMM_SMEM);
    cudaFuncSetAttribute(gemm3bf<1>, cudaFuncAttributeMaxDynamicSharedMemorySize, GEMM_SMEM);
    cudaFuncSetAttribute(gemm3bf<2>, cudaFuncAttributeMaxDynamicSharedMemorySize, GEMM_SMEM);
    cudaFuncSetAttribute(gemm3bf<3>, cudaFuncAttributeMaxDynamicSharedMemorySize, GEMM_SMEM);
    cudaFuncSetAttribute(attn_mma_k, cudaFuncAttributeMaxDynamicSharedMemorySize, ATTN_SMEM);

    // weight transpose+split; gate/up interleaved (row 2j = gate, 2j+1 = up)
    dim3 tb(32, 8);
    transconv_k<<<dim3(HID/32,  HID/64),  tb>>>(wq, pwq_h, pwq_l, HID, HID, 1, 0);
    transconv_k<<<dim3(HID/32,  HID/64),  tb>>>(wk, pwk_h, pwk_l, HID, HID, 1, 0);
    transconv_k<<<dim3(HID/32,  HID/64),  tb>>>(wv, pwv_h, pwv_l, HID, HID, 1, 0);
    transconv_k<<<dim3(HID/32,  HID/64),  tb>>>(wo, pwo_h, pwo_l, HID, HID, 1, 0);
    transconv_k<<<dim3(INTER/32,HID/64),  tb>>>(wg, pwgu_h, pwgu_l, HID, INTER, 2, 0);
    transconv_k<<<dim3(INTER/32,HID/64),  tb>>>(wu, pwgu_h, pwgu_l, HID, INTER, 2, 1);
    transconv_k<<<dim3(HID/32,  INTER/64),tb>>>(wd, pwd_h, pwd_l, INTER, HID, 1, 0);

    // 1) rmsnorm -> bf16 hi/lo
    rmsnorm_conv_k<<<MTOK, 256>>>(hidden, ln1, px_h, px_l);

    // 2) QKV projections
    const float sc = 0.08838834764831845f;
    dim3 gHH(HID/128, MTOK/256);   // (16, 16)
    gemm3bf<2><<<gHH, 256, GEMM_SMEM>>>(px_h, px_l, pwq_h, pwq_l, nullptr, nullptr,
                                        pq_h, pq_l, sc, MTOK, HID, HID);
    gemm3bf<2><<<gHH, 256, GEMM_SMEM>>>(px_h, px_l, pwk_h, pwk_l, nullptr, nullptr,
                                        pk_h, pk_l, 1.f, MTOK, HID, HID);
    gemm3bf<2><<<gHH, 256, GEMM_SMEM>>>(px_h, px_l, pwv_h, pwv_l, nullptr, nullptr,
                                        pv_h, pv_l, 1.f, MTOK, HID, HID);
    vtrans_bf_k<<<dim3(64, 4, 32), tb>>>(pv_h, pv_l, pvt_h, pvt_l);

    // 3) tensor-core attention -> bf16 hi/lo
    attn_mma_k<<<dim3(16, 16, 2), 256, ATTN_SMEM>>>(pq_h, pq_l, pk_h, pk_l,
                                                    pvt_h, pvt_l, pat_h, pat_l);

    // 4) O-proj + residual
    gemm3bf<1><<<gHH, 256, GEMM_SMEM>>>(pat_h, pat_l, pwo_h, pwo_l, hidden, h1,
                                        nullptr, nullptr, 1.f, MTOK, HID, HID);

    // 5) rmsnorm2 -> bf16 hi/lo
    rmsnorm_conv_k<<<MTOK, 256>>>(h1, ln2, px_h, px_l);

    // 6) fused gate+up GEMM with silu-mul epilogue -> m (bf16 hi/lo) directly
    gemm3bf<3><<<dim3(2*INTER/128, MTOK/256), 256, GEMM_SMEM>>>(
        px_h, px_l, pwgu_h, pwgu_l, nullptr, nullptr,
        pm_h, pm_l, 1.f, MTOK, 2*INTER, HID);

    // 7) down-proj + residual -> d_out
    gemm3bf<1><<<gHH, 256, GEMM_SMEM>>>(pm_h, pm_l, pwd_h, pwd_l, h1, (float*)d_out,
                                        nullptr, nullptr, 1.f, MTOK, HID, INTER);
}

// round 11
// speedup vs baseline: 1.0064x; 1.0028x over previous
#include <cuda_runtime.h>
#include <cuda_bf16.h>
#include <math.h>
#include <stdint.h>

#define MTOK 4096      // B*S
#define HID  2048
#define INTER 8192

// ======================= device scratch (no allocations) ====================
__device__ __nv_bfloat16 w_q_hi[HID*HID],  w_q_lo[HID*HID];
__device__ __nv_bfloat16 w_k_hi[HID*HID],  w_k_lo[HID*HID];
__device__ __nv_bfloat16 w_v_hi[HID*HID],  w_v_lo[HID*HID];
__device__ __nv_bfloat16 w_o_hi[HID*HID],  w_o_lo[HID*HID];
__device__ __nv_bfloat16 w_gu_hi[(size_t)2*INTER*HID], w_gu_lo[(size_t)2*INTER*HID]; // interleaved
__device__ __nv_bfloat16 w_d_hi[(size_t)HID*INTER], w_d_lo[(size_t)HID*INTER];
__device__ __nv_bfloat16 a_x_hi[MTOK*HID],  a_x_lo[MTOK*HID];
__device__ __nv_bfloat16 a_at_hi[MTOK*HID], a_at_lo[MTOK*HID];
__device__ __nv_bfloat16 a_m_hi[(size_t)MTOK*INTER], a_m_lo[(size_t)MTOK*INTER];
__device__ __nv_bfloat16 q_bhi[MTOK*HID], q_blo[MTOK*HID];
__device__ __nv_bfloat16 k_bhi[MTOK*HID], k_blo[MTOK*HID];
__device__ __nv_bfloat16 v_bhi[MTOK*HID], v_blo[MTOK*HID];
__device__ __nv_bfloat16 vt_hi[MTOK*HID], vt_lo[MTOK*HID];   // [b*16+h][hd][kv]
__device__ float s_h1[MTOK*HID];

// ======================= helpers ============================================
__device__ __forceinline__ uint32_t smem_u32(const void* p) {
    uint32_t a;
    asm("{ .reg .u64 t; cvta.to.shared.u64 t, %1; cvt.u32.u64 %0, t; }" : "=r"(a) : "l"(p));
    return a;
}
__device__ __forceinline__ void cp16(uint32_t s, const void* g) {
    asm volatile("cp.async.cg.shared.global [%0], [%1], 16;" :: "r"(s), "l"(g));
}
#define CP_COMMIT() asm volatile("cp.async.commit_group;")
#define CP_WAIT(N)  asm volatile("cp.async.wait_group %0;" :: "n"(N))

__device__ __forceinline__ void mma_bf16(float* c, const uint32_t* a, const uint32_t* b) {
    asm volatile(
        "mma.sync.aligned.m16n8k16.row.col.f32.bf16.bf16.f32 "
        "{%0,%1,%2,%3}, {%4,%5,%6,%7}, {%8,%9}, {%0,%1,%2,%3};"
        : "+f"(c[0]), "+f"(c[1]), "+f"(c[2]), "+f"(c[3])
        : "r"(a[0]), "r"(a[1]), "r"(a[2]), "r"(a[3]), "r"(b[0]), "r"(b[1]));
}
__device__ __forceinline__ void split2(float x, float y, uint32_t& hi, uint32_t& lo) {
    __nv_bfloat162 h;
    h.x = __float2bfloat16(x); h.y = __float2bfloat16(y);
    __nv_bfloat162 l;
    l.x = __float2bfloat16(x - __bfloat162float(h.x));
    l.y = __float2bfloat16(y - __bfloat162float(h.y));
    hi = *reinterpret_cast<uint32_t*>(&h);
    lo = *reinterpret_cast<uint32_t*>(&l);
}

// ======================= bf16x3 mma.sync GEMM (round-8 core) ================
// OM: 0 = fp32 out, 1 = fp32 out + residual, 2 = bf16 hi/lo out (scaled),
//     3 = fused silu(even)*odd -> bf16 hi/lo out at column c/2 (Nout = N/2)
#define RB    144
#define ATILE (256*RB)
#define BTILE (128*RB)
#define STG   (2*ATILE + 2*BTILE)  // 110592
#define GEMM_SMEM (2*STG)          // 221184

template<int OM>
__global__ __launch_bounds__(256) void gemm3bf(
    const __nv_bfloat16* __restrict__ Ahi, const __nv_bfloat16* __restrict__ Alo,
    const __nv_bfloat16* __restrict__ Bhi, const __nv_bfloat16* __restrict__ Blo,
    const float* __restrict__ R, float* __restrict__ C,
    __nv_bfloat16* __restrict__ Ch, __nv_bfloat16* __restrict__ Cl,
    float scale, int M, int N, int K)
{
    extern __shared__ char sm[];
    const uint32_t sbase = smem_u32(sm);

    const int tid = threadIdx.x;
    const int lane = tid & 31;
    const int wid = tid >> 5;
    const int g = lane >> 2, tig = lane & 3;
    const int warp_m = wid & 3;
    const int warp_n = wid >> 2;
    const int bm = blockIdx.y * 256;
    const int bn = blockIdx.x * 128;

    const int crow = tid >> 3;
    const int ccolB = (tid & 7) * 16;

    const int S = K >> 6;

    auto load_stage = [&](int s) {
        const uint32_t b = sbase + (uint32_t)(s & 1) * STG;
        const int k0 = s << 6;
        const size_t ga = ((size_t)(bm + crow) * K + k0) * 2 + ccolB;
        const size_t gb = ((size_t)(bn + crow) * K + k0) * 2 + ccolB;
        const size_t rstep = (size_t)32 * K * 2;
        const char* pah = (const char*)Ahi + ga;
        const char* pal = (const char*)Alo + ga;
        const char* pbh = (const char*)Bhi + gb;
        const char* pbl = (const char*)Blo + gb;
        #pragma unroll
        for (int i = 0; i < 8; i++) {
            const uint32_t so = (uint32_t)((crow + 32*i) * RB + ccolB);
            cp16(b + so,         pah); pah += rstep;
            cp16(b + ATILE + so, pal); pal += rstep;
        }
        #pragma unroll
        for (int i = 0; i < 4; i++) {
            const uint32_t so = (uint32_t)((crow + 32*i) * RB + ccolB);
            cp16(b + 2*ATILE + so,         pbh); pbh += rstep;
            cp16(b + 2*ATILE + BTILE + so, pbl); pbl += rstep;
        }
        CP_COMMIT();
    };

    load_stage(0);
    if (S > 1) load_stage(1);

    float acc[4][8][4];
    #pragma unroll
    for (int mt = 0; mt < 4; mt++)
        #pragma unroll
        for (int nt = 0; nt < 8; nt++)
            #pragma unroll
            for (int e = 0; e < 4; e++) acc[mt][nt][e] = 0.f;

    const int arow0 = warp_m * 64 + g;
    const int brow0 = warp_n * 64 + g;

    for (int s = 0; s < S; ++s) {
        if (s + 1 < S) { CP_WAIT(1); } else { CP_WAIT(0); }
        __syncthreads();
        const char* b = sm + (size_t)(s & 1) * STG;

        #pragma unroll
        for (int ks = 0; ks < 4; ++ks) {
            const int kb = ks * 32 + tig * 4;

            uint32_t bhf[8][2], blf[8][2];
            #pragma unroll
            for (int nt = 0; nt < 8; nt++) {
                const char* rb = b + 2*ATILE + (brow0 + nt*8) * RB + kb;
                bhf[nt][0] = *(const uint32_t*)(rb);
                bhf[nt][1] = *(const uint32_t*)(rb + 16);
                blf[nt][0] = *(const uint32_t*)(rb + BTILE);
                blf[nt][1] = *(const uint32_t*)(rb + BTILE + 16);
            }

            #pragma unroll
            for (int mt = 0; mt < 4; mt++) {
                uint32_t ah[4], al[4];
                const char* ra = b + (arow0 + mt*16) * RB + kb;
                ah[0] = *(const uint32_t*)(ra);
                ah[1] = *(const uint32_t*)(ra + 8*RB);
                ah[2] = *(const uint32_t*)(ra + 16);
                ah[3] = *(const uint32_t*)(ra + 8*RB + 16);
                al[0] = *(const uint32_t*)(ra + ATILE);
                al[1] = *(const uint32_t*)(ra + ATILE + 8*RB);
                al[2] = *(const uint32_t*)(ra + ATILE + 16);
                al[3] = *(const uint32_t*)(ra + ATILE + 8*RB + 16);

                #pragma unroll
                for (int nt = 0; nt < 8; nt++)
                    mma_bf16(acc[mt][nt], ah, bhf[nt]);
                #pragma unroll
                for (int nt = 0; nt < 8; nt++)
                    mma_bf16(acc[mt][nt], ah, blf[nt]);
                #pragma unroll
                for (int nt = 0; nt < 8; nt++)
                    mma_bf16(acc[mt][nt], al, bhf[nt]);
            }
        }
        __syncthreads();
        if (s + 2 < S) load_stage(s + 2);
    }

    const int row0 = bm + warp_m*64 + g;
    const int col0 = bn + warp_n*64 + tig*2;
    #pragma unroll
    for (int mt = 0; mt < 4; mt++) {
        #pragma unroll
        for (int nt = 0; nt < 8; nt++) {
            const int r = row0 + mt*16;
            const int c = col0 + nt*8;
            if (OM == 3) {
                const int Nout = N >> 1;
                const int cc = c >> 1;
                const float g0 = acc[mt][nt][0], u0 = acc[mt][nt][1];
                const float g1 = acc[mt][nt][2], u1 = acc[mt][nt][3];
                const float r0 = g0 / (1.f + __expf(-g0)) * u0;
                const float r1 = g1 / (1.f + __expf(-g1)) * u1;
                const __nv_bfloat16 h0 = __float2bfloat16(r0);
                const __nv_bfloat16 h1 = __float2bfloat16(r1);
                Ch[(size_t)r * Nout + cc]     = h0;
                Cl[(size_t)r * Nout + cc]     = __float2bfloat16(r0 - __bfloat162float(h0));
                Ch[(size_t)(r+8) * Nout + cc] = h1;
                Cl[(size_t)(r+8) * Nout + cc] = __float2bfloat16(r1 - __bfloat162float(h1));
            } else if (OM == 2) {
                uint32_t h0, l0u, h1, l1u;
                split2(acc[mt][nt][0]*scale, acc[mt][nt][1]*scale, h0, l0u);
                split2(acc[mt][nt][2]*scale, acc[mt][nt][3]*scale, h1, l1u);
                *(uint32_t*)(Ch + (size_t)r * N + c)     = h0;
                *(uint32_t*)(Cl + (size_t)r * N + c)     = l0u;
                *(uint32_t*)(Ch + (size_t)(r+8) * N + c) = h1;
                *(uint32_t*)(Cl + (size_t)(r+8) * N + c) = l1u;
            } else {
                float2 v0 = make_float2(acc[mt][nt][0], acc[mt][nt][1]);
                float2 v1 = make_float2(acc[mt][nt][2], acc[mt][nt][3]);
                if (OM == 1) {
                    const float2 r0 = *(const float2*)(R + (size_t)r * N + c);
                    const float2 r1 = *(const float2*)(R + (size_t)(r+8) * N + c);
                    v0.x += r0.x; v0.y += r0.y;
                    v1.x += r1.x; v1.y += r1.y;
                }
                *(float2*)(C + (size_t)r * N + c)     = v0;
                *(float2*)(C + (size_t)(r+8) * N + c) = v1;
            }
        }
    }
}

// ======================= tensor-core causal flash attention =================
// (verbatim champion)
#define RBQ 272
#define RBV 144
#define QT_BYTES (128*RBQ)
#define KT_BYTES (64*RBQ)
#define VT_BYTES (128*RBV)
#define STAGE_B  (2*KT_BYTES + 2*VT_BYTES)
#define ATTN_SMEM (2*QT_BYTES + 2*STAGE_B)

__global__ __launch_bounds__(256) void attn_mma_k(
    const __nv_bfloat16* __restrict__ qh, const __nv_bfloat16* __restrict__ ql,
    const __nv_bfloat16* __restrict__ kh, const __nv_bfloat16* __restrict__ kl,
    const __nv_bfloat16* __restrict__ vh, const __nv_bfloat16* __restrict__ vl,
    __nv_bfloat16* __restrict__ Oh, __nv_bfloat16* __restrict__ Ol)
{
    extern __shared__ char sm[];
    const uint32_t sb = smem_u32(sm);

    const int tid = threadIdx.x, lane = tid & 31, wid = tid >> 5;
    const int g = lane >> 2, tig = lane & 3;
    const int qt = 15 - blockIdx.x, h = blockIdx.y, b = blockIdx.z;
    const int ntiles = 2 * (qt + 1);

    {
        const size_t gq = ((size_t)(b*2048 + qt*128) * 2048 + h*128) * 2;
        #pragma unroll
        for (int i = 0; i < 16; i++) {
            const int c = tid + i*256;
            const int t = c >> 11;
            const int cc = c & 2047;
            const int row = cc >> 4, col = cc & 15;
            const char* gp = (const char*)(t ? ql : qh) + gq + (size_t)row*4096 + col*16;
            cp16(sb + (t ? QT_BYTES : 0) + row*RBQ + col*16, gp);
        }
        CP_COMMIT();
    }

    auto load_stage = [&](int kt) {
        const uint32_t base = sb + 2*QT_BYTES + (uint32_t)(kt & 1) * STAGE_B;
        const size_t gk = ((size_t)(b*2048 + kt*64) * 2048 + h*128) * 2;
        const size_t gv = (((size_t)((b*16 + h)*128)) * 2048 + kt*64) * 2;
        #pragma unroll
        for (int i = 0; i < 16; i++) {
            const int c = tid + i*256;
            const int sel = c >> 10;
            const int cc = c & 1023;
            if (sel < 2) {
                const int row = cc >> 4, col = cc & 15;
                const char* gp = (const char*)(sel ? kl : kh) + gk + (size_t)row*4096 + col*16;
                cp16(base + (sel ? KT_BYTES : 0) + row*RBQ + col*16, gp);
            } else {
                const int row = cc >> 3, col = cc & 7;
                const char* gp = (const char*)(sel == 3 ? vl : vh) + gv + (size_t)row*4096 + col*16;
                cp16(base + 2*KT_BYTES + (sel == 3 ? VT_BYTES : 0) + row*RBV + col*16, gp);
            }
        }
        CP_COMMIT();
    };

    load_stage(0);
    load_stage(1);

    float accO[16][4];
    #pragma unroll
    for (int nt = 0; nt < 16; nt++)
        #pragma unroll
        for (int e = 0; e < 4; e++) accO[nt][e] = 0.f;
    float m0 = -INFINITY, m1 = -INFINITY, l0 = 0.f, l1 = 0.f;

    const int row0 = wid * 16;
    const int qrow0 = qt*128 + row0 + g;

    for (int s = 0; s < ntiles; s++) {
        if (s + 1 < ntiles) { CP_WAIT(1); } else { CP_WAIT(0); }
        __syncthreads();
        const char* stg = sm + 2*QT_BYTES + (size_t)(s & 1) * STAGE_B;

        float accS[8][4];
        #pragma unroll
        for (int nt = 0; nt < 8; nt++)
            #pragma unroll
            for (int e = 0; e < 4; e++) accS[nt][e] = 0.f;

        #pragma unroll
        for (int ks = 0; ks < 8; ks++) {
            const int kb = ks*32 + tig*4;
            uint32_t ah[4], al[4], bh2[8][2], bl2[8][2];
            const char* ra = sm + (row0 + g)*RBQ + kb;
            ah[0] = *(const uint32_t*)(ra);
            ah[1] = *(const uint32_t*)(ra + 8*RBQ);
            ah[2] = *(const uint32_t*)(ra + 16);
            ah[3] = *(const uint32_t*)(ra + 8*RBQ + 16);
            al[0] = *(const uint32_t*)(ra + QT_BYTES);
            al[1] = *(const uint32_t*)(ra + QT_BYTES + 8*RBQ);
            al[2] = *(const uint32_t*)(ra + QT_BYTES + 16);
            al[3] = *(const uint32_t*)(ra + QT_BYTES + 8*RBQ + 16);
            #pragma unroll
            for (int nt = 0; nt < 8; nt++) {
                const char* rb = stg + (nt*8 + g)*RBQ + kb;
                bh2[nt][0] = *(const uint32_t*)(rb);
                bh2[nt][1] = *(const uint32_t*)(rb + 16);
                bl2[nt][0] = *(const uint32_t*)(rb + KT_BYTES);
                bl2[nt][1] = *(const uint32_t*)(rb + KT_BYTES + 16);
            }
            #pragma unroll
            for (int nt = 0; nt < 8; nt++) mma_bf16(accS[nt], ah, bh2[nt]);
            #pragma unroll
            for (int nt = 0; nt < 8; nt++) mma_bf16(accS[nt], ah, bl2[nt]);
            #pragma unroll
            for (int nt = 0; nt < 8; nt++) mma_bf16(accS[nt], al, bh2[nt]);
        }

        if (s >= ntiles - 2) {
            #pragma unroll
            for (int nt = 0; nt < 8; nt++) {
                const int col = s*64 + nt*8 + tig*2;
                if (col     > qrow0)     accS[nt][0] = -INFINITY;
                if (col + 1 > qrow0)     accS[nt][1] = -INFINITY;
                if (col     > qrow0 + 8) accS[nt][2] = -INFINITY;
                if (col + 1 > qrow0 + 8) accS[nt][3] = -INFINITY;
            }
        }

        float mt0 = -INFINITY, mt1 = -INFINITY;
        #pragma unroll
        for (int nt = 0; nt < 8; nt++) {
            mt0 = fmaxf(mt0, fmaxf(accS[nt][0], accS[nt][1]));
            mt1 = fmaxf(mt1, fmaxf(accS[nt][2], accS[nt][3]));
        }
        mt0 = fmaxf(mt0, __shfl_xor_sync(0xffffffffu, mt0, 1));
        mt0 = fmaxf(mt0, __shfl_xor_sync(0xffffffffu, mt0, 2));
        mt1 = fmaxf(mt1, __shfl_xor_sync(0xffffffffu, mt1, 1));
        mt1 = fmaxf(mt1, __shfl_xor_sync(0xffffffffu, mt1, 2));

        const float mn0 = fmaxf(m0, mt0), mn1 = fmaxf(m1, mt1);
        const float sc0 = __expf(m0 - mn0), sc1 = __expf(m1 - mn1);
        m0 = mn0; m1 = mn1;

        float rs0 = 0.f, rs1 = 0.f;
        #pragma unroll
        for (int nt = 0; nt < 8; nt++) {
            accS[nt][0] = __expf(accS[nt][0] - mn0);
            accS[nt][1] = __expf(accS[nt][1] - mn0);
            accS[nt][2] = __expf(accS[nt][2] - mn1);
            accS[nt][3] = __expf(accS[nt][3] - mn1);
            rs0 += accS[nt][0] + accS[nt][1];
            rs1 += accS[nt][2] + accS[nt][3];
        }
        rs0 += __shfl_xor_sync(0xffffffffu, rs0, 1);
        rs0 += __shfl_xor_sync(0xffffffffu, rs0, 2);
        rs1 += __shfl_xor_sync(0xffffffffu, rs1, 1);
        rs1 += __shfl_xor_sync(0xffffffffu, rs1, 2);
        l0 = l0*sc0 + rs0;
        l1 = l1*sc1 + rs1;

        #pragma unroll
        for (int nt = 0; nt < 16; nt++) {
            accO[nt][0] *= sc0; accO[nt][1] *= sc0;
            accO[nt][2] *= sc1; accO[nt][3] *= sc1;
        }

        #pragma unroll
        for (int kk = 0; kk < 4; kk++) {
            uint32_t ph[4], pl[4];
            split2(accS[2*kk][0],   accS[2*kk][1],   ph[0], pl[0]);
            split2(accS[2*kk][2],   accS[2*kk][3],   ph[1], pl[1]);
            split2(accS[2*kk+1][0], accS[2*kk+1][1], ph[2], pl[2]);
            split2(accS[2*kk+1][2], accS[2*kk+1][3], ph[3], pl[3]);
            const int kb = kk*32 + tig*4;
            #pragma unroll
            for (int nt = 0; nt < 16; nt++) {
                const char* rv = stg + 2*KT_BYTES + (nt*8 + g)*RBV + kb;
                uint32_t vbh[2], vbl[2];
                vbh[0] = *(const uint32_t*)(rv);
                vbh[1] = *(const uint32_t*)(rv + 16);
                vbl[0] = *(const uint32_t*)(rv + VT_BYTES);
                vbl[1] = *(const uint32_t*)(rv + VT_BYTES + 16);
                mma_bf16(accO[nt], ph, vbh);
                mma_bf16(accO[nt], ph, vbl);
                mma_bf16(accO[nt], pl, vbh);
            }
        }

        __syncthreads();
        if (s + 2 < ntiles) load_stage(s + 2);
    }

    const float inv0 = 1.f / l0, inv1 = 1.f / l1;
    const size_t ob = ((size_t)(b*2048 + qt*128 + row0 + g)) * 2048 + h*128;
    #pragma unroll
    for (int nt = 0; nt < 16; nt++) {
        const int c = nt*8 + tig*2;
        uint32_t h0, l0u, h1, l1u;
        split2(accO[nt][0]*inv0, accO[nt][1]*inv0, h0, l0u);
        split2(accO[nt][2]*inv1, accO[nt][3]*inv1, h1, l1u);
        *(uint32_t*)(Oh + ob + c)           = h0;
        *(uint32_t*)(Ol + ob + c)           = l0u;
        *(uint32_t*)(Oh + ob + 8*2048 + c)  = h1;
        *(uint32_t*)(Ol + ob + 8*2048 + c)  = l1u;
    }
}

// ======================= batched weight transpose + split ====================
// 64k x 64n tiles, up to 4 jobs per launch via blockIdx.z.
struct TCJob  { const float* W; __nv_bfloat16* Th; __nv_bfloat16* Tl; int rowOff; };
struct TCJobs { TCJob j[4]; };

__global__ void transconv64_k(TCJobs jobs, int K, int N, int rowStride)
{
    const TCJob jb = jobs.j[blockIdx.z];
    __shared__ float t[64][65];
    const int n0 = blockIdx.x * 64, k0 = blockIdx.y * 64;
    const int tx = threadIdx.x, ty = threadIdx.y;   // (32, 8)
    #pragma unroll
    for (int r = ty; r < 64; r += 8) {
        const float2 v = *(const float2*)(jb.W + (size_t)(k0 + r) * N + n0 + 2*tx);
        t[r][2*tx]   = v.x;
        t[r][2*tx+1] = v.y;
    }
    __syncthreads();
    #pragma unroll
    for (int i = ty; i < 64; i += 8) {
        uint32_t hi, lo;
        split2(t[2*tx][i], t[2*tx+1][i], hi, lo);
        const size_t o = ((size_t)(n0 + i) * rowStride + jb.rowOff) * K + k0 + 2*tx;
        *(uint32_t*)(jb.Th + o) = hi;
        *(uint32_t*)(jb.Tl + o) = lo;
    }
}

// ======================= V transpose (bf16 hi/lo pair) ======================
__global__ void vtrans_bf_k(const __nv_bfloat16* __restrict__ Vh,
                            const __nv_bfloat16* __restrict__ Vl,
                            __nv_bfloat16* __restrict__ Th, __nv_bfloat16* __restrict__ Tl)
{
    __shared__ __nv_bfloat16 th[32][33], tl[32][33];
    const int kv0 = blockIdx.x * 32, hd0 = blockIdx.y * 32, bh = blockIdx.z;
    const int b = bh >> 4, h = bh & 15;
    const int tx = threadIdx.x, ty = threadIdx.y;
    #pragma unroll
    for (int i = ty; i < 32; i += 8) {
        const size_t src = (size_t)(b*2048 + kv0 + i) * 2048 + h*128 + hd0 + tx;
        th[i][tx] = Vh[src];
        tl[i][tx] = Vl[src];
    }
    __syncthreads();
    #pragma unroll
    for (int i = ty; i < 32; i += 8) {
        const size_t o = ((size_t)(bh*128 + hd0 + i)) * 2048 + kv0 + tx;
        Th[o] = th[tx][i];
        Tl[o] = tl[tx][i];
    }
}

// ======================= RMSNorm -> bf16 hi/lo ==============================
__global__ __launch_bounds__(256) void rmsnorm_conv_k(
    const float* __restrict__ x, const float* __restrict__ w,
    __nv_bfloat16* __restrict__ yh, __nv_bfloat16* __restrict__ yl)
{
    const int row = blockIdx.x;
    const float4* xr = (const float4*)(x + (size_t)row * HID);
    const float4* w4 = (const float4*)w;

    float4 v0 = xr[threadIdx.x];
    float4 v1 = xr[threadIdx.x + 256];
    float ss = v0.x*v0.x + v0.y*v0.y + v0.z*v0.z + v0.w*v0.w
             + v1.x*v1.x + v1.y*v1.y + v1.z*v1.z + v1.w*v1.w;
    #pragma unroll
    for (int off = 16; off > 0; off >>= 1) ss += __shfl_xor_sync(0xffffffffu, ss, off);

    __shared__ float red[8]; __shared__ float s_inv;
    if ((threadIdx.x & 31) == 0) red[threadIdx.x >> 5] = ss;
    __syncthreads();
    if (threadIdx.x == 0) {
        float t = 0.f;
        #pragma unroll
        for (int i = 0; i < 8; i++) t += red[i];
        s_inv = rsqrtf(t * (1.f / (float)HID) + 1e-6f);
    }
    __syncthreads();
    const float inv = s_inv;

    const float4 w0 = w4[threadIdx.x], w1 = w4[threadIdx.x + 256];
    float o[8] = { v0.x*inv*w0.x, v0.y*inv*w0.y, v0.z*inv*w0.z, v0.w*inv*w0.w,
                   v1.x*inv*w1.x, v1.y*inv*w1.y, v1.z*inv*w1.z, v1.w*inv*w1.w };
    const size_t b0 = (size_t)row * HID + threadIdx.x * 4;
    const size_t b1 = (size_t)row * HID + (threadIdx.x + 256) * 4;
    #pragma unroll
    for (int j = 0; j < 4; j++) {
        __nv_bfloat16 h = __float2bfloat16(o[j]);
        yh[b0 + j] = h; yl[b0 + j] = __float2bfloat16(o[j] - __bfloat162float(h));
    }
    #pragma unroll
    for (int j = 0; j < 4; j++) {
        __nv_bfloat16 h = __float2bfloat16(o[4 + j]);
        yh[b1 + j] = h; yl[b1 + j] = __float2bfloat16(o[4 + j] - __bfloat162float(h));
    }
}

// ======================= launch =============================================
extern "C" void kernel_launch(void* const* d_in, const int* in_sizes, int n_in,
                              void* d_out, int out_size)
{
    const float* hidden = (const float*)d_in[0];
    const float* wq  = (const float*)d_in[1];
    const float* wk  = (const float*)d_in[2];
    const float* wv  = (const float*)d_in[3];
    const float* wo  = (const float*)d_in[4];
    const float* wg  = (const float*)d_in[5];
    const float* wu  = (const float*)d_in[6];
    const float* wd  = (const float*)d_in[7];
    const float* ln1 = (const float*)d_in[8];
    const float* ln2 = (const float*)d_in[9];

    __nv_bfloat16 *pwq_h,*pwq_l,*pwk_h,*pwk_l,*pwv_h,*pwv_l,*pwo_h,*pwo_l;
    __nv_bfloat16 *pwgu_h,*pwgu_l,*pwd_h,*pwd_l;
    __nv_bfloat16 *px_h,*px_l,*pat_h,*pat_l,*pm_h,*pm_l;
    __nv_bfloat16 *pq_h,*pq_l,*pk_h,*pk_l,*pv_h,*pv_l,*pvt_h,*pvt_l;
    float *h1;
    cudaGetSymbolAddress((void**)&pwq_h, w_q_hi); cudaGetSymbolAddress((void**)&pwq_l, w_q_lo);
    cudaGetSymbolAddress((void**)&pwk_h, w_k_hi); cudaGetSymbolAddress((void**)&pwk_l, w_k_lo);
    cudaGetSymbolAddress((void**)&pwv_h, w_v_hi); cudaGetSymbolAddress((void**)&pwv_l, w_v_lo);
    cudaGetSymbolAddress((void**)&pwo_h, w_o_hi); cudaGetSymbolAddress((void**)&pwo_l, w_o_lo);
    cudaGetSymbolAddress((void**)&pwgu_h, w_gu_hi); cudaGetSymbolAddress((void**)&pwgu_l, w_gu_lo);
    cudaGetSymbolAddress((void**)&pwd_h, w_d_hi); cudaGetSymbolAddress((void**)&pwd_l, w_d_lo);
    cudaGetSymbolAddress((void**)&px_h,  a_x_hi); cudaGetSymbolAddress((void**)&px_l,  a_x_lo);
    cudaGetSymbolAddress((void**)&pat_h, a_at_hi);cudaGetSymbolAddress((void**)&pat_l, a_at_lo);
    cudaGetSymbolAddress((void**)&pm_h,  a_m_hi); cudaGetSymbolAddress((void**)&pm_l,  a_m_lo);
    cudaGetSymbolAddress((void**)&pq_h,  q_bhi);  cudaGetSymbolAddress((void**)&pq_l,  q_blo);
    cudaGetSymbolAddress((void**)&pk_h,  k_bhi);  cudaGetSymbolAddress((void**)&pk_l,  k_blo);
    cudaGetSymbolAddress((void**)&pv_h,  v_bhi);  cudaGetSymbolAddress((void**)&pv_l,  v_blo);
    cudaGetSymbolAddress((void**)&pvt_h, vt_hi);  cudaGetSymbolAddress((void**)&pvt_l, vt_lo);
    cudaGetSymbolAddress((void**)&h1, s_h1);

    cudaFuncSetAttribute(gemm3bf<0>, cudaFuncAttributeMaxDynamicSharedMemorySize, GEMM_SMEM);
    cudaFuncSetAttribute(gemm3bf<1>, cudaFuncAttributeMaxDynamicSharedMemorySize, GEMM_SMEM);
    cudaFuncSetAttribute(gemm3bf<2>, cudaFuncAttributeMaxDynamicSharedMemorySize, GEMM_SMEM);
    cudaFuncSetAttribute(gemm3bf<3>, cudaFuncAttributeMaxDynamicSharedMemorySize, GEMM_SMEM);
    cudaFuncSetAttribute(attn_mma_k, cudaFuncAttributeMaxDynamicSharedMemorySize, ATTN_SMEM);

    // batched weight transpose+split: 3 launches total
    dim3 tb(32, 8);
    {
        TCJobs jqkvo;
        jqkvo.j[0] = { wq, pwq_h, pwq_l, 0 };
        jqkvo.j[1] = { wk, pwk_h, pwk_l, 0 };
        jqkvo.j[2] = { wv, pwv_h, pwv_l, 0 };
        jqkvo.j[3] = { wo, pwo_h, pwo_l, 0 };
        transconv64_k<<<dim3(HID/64, HID/64, 4), tb>>>(jqkvo, HID, HID, 1);

        TCJobs jgu;
        jgu.j[0] = { wg, pwgu_h, pwgu_l, 0 };
        jgu.j[1] = { wu, pwgu_h, pwgu_l, 1 };
        jgu.j[2] = { wg, pwgu_h, pwgu_l, 0 };   // unused (z<2)
        jgu.j[3] = { wg, pwgu_h, pwgu_l, 0 };
        transconv64_k<<<dim3(INTER/64, HID/64, 2), tb>>>(jgu, HID, INTER, 2);

        TCJobs jd;
        jd.j[0] = { wd, pwd_h, pwd_l, 0 };
        jd.j[1] = jd.j[0]; jd.j[2] = jd.j[0]; jd.j[3] = jd.j[0];
        transconv64_k<<<dim3(HID/64, INTER/64, 1), tb>>>(jd, INTER, HID, 1);
    }

    // 1) rmsnorm -> bf16 hi/lo
    rmsnorm_conv_k<<<MTOK, 256>>>(hidden, ln1, px_h, px_l);

    // 2) QKV projections
    const float sc = 0.08838834764831845f;
    dim3 gHH(HID/128, MTOK/256);   // (16, 16)
    gemm3bf<2><<<gHH, 256, GEMM_SMEM>>>(px_h, px_l, pwq_h, pwq_l, nullptr, nullptr,
                                        pq_h, pq_l, sc, MTOK, HID, HID);
    gemm3bf<2><<<gHH, 256, GEMM_SMEM>>>(px_h, px_l, pwk_h, pwk_l, nullptr, nullptr,
                                        pk_h, pk_l, 1.f, MTOK, HID, HID);
    gemm3bf<2><<<gHH, 256, GEMM_SMEM>>>(px_h, px_l, pwv_h, pwv_l, nullptr, nullptr,
                                        pv_h, pv_l, 1.f, MTOK, HID, HID);
    vtrans_bf_k<<<dim3(64, 4, 32), tb>>>(pv_h, pv_l, pvt_h, pvt_l);

    // 3) tensor-core attention -> bf16 hi/lo
    attn_mma_k<<<dim3(16, 16, 2), 256, ATTN_SMEM>>>(pq_h, pq_l, pk_h, pk_l,
                                                    pvt_h, pvt_l, pat_h, pat_l);

    // 4) O-proj + residual
    gemm3bf<1><<<gHH, 256, GEMM_SMEM>>>(pat_h, pat_l, pwo_h, pwo_l, hidden, h1,
                                        nullptr, nullptr, 1.f, MTOK, HID, HID);

    // 5) rmsnorm2 -> bf16 hi/lo
    rmsnorm_conv_k<<<MTOK, 256>>>(h1, ln2, px_h, px_l);

    // 6) fused gate+up GEMM with silu-mul epilogue -> m (bf16 hi/lo) directly
    gemm3bf<3><<<dim3(2*INTER/128, MTOK/256), 256, GEMM_SMEM>>>(
        px_h, px_l, pwgu_h, pwgu_l, nullptr, nullptr,
        pm_h, pm_l, 1.f, MTOK, 2*INTER, HID);

    // 7) down-proj + residual -> d_out
    gemm3bf<1><<<gHH, 256, GEMM_SMEM>>>(pm_h, pm_l, pwd_h, pwd_l, h1, (float*)d_out,
                                        nullptr, nullptr, 1.f, MTOK, HID, INTER);
}

// round 12
// speedup vs baseline: 1.0096x; 1.0032x over previous
#include <cuda_runtime.h>
#include <cuda_bf16.h>
#include <math.h>
#include <stdint.h>

#define MTOK 4096      // B*S
#define HID  2048
#define INTER 8192

// ======================= device scratch (no allocations) ====================
__device__ __nv_bfloat16 w_q_hi[HID*HID],  w_q_lo[HID*HID];
__device__ __nv_bfloat16 w_k_hi[HID*HID],  w_k_lo[HID*HID];
__device__ __nv_bfloat16 w_v_hi[HID*HID],  w_v_lo[HID*HID];
__device__ __nv_bfloat16 w_o_hi[HID*HID],  w_o_lo[HID*HID];
__device__ __nv_bfloat16 w_gu_hi[(size_t)2*INTER*HID], w_gu_lo[(size_t)2*INTER*HID]; // interleaved
__device__ __nv_bfloat16 w_d_hi[(size_t)HID*INTER], w_d_lo[(size_t)HID*INTER];
__device__ __nv_bfloat16 a_x_hi[MTOK*HID],  a_x_lo[MTOK*HID];
__device__ __nv_bfloat16 a_at_hi[MTOK*HID], a_at_lo[MTOK*HID];
__device__ __nv_bfloat16 a_m_hi[(size_t)MTOK*INTER], a_m_lo[(size_t)MTOK*INTER];
__device__ __nv_bfloat16 q_bhi[MTOK*HID], q_blo[MTOK*HID];
__device__ __nv_bfloat16 k_bhi[MTOK*HID], k_blo[MTOK*HID];
__device__ __nv_bfloat16 v_bhi[MTOK*HID], v_blo[MTOK*HID];
__device__ __nv_bfloat16 vt_hi[MTOK*HID], vt_lo[MTOK*HID];   // [b*16+h][hd][kv]
__device__ float s_h1[MTOK*HID];

// ======================= helpers ============================================
__device__ __forceinline__ uint32_t smem_u32(const void* p) {
    uint32_t a;
    asm("{ .reg .u64 t; cvta.to.shared.u64 t, %1; cvt.u32.u64 %0, t; }" : "=r"(a) : "l"(p));
    return a;
}
__device__ __forceinline__ void cp16(uint32_t s, const void* g) {
    asm volatile("cp.async.cg.shared.global [%0], [%1], 16;" :: "r"(s), "l"(g));
}
#define CP_COMMIT() asm volatile("cp.async.commit_group;")
#define CP_WAIT(N)  asm volatile("cp.async.wait_group %0;" :: "n"(N))

__device__ __forceinline__ void mma_bf16(float* c, const uint32_t* a, const uint32_t* b) {
    asm volatile(
        "mma.sync.aligned.m16n8k16.row.col.f32.bf16.bf16.f32 "
        "{%0,%1,%2,%3}, {%4,%5,%6,%7}, {%8,%9}, {%0,%1,%2,%3};"
        : "+f"(c[0]), "+f"(c[1]), "+f"(c[2]), "+f"(c[3])
        : "r"(a[0]), "r"(a[1]), "r"(a[2]), "r"(a[3]), "r"(b[0]), "r"(b[1]));
}
__device__ __forceinline__ void split2(float x, float y, uint32_t& hi, uint32_t& lo) {
    __nv_bfloat162 h;
    h.x = __float2bfloat16(x); h.y = __float2bfloat16(y);
    __nv_bfloat162 l;
    l.x = __float2bfloat16(x - __bfloat162float(h.x));
    l.y = __float2bfloat16(y - __bfloat162float(h.y));
    hi = *reinterpret_cast<uint32_t*>(&h);
    lo = *reinterpret_cast<uint32_t*>(&l);
}

// ======================= bf16x3 mma.sync GEMM (round-8 core) ================
// OM: 0 = fp32 out, 1 = fp32 out + residual, 2 = bf16 hi/lo out (scaled),
//     3 = fused silu(even)*odd -> bf16 hi/lo out at column c/2 (Nout = N/2)
#define RB    144
#define ATILE (256*RB)
#define BTILE (128*RB)
#define STG   (2*ATILE + 2*BTILE)  // 110592
#define GEMM_SMEM (2*STG)          // 221184

template<int OM>
__global__ __launch_bounds__(256) void gemm3bf(
    const __nv_bfloat16* __restrict__ Ahi, const __nv_bfloat16* __restrict__ Alo,
    const __nv_bfloat16* __restrict__ Bhi, const __nv_bfloat16* __restrict__ Blo,
    const float* __restrict__ R, float* __restrict__ C,
    __nv_bfloat16* __restrict__ Ch, __nv_bfloat16* __restrict__ Cl,
    float scale, int M, int N, int K)
{
    extern __shared__ char sm[];
    const uint32_t sbase = smem_u32(sm);

    const int tid = threadIdx.x;
    const int lane = tid & 31;
    const int wid = tid >> 5;
    const int g = lane >> 2, tig = lane & 3;
    const int warp_m = wid & 3;
    const int warp_n = wid >> 2;
    const int bm = blockIdx.y * 256;
    const int bn = blockIdx.x * 128;

    const int crow = tid >> 3;
    const int ccolB = (tid & 7) * 16;

    const int S = K >> 6;

    auto load_stage = [&](int s) {
        const uint32_t b = sbase + (uint32_t)(s & 1) * STG;
        const int k0 = s << 6;
        const size_t ga = ((size_t)(bm + crow) * K + k0) * 2 + ccolB;
        const size_t gb = ((size_t)(bn + crow) * K + k0) * 2 + ccolB;
        const size_t rstep = (size_t)32 * K * 2;
        const char* pah = (const char*)Ahi + ga;
        const char* pal = (const char*)Alo + ga;
        const char* pbh = (const char*)Bhi + gb;
        const char* pbl = (const char*)Blo + gb;
        #pragma unroll
        for (int i = 0; i < 8; i++) {
            const uint32_t so = (uint32_t)((crow + 32*i) * RB + ccolB);
            cp16(b + so,         pah); pah += rstep;
            cp16(b + ATILE + so, pal); pal += rstep;
        }
        #pragma unroll
        for (int i = 0; i < 4; i++) {
            const uint32_t so = (uint32_t)((crow + 32*i) * RB + ccolB);
            cp16(b + 2*ATILE + so,         pbh); pbh += rstep;
            cp16(b + 2*ATILE + BTILE + so, pbl); pbl += rstep;
        }
        CP_COMMIT();
    };

    load_stage(0);
    if (S > 1) load_stage(1);

    float acc[4][8][4];
    #pragma unroll
    for (int mt = 0; mt < 4; mt++)
        #pragma unroll
        for (int nt = 0; nt < 8; nt++)
            #pragma unroll
            for (int e = 0; e < 4; e++) acc[mt][nt][e] = 0.f;

    const int arow0 = warp_m * 64 + g;
    const int brow0 = warp_n * 64 + g;

    for (int s = 0; s < S; ++s) {
        if (s + 1 < S) { CP_WAIT(1); } else { CP_WAIT(0); }
        __syncthreads();
        const char* b = sm + (size_t)(s & 1) * STG;

        #pragma unroll
        for (int ks = 0; ks < 4; ++ks) {
            const int kb = ks * 32 + tig * 4;

            uint32_t bhf[8][2], blf[8][2];
            #pragma unroll
            for (int nt = 0; nt < 8; nt++) {
                const char* rb = b + 2*ATILE + (brow0 + nt*8) * RB + kb;
                bhf[nt][0] = *(const uint32_t*)(rb);
                bhf[nt][1] = *(const uint32_t*)(rb + 16);
                blf[nt][0] = *(const uint32_t*)(rb + BTILE);
                blf[nt][1] = *(const uint32_t*)(rb + BTILE + 16);
            }

            #pragma unroll
            for (int mt = 0; mt < 4; mt++) {
                uint32_t ah[4], al[4];
                const char* ra = b + (arow0 + mt*16) * RB + kb;
                ah[0] = *(const uint32_t*)(ra);
                ah[1] = *(const uint32_t*)(ra + 8*RB);
                ah[2] = *(const uint32_t*)(ra + 16);
                ah[3] = *(const uint32_t*)(ra + 8*RB + 16);
                al[0] = *(const uint32_t*)(ra + ATILE);
                al[1] = *(const uint32_t*)(ra + ATILE + 8*RB);
                al[2] = *(const uint32_t*)(ra + ATILE + 16);
                al[3] = *(const uint32_t*)(ra + ATILE + 8*RB + 16);

                #pragma unroll
                for (int nt = 0; nt < 8; nt++)
                    mma_bf16(acc[mt][nt], ah, bhf[nt]);
                #pragma unroll
                for (int nt = 0; nt < 8; nt++)
                    mma_bf16(acc[mt][nt], ah, blf[nt]);
                #pragma unroll
                for (int nt = 0; nt < 8; nt++)
                    mma_bf16(acc[mt][nt], al, bhf[nt]);
            }
        }
        __syncthreads();
        if (s + 2 < S) load_stage(s + 2);
    }

    const int row0 = bm + warp_m*64 + g;
    const int col0 = bn + warp_n*64 + tig*2;
    #pragma unroll
    for (int mt = 0; mt < 4; mt++) {
        #pragma unroll
        for (int nt = 0; nt < 8; nt++) {
            const int r = row0 + mt*16;
            const int c = col0 + nt*8;
            if (OM == 3) {
                const int Nout = N >> 1;
                const int cc = c >> 1;
                const float g0 = acc[mt][nt][0], u0 = acc[mt][nt][1];
                const float g1 = acc[mt][nt][2], u1 = acc[mt][nt][3];
                const float r0 = g0 / (1.f + __expf(-g0)) * u0;
                const float r1 = g1 / (1.f + __expf(-g1)) * u1;
                const __nv_bfloat16 h0 = __float2bfloat16(r0);
                const __nv_bfloat16 h1 = __float2bfloat16(r1);
                Ch[(size_t)r * Nout + cc]     = h0;
                Cl[(size_t)r * Nout + cc]     = __float2bfloat16(r0 - __bfloat162float(h0));
                Ch[(size_t)(r+8) * Nout + cc] = h1;
                Cl[(size_t)(r+8) * Nout + cc] = __float2bfloat16(r1 - __bfloat162float(h1));
            } else if (OM == 2) {
                uint32_t h0, l0u, h1, l1u;
                split2(acc[mt][nt][0]*scale, acc[mt][nt][1]*scale, h0, l0u);
                split2(acc[mt][nt][2]*scale, acc[mt][nt][3]*scale, h1, l1u);
                *(uint32_t*)(Ch + (size_t)r * N + c)     = h0;
                *(uint32_t*)(Cl + (size_t)r * N + c)     = l0u;
                *(uint32_t*)(Ch + (size_t)(r+8) * N + c) = h1;
                *(uint32_t*)(Cl + (size_t)(r+8) * N + c) = l1u;
            } else {
                float2 v0 = make_float2(acc[mt][nt][0], acc[mt][nt][1]);
                float2 v1 = make_float2(acc[mt][nt][2], acc[mt][nt][3]);
                if (OM == 1) {
                    const float2 r0 = *(const float2*)(R + (size_t)r * N + c);
                    const float2 r1 = *(const float2*)(R + (size_t)(r+8) * N + c);
                    v0.x += r0.x; v0.y += r0.y;
                    v1.x += r1.x; v1.y += r1.y;
                }
                *(float2*)(C + (size_t)r * N + c)     = v0;
                *(float2*)(C + (size_t)(r+8) * N + c) = v1;
            }
        }
    }
}

// ======================= tensor-core causal flash attention =================
// (verbatim champion)
#define RBQ 272
#define RBV 144
#define QT_BYTES (128*RBQ)
#define KT_BYTES (64*RBQ)
#define VT_BYTES (128*RBV)
#define STAGE_B  (2*KT_BYTES + 2*VT_BYTES)
#define ATTN_SMEM (2*QT_BYTES + 2*STAGE_B)

__global__ __launch_bounds__(256) void attn_mma_k(
    const __nv_bfloat16* __restrict__ qh, const __nv_bfloat16* __restrict__ ql,
    const __nv_bfloat16* __restrict__ kh, const __nv_bfloat16* __restrict__ kl,
    const __nv_bfloat16* __restrict__ vh, const __nv_bfloat16* __restrict__ vl,
    __nv_bfloat16* __restrict__ Oh, __nv_bfloat16* __restrict__ Ol)
{
    extern __shared__ char sm[];
    const uint32_t sb = smem_u32(sm);

    const int tid = threadIdx.x, lane = tid & 31, wid = tid >> 5;
    const int g = lane >> 2, tig = lane & 3;
    const int qt = 15 - blockIdx.x, h = blockIdx.y, b = blockIdx.z;
    const int ntiles = 2 * (qt + 1);

    {
        const size_t gq = ((size_t)(b*2048 + qt*128) * 2048 + h*128) * 2;
        #pragma unroll
        for (int i = 0; i < 16; i++) {
            const int c = tid + i*256;
            const int t = c >> 11;
            const int cc = c & 2047;
            const int row = cc >> 4, col = cc & 15;
            const char* gp = (const char*)(t ? ql : qh) + gq + (size_t)row*4096 + col*16;
            cp16(sb + (t ? QT_BYTES : 0) + row*RBQ + col*16, gp);
        }
        CP_COMMIT();
    }

    auto load_stage = [&](int kt) {
        const uint32_t base = sb + 2*QT_BYTES + (uint32_t)(kt & 1) * STAGE_B;
        const size_t gk = ((size_t)(b*2048 + kt*64) * 2048 + h*128) * 2;
        const size_t gv = (((size_t)((b*16 + h)*128)) * 2048 + kt*64) * 2;
        #pragma unroll
        for (int i = 0; i < 16; i++) {
            const int c = tid + i*256;
            const int sel = c >> 10;
            const int cc = c & 1023;
            if (sel < 2) {
                const int row = cc >> 4, col = cc & 15;
                const char* gp = (const char*)(sel ? kl : kh) + gk + (size_t)row*4096 + col*16;
                cp16(base + (sel ? KT_BYTES : 0) + row*RBQ + col*16, gp);
            } else {
                const int row = cc >> 3, col = cc & 7;
                const char* gp = (const char*)(sel == 3 ? vl : vh) + gv + (size_t)row*4096 + col*16;
                cp16(base + 2*KT_BYTES + (sel == 3 ? VT_BYTES : 0) + row*RBV + col*16, gp);
            }
        }
        CP_COMMIT();
    };

    load_stage(0);
    load_stage(1);

    float accO[16][4];
    #pragma unroll
    for (int nt = 0; nt < 16; nt++)
        #pragma unroll
        for (int e = 0; e < 4; e++) accO[nt][e] = 0.f;
    float m0 = -INFINITY, m1 = -INFINITY, l0 = 0.f, l1 = 0.f;

    const int row0 = wid * 16;
    const int qrow0 = qt*128 + row0 + g;

    for (int s = 0; s < ntiles; s++) {
        if (s + 1 < ntiles) { CP_WAIT(1); } else { CP_WAIT(0); }
        __syncthreads();
        const char* stg = sm + 2*QT_BYTES + (size_t)(s & 1) * STAGE_B;

        float accS[8][4];
        #pragma unroll
        for (int nt = 0; nt < 8; nt++)
            #pragma unroll
            for (int e = 0; e < 4; e++) accS[nt][e] = 0.f;

        #pragma unroll
        for (int ks = 0; ks < 8; ks++) {
            const int kb = ks*32 + tig*4;
            uint32_t ah[4], al[4], bh2[8][2], bl2[8][2];
            const char* ra = sm + (row0 + g)*RBQ + kb;
            ah[0] = *(const uint32_t*)(ra);
            ah[1] = *(const uint32_t*)(ra + 8*RBQ);
            ah[2] = *(const uint32_t*)(ra + 16);
            ah[3] = *(const uint32_t*)(ra + 8*RBQ + 16);
            al[0] = *(const uint32_t*)(ra + QT_BYTES);
            al[1] = *(const uint32_t*)(ra + QT_BYTES + 8*RBQ);
            al[2] = *(const uint32_t*)(ra + QT_BYTES + 16);
            al[3] = *(const uint32_t*)(ra + QT_BYTES + 8*RBQ + 16);
            #pragma unroll
            for (int nt = 0; nt < 8; nt++) {
                const char* rb = stg + (nt*8 + g)*RBQ + kb;
                bh2[nt][0] = *(const uint32_t*)(rb);
                bh2[nt][1] = *(const uint32_t*)(rb + 16);
                bl2[nt][0] = *(const uint32_t*)(rb + KT_BYTES);
                bl2[nt][1] = *(const uint32_t*)(rb + KT_BYTES + 16);
            }
            #pragma unroll
            for (int nt = 0; nt < 8; nt++) mma_bf16(accS[nt], ah, bh2[nt]);
            #pragma unroll
            for (int nt = 0; nt < 8; nt++) mma_bf16(accS[nt], ah, bl2[nt]);
            #pragma unroll
            for (int nt = 0; nt < 8; nt++) mma_bf16(accS[nt], al, bh2[nt]);
        }

        if (s >= ntiles - 2) {
            #pragma unroll
            for (int nt = 0; nt < 8; nt++) {
                const int col = s*64 + nt*8 + tig*2;
                if (col     > qrow0)     accS[nt][0] = -INFINITY;
                if (col + 1 > qrow0)     accS[nt][1] = -INFINITY;
                if (col     > qrow0 + 8) accS[nt][2] = -INFINITY;
                if (col + 1 > qrow0 + 8) accS[nt][3] = -INFINITY;
            }
        }

        float mt0 = -INFINITY, mt1 = -INFINITY;
        #pragma unroll
        for (int nt = 0; nt < 8; nt++) {
            mt0 = fmaxf(mt0, fmaxf(accS[nt][0], accS[nt][1]));
            mt1 = fmaxf(mt1, fmaxf(accS[nt][2], accS[nt][3]));
        }
        mt0 = fmaxf(mt0, __shfl_xor_sync(0xffffffffu, mt0, 1));
        mt0 = fmaxf(mt0, __shfl_xor_sync(0xffffffffu, mt0, 2));
        mt1 = fmaxf(mt1, __shfl_xor_sync(0xffffffffu, mt1, 1));
        mt1 = fmaxf(mt1, __shfl_xor_sync(0xffffffffu, mt1, 2));

        const float mn0 = fmaxf(m0, mt0), mn1 = fmaxf(m1, mt1);
        const float sc0 = __expf(m0 - mn0), sc1 = __expf(m1 - mn1);
        m0 = mn0; m1 = mn1;

        float rs0 = 0.f, rs1 = 0.f;
        #pragma unroll
        for (int nt = 0; nt < 8; nt++) {
            accS[nt][0] = __expf(accS[nt][0] - mn0);
            accS[nt][1] = __expf(accS[nt][1] - mn0);
            accS[nt][2] = __expf(accS[nt][2] - mn1);
            accS[nt][3] = __expf(accS[nt][3] - mn1);
            rs0 += accS[nt][0] + accS[nt][1];
            rs1 += accS[nt][2] + accS[nt][3];
        }
        rs0 += __shfl_xor_sync(0xffffffffu, rs0, 1);
        rs0 += __shfl_xor_sync(0xffffffffu, rs0, 2);
        rs1 += __shfl_xor_sync(0xffffffffu, rs1, 1);
        rs1 += __shfl_xor_sync(0xffffffffu, rs1, 2);
        l0 = l0*sc0 + rs0;
        l1 = l1*sc1 + rs1;

        #pragma unroll
        for (int nt = 0; nt < 16; nt++) {
            accO[nt][0] *= sc0; accO[nt][1] *= sc0;
            accO[nt][2] *= sc1; accO[nt][3] *= sc1;
        }

        #pragma unroll
        for (int kk = 0; kk < 4; kk++) {
            uint32_t ph[4], pl[4];
            split2(accS[2*kk][0],   accS[2*kk][1],   ph[0], pl[0]);
            split2(accS[2*kk][2],   accS[2*kk][3],   ph[1], pl[1]);
            split2(accS[2*kk+1][0], accS[2*kk+1][1], ph[2], pl[2]);
            split2(accS[2*kk+1][2], accS[2*kk+1][3], ph[3], pl[3]);
            const int kb = kk*32 + tig*4;
            #pragma unroll
            for (int nt = 0; nt < 16; nt++) {
                const char* rv = stg + 2*KT_BYTES + (nt*8 + g)*RBV + kb;
                uint32_t vbh[2], vbl[2];
                vbh[0] = *(const uint32_t*)(rv);
                vbh[1] = *(const uint32_t*)(rv + 16);
                vbl[0] = *(const uint32_t*)(rv + VT_BYTES);
                vbl[1] = *(const uint32_t*)(rv + VT_BYTES + 16);
                mma_bf16(accO[nt], ph, vbh);
                mma_bf16(accO[nt], ph, vbl);
                mma_bf16(accO[nt], pl, vbh);
            }
        }

        __syncthreads();
        if (s + 2 < ntiles) load_stage(s + 2);
    }

    const float inv0 = 1.f / l0, inv1 = 1.f / l1;
    const size_t ob = ((size_t)(b*2048 + qt*128 + row0 + g)) * 2048 + h*128;
    #pragma unroll
    for (int nt = 0; nt < 16; nt++) {
        const int c = nt*8 + tig*2;
        uint32_t h0, l0u, h1, l1u;
        split2(accO[nt][0]*inv0, accO[nt][1]*inv0, h0, l0u);
        split2(accO[nt][2]*inv1, accO[nt][3]*inv1, h1, l1u);
        *(uint32_t*)(Oh + ob + c)           = h0;
        *(uint32_t*)(Ol + ob + c)           = l0u;
        *(uint32_t*)(Oh + ob + 8*2048 + c)  = h1;
        *(uint32_t*)(Ol + ob + 8*2048 + c)  = l1u;
    }
}

// ======================= batched weight transpose + split ====================
struct TCJob  { const float* W; __nv_bfloat16* Th; __nv_bfloat16* Tl; int rowOff; };
struct TCJobs { TCJob j[4]; };

__global__ void transconv64_k(TCJobs jobs, int K, int N, int rowStride)
{
    const TCJob jb = jobs.j[blockIdx.z];
    __shared__ float t[64][65];
    const int n0 = blockIdx.x * 64, k0 = blockIdx.y * 64;
    const int tx = threadIdx.x, ty = threadIdx.y;   // (32, 8)
    #pragma unroll
    for (int r = ty; r < 64; r += 8) {
        const float2 v = *(const float2*)(jb.W + (size_t)(k0 + r) * N + n0 + 2*tx);
        t[r][2*tx]   = v.x;
        t[r][2*tx+1] = v.y;
    }
    __syncthreads();
    #pragma unroll
    for (int i = ty; i < 64; i += 8) {
        uint32_t hi, lo;
        split2(t[2*tx][i], t[2*tx+1][i], hi, lo);
        const size_t o = ((size_t)(n0 + i) * rowStride + jb.rowOff) * K + k0 + 2*tx;
        *(uint32_t*)(jb.Th + o) = hi;
        *(uint32_t*)(jb.Tl + o) = lo;
    }
}

// ======================= V transpose (64x64, u32 I/O) ========================
// Vh/Vl: [tok][2048] -> Th/Tl: [b*16+h][hd][kv=2048]
__global__ void vtrans64_k(const __nv_bfloat16* __restrict__ Vh,
                           const __nv_bfloat16* __restrict__ Vl,
                           __nv_bfloat16* __restrict__ Th, __nv_bfloat16* __restrict__ Tl)
{
    __shared__ __nv_bfloat16 th[64][66], tl[64][66];   // pad 66: u32-aligned, <=2-way conflicts
    const int kv0 = blockIdx.x * 64, hd0 = blockIdx.y * 64, bh = blockIdx.z;
    const int b = bh >> 4, h = bh & 15;
    const int tx = threadIdx.x, ty = threadIdx.y;      // (32, 8)
    #pragma unroll
    for (int r = ty; r < 64; r += 8) {
        const size_t src = (size_t)(b*2048 + kv0 + r) * 2048 + h*128 + hd0 + 2*tx;
        *(uint32_t*)&th[r][2*tx] = *(const uint32_t*)(Vh + src);
        *(uint32_t*)&tl[r][2*tx] = *(const uint32_t*)(Vl + src);
    }
    __syncthreads();
    #pragma unroll
    for (int i = ty; i < 64; i += 8) {
        __nv_bfloat162 ph, pl;
        ph.x = th[2*tx][i]; ph.y = th[2*tx+1][i];
        pl.x = tl[2*tx][i]; pl.y = tl[2*tx+1][i];
        const size_t o = ((size_t)(bh*128 + hd0 + i)) * 2048 + kv0 + 2*tx;
        *(uint32_t*)(Th + o) = *(uint32_t*)&ph;
        *(uint32_t*)(Tl + o) = *(uint32_t*)&pl;
    }
}

// ======================= RMSNorm: warp-per-row, barrier-free ================
// block = 8 warps, each warp owns one row; two passes (sum-sq, then store).
__global__ __launch_bounds__(256) void rmsnorm_warp_k(
    const float* __restrict__ x, const float* __restrict__ w,
    __nv_bfloat16* __restrict__ yh, __nv_bfloat16* __restrict__ yl)
{
    const int row  = blockIdx.x * 8 + (threadIdx.x >> 5);
    const int lane = threadIdx.x & 31;
    const float4* xr = (const float4*)(x + (size_t)row * HID);
    const float4* w4 = (const float4*)w;

    float ss = 0.f;
    #pragma unroll
    for (int i = 0; i < 16; i++) {
        const float4 v = xr[i*32 + lane];
        ss += v.x*v.x + v.y*v.y + v.z*v.z + v.w*v.w;
    }
    #pragma unroll
    for (int off = 16; off > 0; off >>= 1)
        ss += __shfl_xor_sync(0xffffffffu, ss, off);
    const float inv = rsqrtf(ss * (1.f / (float)HID) + 1e-6f);

    #pragma unroll
    for (int i = 0; i < 16; i++) {
        const float4 v = xr[i*32 + lane];
        const float4 ww = w4[i*32 + lane];
        const float o0 = v.x*inv*ww.x, o1 = v.y*inv*ww.y;
        const float o2 = v.z*inv*ww.z, o3 = v.w*inv*ww.w;
        uint32_t h0, l0, h1, l1;
        split2(o0, o1, h0, l0);
        split2(o2, o3, h1, l1);
        const size_t base = (size_t)row * HID + (size_t)(i*32 + lane) * 4;
        uint2 vh = make_uint2(h0, h1), vl = make_uint2(l0, l1);
        *(uint2*)(yh + base) = vh;
        *(uint2*)(yl + base) = vl;
    }
}

// ======================= launch =============================================
extern "C" void kernel_launch(void* const* d_in, const int* in_sizes, int n_in,
                              void* d_out, int out_size)
{
    const float* hidden = (const float*)d_in[0];
    const float* wq  = (const float*)d_in[1];
    const float* wk  = (const float*)d_in[2];
    const float* wv  = (const float*)d_in[3];
    const float* wo  = (const float*)d_in[4];
    const float* wg  = (const float*)d_in[5];
    const float* wu  = (const float*)d_in[6];
    const float* wd  = (const float*)d_in[7];
    const float* ln1 = (const float*)d_in[8];
    const float* ln2 = (const float*)d_in[9];

    __nv_bfloat16 *pwq_h,*pwq_l,*pwk_h,*pwk_l,*pwv_h,*pwv_l,*pwo_h,*pwo_l;
    __nv_bfloat16 *pwgu_h,*pwgu_l,*pwd_h,*pwd_l;
    __nv_bfloat16 *px_h,*px_l,*pat_h,*pat_l,*pm_h,*pm_l;
    __nv_bfloat16 *pq_h,*pq_l,*pk_h,*pk_l,*pv_h,*pv_l,*pvt_h,*pvt_l;
    float *h1;
    cudaGetSymbolAddress((void**)&pwq_h, w_q_hi); cudaGetSymbolAddress((void**)&pwq_l, w_q_lo);
    cudaGetSymbolAddress((void**)&pwk_h, w_k_hi); cudaGetSymbolAddress((void**)&pwk_l, w_k_lo);
    cudaGetSymbolAddress((void**)&pwv_h, w_v_hi); cudaGetSymbolAddress((void**)&pwv_l, w_v_lo);
    cudaGetSymbolAddress((void**)&pwo_h, w_o_hi); cudaGetSymbolAddress((void**)&pwo_l, w_o_lo);
    cudaGetSymbolAddress((void**)&pwgu_h, w_gu_hi); cudaGetSymbolAddress((void**)&pwgu_l, w_gu_lo);
    cudaGetSymbolAddress((void**)&pwd_h, w_d_hi); cudaGetSymbolAddress((void**)&pwd_l, w_d_lo);
    cudaGetSymbolAddress((void**)&px_h,  a_x_hi); cudaGetSymbolAddress((void**)&px_l,  a_x_lo);
    cudaGetSymbolAddress((void**)&pat_h, a_at_hi);cudaGetSymbolAddress((void**)&pat_l, a_at_lo);
    cudaGetSymbolAddress((void**)&pm_h,  a_m_hi); cudaGetSymbolAddress((void**)&pm_l,  a_m_lo);
    cudaGetSymbolAddress((void**)&pq_h,  q_bhi);  cudaGetSymbolAddress((void**)&pq_l,  q_blo);
    cudaGetSymbolAddress((void**)&pk_h,  k_bhi);  cudaGetSymbolAddress((void**)&pk_l,  k_blo);
    cudaGetSymbolAddress((void**)&pv_h,  v_bhi);  cudaGetSymbolAddress((void**)&pv_l,  v_blo);
    cudaGetSymbolAddress((void**)&pvt_h, vt_hi);  cudaGetSymbolAddress((void**)&pvt_l, vt_lo);
    cudaGetSymbolAddress((void**)&h1, s_h1);

    cudaFuncSetAttribute(gemm3bf<0>, cudaFuncAttributeMaxDynamicSharedMemorySize, GEMM_SMEM);
    cudaFuncSetAttribute(gemm3bf<1>, cudaFuncAttributeMaxDynamicSharedMemorySize, GEMM_SMEM);
    cudaFuncSetAttribute(gemm3bf<2>, cudaFuncAttributeMaxDynamicSharedMemorySize, GEMM_SMEM);
    cudaFuncSetAttribute(gemm3bf<3>, cudaFuncAttributeMaxDynamicSharedMemorySize, GEMM_SMEM);
    cudaFuncSetAttribute(attn_mma_k, cudaFuncAttributeMaxDynamicSharedMemorySize, ATTN_SMEM);

    // batched weight transpose+split: 3 launches
    dim3 tb(32, 8);
    {
        TCJobs jqkvo;
        jqkvo.j[0] = { wq, pwq_h, pwq_l, 0 };
        jqkvo.j[1] = { wk, pwk_h, pwk_l, 0 };
        jqkvo.j[2] = { wv, pwv_h, pwv_l, 0 };
        jqkvo.j[3] = { wo, pwo_h, pwo_l, 0 };
        transconv64_k<<<dim3(HID/64, HID/64, 4), tb>>>(jqkvo, HID, HID, 1);

        TCJobs jgu;
        jgu.j[0] = { wg, pwgu_h, pwgu_l, 0 };
        jgu.j[1] = { wu, pwgu_h, pwgu_l, 1 };
        jgu.j[2] = jgu.j[0];
        jgu.j[3] = jgu.j[0];
        transconv64_k<<<dim3(INTER/64, HID/64, 2), tb>>>(jgu, HID, INTER, 2);

        TCJobs jd;
        jd.j[0] = { wd, pwd_h, pwd_l, 0 };
        jd.j[1] = jd.j[0]; jd.j[2] = jd.j[0]; jd.j[3] = jd.j[0];
        transconv64_k<<<dim3(HID/64, INTER/64, 1), tb>>>(jd, INTER, HID, 1);
    }

    // 1) rmsnorm -> bf16 hi/lo (warp-per-row)
    rmsnorm_warp_k<<<MTOK/8, 256>>>(hidden, ln1, px_h, px_l);

    // 2) QKV projections
    const float sc = 0.08838834764831845f;
    dim3 gHH(HID/128, MTOK/256);   // (16, 16)
    gemm3bf<2><<<gHH, 256, GEMM_SMEM>>>(px_h, px_l, pwq_h, pwq_l, nullptr, nullptr,
                                        pq_h, pq_l, sc, MTOK, HID, HID);
    gemm3bf<2><<<gHH, 256, GEMM_SMEM>>>(px_h, px_l, pwk_h, pwk_l, nullptr, nullptr,
                                        pk_h, pk_l, 1.f, MTOK, HID, HID);
    gemm3bf<2><<<gHH, 256, GEMM_SMEM>>>(px_h, px_l, pwv_h, pwv_l, nullptr, nullptr,
                                        pv_h, pv_l, 1.f, MTOK, HID, HID);
    vtrans64_k<<<dim3(32, 2, 32), tb>>>(pv_h, pv_l, pvt_h, pvt_l);

    // 3) tensor-core attention -> bf16 hi/lo
    attn_mma_k<<<dim3(16, 16, 2), 256, ATTN_SMEM>>>(pq_h, pq_l, pk_h, pk_l,
                                                    pvt_h, pvt_l, pat_h, pat_l);

    // 4) O-proj + residual
    gemm3bf<1><<<gHH, 256, GEMM_SMEM>>>(pat_h, pat_l, pwo_h, pwo_l, hidden, h1,
                                        nullptr, nullptr, 1.f, MTOK, HID, HID);

    // 5) rmsnorm2 -> bf16 hi/lo
    rmsnorm_warp_k<<<MTOK/8, 256>>>(h1, ln2, px_h, px_l);

    // 6) fused gate+up GEMM with silu-mul epilogue -> m (bf16 hi/lo)
    gemm3bf<3><<<dim3(2*INTER/128, MTOK/256), 256, GEMM_SMEM>>>(
        px_h, px_l, pwgu_h, pwgu_l, nullptr, nullptr,
        pm_h, pm_l, 1.f, MTOK, 2*INTER, HID);

    // 7) down-proj + residual -> d_out
    gemm3bf<1><<<gHH, 256, GEMM_SMEM>>>(pm_h, pm_l, pwd_h, pwd_l, h1, (float*)d_out,
                                        nullptr, nullptr, 1.f, MTOK, HID, INTER);
}

// round 13
// speedup vs baseline: 1.0154x; 1.0058x over previous
#include <cuda_runtime.h>
#include <cuda_bf16.h>
#include <math.h>
#include <stdint.h>

#define MTOK 4096      // B*S
#define HID  2048
#define INTER 8192

// ======================= device scratch (no allocations) ====================
__device__ __nv_bfloat16 w_q_hi[HID*HID],  w_q_lo[HID*HID];
__device__ __nv_bfloat16 w_k_hi[HID*HID],  w_k_lo[HID*HID];
__device__ __nv_bfloat16 w_v_hi[HID*HID],  w_v_lo[HID*HID];
__device__ __nv_bfloat16 w_o_hi[HID*HID],  w_o_lo[HID*HID];
__device__ __nv_bfloat16 w_gu_hi[(size_t)2*INTER*HID], w_gu_lo[(size_t)2*INTER*HID]; // interleaved
__device__ __nv_bfloat16 w_d_hi[(size_t)HID*INTER], w_d_lo[(size_t)HID*INTER];
__device__ __nv_bfloat16 a_x_hi[MTOK*HID],  a_x_lo[MTOK*HID];
__device__ __nv_bfloat16 a_at_hi[MTOK*HID], a_at_lo[MTOK*HID];
__device__ __nv_bfloat16 a_m_hi[(size_t)MTOK*INTER], a_m_lo[(size_t)MTOK*INTER];
__device__ __nv_bfloat16 q_bhi[MTOK*HID], q_blo[MTOK*HID];
__device__ __nv_bfloat16 k_bhi[MTOK*HID], k_blo[MTOK*HID];
__device__ __nv_bfloat16 v_bhi[MTOK*HID], v_blo[MTOK*HID];
__device__ __nv_bfloat16 vt_hi[MTOK*HID], vt_lo[MTOK*HID];   // [b*16+h][hd][kv]
__device__ float s_h1[MTOK*HID];

// ======================= helpers ============================================
__device__ __forceinline__ uint32_t smem_u32(const void* p) {
    uint32_t a;
    asm("{ .reg .u64 t; cvta.to.shared.u64 t, %1; cvt.u32.u64 %0, t; }" : "=r"(a) : "l"(p));
    return a;
}
__device__ __forceinline__ void cp16(uint32_t s, const void* g) {
    asm volatile("cp.async.cg.shared.global [%0], [%1], 16;" :: "r"(s), "l"(g));
}
#define CP_COMMIT() asm volatile("cp.async.commit_group;")
#define CP_WAIT(N)  asm volatile("cp.async.wait_group %0;" :: "n"(N))

__device__ __forceinline__ void mma_bf16(float* c, const uint32_t* a, const uint32_t* b) {
    asm volatile(
        "mma.sync.aligned.m16n8k16.row.col.f32.bf16.bf16.f32 "
        "{%0,%1,%2,%3}, {%4,%5,%6,%7}, {%8,%9}, {%0,%1,%2,%3};"
        : "+f"(c[0]), "+f"(c[1]), "+f"(c[2]), "+f"(c[3])
        : "r"(a[0]), "r"(a[1]), "r"(a[2]), "r"(a[3]), "r"(b[0]), "r"(b[1]));
}
__device__ __forceinline__ void split2(float x, float y, uint32_t& hi, uint32_t& lo) {
    __nv_bfloat162 h;
    h.x = __float2bfloat16(x); h.y = __float2bfloat16(y);
    __nv_bfloat162 l;
    l.x = __float2bfloat16(x - __bfloat162float(h.x));
    l.y = __float2bfloat16(y - __bfloat162float(h.y));
    hi = *reinterpret_cast<uint32_t*>(&h);
    lo = *reinterpret_cast<uint32_t*>(&l);
}

// ======================= bf16x3 mma.sync GEMM (champion core) ===============
// OM: 0 = fp32 out, 1 = fp32 out + residual, 2 = bf16 hi/lo out (scaled),
//     3 = fused silu(even)*odd -> bf16 hi/lo out at column c/2 (Nout = N/2)
#define RB    144
#define ATILE (256*RB)
#define BTILE (128*RB)
#define STG   (2*ATILE + 2*BTILE)  // 110592
#define GEMM_SMEM (2*STG)          // 221184

template<int OM>
__global__ __launch_bounds__(256) void gemm3bf(
    const __nv_bfloat16* __restrict__ Ahi, const __nv_bfloat16* __restrict__ Alo,
    const __nv_bfloat16* __restrict__ Bhi, const __nv_bfloat16* __restrict__ Blo,
    const float* __restrict__ R, float* __restrict__ C,
    __nv_bfloat16* __restrict__ Ch, __nv_bfloat16* __restrict__ Cl,
    float scale, int M, int N, int K)
{
    extern __shared__ char sm[];
    const uint32_t sbase = smem_u32(sm);

    const int tid = threadIdx.x;
    const int lane = tid & 31;
    const int wid = tid >> 5;
    const int g = lane >> 2, tig = lane & 3;
    const int warp_m = wid & 3;
    const int warp_n = wid >> 2;
    const int bm = blockIdx.y * 256;
    const int bn = blockIdx.x * 128;

    const int crow = tid >> 3;
    const int ccolB = (tid & 7) * 16;

    const int S = K >> 6;

    auto load_stage = [&](int s) {
        const uint32_t b = sbase + (uint32_t)(s & 1) * STG;
        const int k0 = s << 6;
        const size_t ga = ((size_t)(bm + crow) * K + k0) * 2 + ccolB;
        const size_t gb = ((size_t)(bn + crow) * K + k0) * 2 + ccolB;
        const size_t rstep = (size_t)32 * K * 2;
        const char* pah = (const char*)Ahi + ga;
        const char* pal = (const char*)Alo + ga;
        const char* pbh = (const char*)Bhi + gb;
        const char* pbl = (const char*)Blo + gb;
        #pragma unroll
        for (int i = 0; i < 8; i++) {
            const uint32_t so = (uint32_t)((crow + 32*i) * RB + ccolB);
            cp16(b + so,         pah); pah += rstep;
            cp16(b + ATILE + so, pal); pal += rstep;
        }
        #pragma unroll
        for (int i = 0; i < 4; i++) {
            const uint32_t so = (uint32_t)((crow + 32*i) * RB + ccolB);
            cp16(b + 2*ATILE + so,         pbh); pbh += rstep;
            cp16(b + 2*ATILE + BTILE + so, pbl); pbl += rstep;
        }
        CP_COMMIT();
    };

    load_stage(0);
    if (S > 1) load_stage(1);

    float acc[4][8][4];
    #pragma unroll
    for (int mt = 0; mt < 4; mt++)
        #pragma unroll
        for (int nt = 0; nt < 8; nt++)
            #pragma unroll
            for (int e = 0; e < 4; e++) acc[mt][nt][e] = 0.f;

    const int arow0 = warp_m * 64 + g;
    const int brow0 = warp_n * 64 + g;

    for (int s = 0; s < S; ++s) {
        if (s + 1 < S) { CP_WAIT(1); } else { CP_WAIT(0); }
        __syncthreads();
        const char* b = sm + (size_t)(s & 1) * STG;

        #pragma unroll
        for (int ks = 0; ks < 4; ++ks) {
            const int kb = ks * 32 + tig * 4;

            uint32_t bhf[8][2], blf[8][2];
            #pragma unroll
            for (int nt = 0; nt < 8; nt++) {
                const char* rb = b + 2*ATILE + (brow0 + nt*8) * RB + kb;
                bhf[nt][0] = *(const uint32_t*)(rb);
                bhf[nt][1] = *(const uint32_t*)(rb + 16);
                blf[nt][0] = *(const uint32_t*)(rb + BTILE);
                blf[nt][1] = *(const uint32_t*)(rb + BTILE + 16);
            }

            #pragma unroll
            for (int mt = 0; mt < 4; mt++) {
                uint32_t ah[4], al[4];
                const char* ra = b + (arow0 + mt*16) * RB + kb;
                ah[0] = *(const uint32_t*)(ra);
                ah[1] = *(const uint32_t*)(ra + 8*RB);
                ah[2] = *(const uint32_t*)(ra + 16);
                ah[3] = *(const uint32_t*)(ra + 8*RB + 16);
                al[0] = *(const uint32_t*)(ra + ATILE);
                al[1] = *(const uint32_t*)(ra + ATILE + 8*RB);
                al[2] = *(const uint32_t*)(ra + ATILE + 16);
                al[3] = *(const uint32_t*)(ra + ATILE + 8*RB + 16);

                #pragma unroll
                for (int nt = 0; nt < 8; nt++)
                    mma_bf16(acc[mt][nt], ah, bhf[nt]);
                #pragma unroll
                for (int nt = 0; nt < 8; nt++)
                    mma_bf16(acc[mt][nt], ah, blf[nt]);
                #pragma unroll
                for (int nt = 0; nt < 8; nt++)
                    mma_bf16(acc[mt][nt], al, bhf[nt]);
            }
        }
        __syncthreads();
        if (s + 2 < S) load_stage(s + 2);
    }

    const int row0 = bm + warp_m*64 + g;
    const int col0 = bn + warp_n*64 + tig*2;
    #pragma unroll
    for (int mt = 0; mt < 4; mt++) {
        #pragma unroll
        for (int nt = 0; nt < 8; nt++) {
            const int r = row0 + mt*16;
            const int c = col0 + nt*8;
            if (OM == 3) {
                const int Nout = N >> 1;
                const int cc = c >> 1;
                const float g0 = acc[mt][nt][0], u0 = acc[mt][nt][1];
                const float g1 = acc[mt][nt][2], u1 = acc[mt][nt][3];
                const float r0 = g0 / (1.f + __expf(-g0)) * u0;
                const float r1 = g1 / (1.f + __expf(-g1)) * u1;
                const __nv_bfloat16 h0 = __float2bfloat16(r0);
                const __nv_bfloat16 h1 = __float2bfloat16(r1);
                Ch[(size_t)r * Nout + cc]     = h0;
                Cl[(size_t)r * Nout + cc]     = __float2bfloat16(r0 - __bfloat162float(h0));
                Ch[(size_t)(r+8) * Nout + cc] = h1;
                Cl[(size_t)(r+8) * Nout + cc] = __float2bfloat16(r1 - __bfloat162float(h1));
            } else if (OM == 2) {
                uint32_t h0, l0u, h1, l1u;
                split2(acc[mt][nt][0]*scale, acc[mt][nt][1]*scale, h0, l0u);
                split2(acc[mt][nt][2]*scale, acc[mt][nt][3]*scale, h1, l1u);
                *(uint32_t*)(Ch + (size_t)r * N + c)     = h0;
                *(uint32_t*)(Cl + (size_t)r * N + c)     = l0u;
                *(uint32_t*)(Ch + (size_t)(r+8) * N + c) = h1;
                *(uint32_t*)(Cl + (size_t)(r+8) * N + c) = l1u;
            } else {
                float2 v0 = make_float2(acc[mt][nt][0], acc[mt][nt][1]);
                float2 v1 = make_float2(acc[mt][nt][2], acc[mt][nt][3]);
                if (OM == 1) {
                    const float2 r0 = *(const float2*)(R + (size_t)r * N + c);
                    const float2 r1 = *(const float2*)(R + (size_t)(r+8) * N + c);
                    v0.x += r0.x; v0.y += r0.y;
                    v1.x += r1.x; v1.y += r1.y;
                }
                *(float2*)(C + (size_t)r * N + c)     = v0;
                *(float2*)(C + (size_t)(r+8) * N + c) = v1;
            }
        }
    }
}

// ======================= tensor-core causal flash attention =================
// (verbatim champion)
#define RBQ 272
#define RBV 144
#define QT_BYTES (128*RBQ)
#define KT_BYTES (64*RBQ)
#define VT_BYTES (128*RBV)
#define STAGE_B  (2*KT_BYTES + 2*VT_BYTES)
#define ATTN_SMEM (2*QT_BYTES + 2*STAGE_B)

__global__ __launch_bounds__(256) void attn_mma_k(
    const __nv_bfloat16* __restrict__ qh, const __nv_bfloat16* __restrict__ ql,
    const __nv_bfloat16* __restrict__ kh, const __nv_bfloat16* __restrict__ kl,
    const __nv_bfloat16* __restrict__ vh, const __nv_bfloat16* __restrict__ vl,
    __nv_bfloat16* __restrict__ Oh, __nv_bfloat16* __restrict__ Ol)
{
    extern __shared__ char sm[];
    const uint32_t sb = smem_u32(sm);

    const int tid = threadIdx.x, lane = tid & 31, wid = tid >> 5;
    const int g = lane >> 2, tig = lane & 3;
    const int qt = 15 - blockIdx.x, h = blockIdx.y, b = blockIdx.z;
    const int ntiles = 2 * (qt + 1);

    {
        const size_t gq = ((size_t)(b*2048 + qt*128) * 2048 + h*128) * 2;
        #pragma unroll
        for (int i = 0; i < 16; i++) {
            const int c = tid + i*256;
            const int t = c >> 11;
            const int cc = c & 2047;
            const int row = cc >> 4, col = cc & 15;
            const char* gp = (const char*)(t ? ql : qh) + gq + (size_t)row*4096 + col*16;
            cp16(sb + (t ? QT_BYTES : 0) + row*RBQ + col*16, gp);
        }
        CP_COMMIT();
    }

    auto load_stage = [&](int kt) {
        const uint32_t base = sb + 2*QT_BYTES + (uint32_t)(kt & 1) * STAGE_B;
        const size_t gk = ((size_t)(b*2048 + kt*64) * 2048 + h*128) * 2;
        const size_t gv = (((size_t)((b*16 + h)*128)) * 2048 + kt*64) * 2;
        #pragma unroll
        for (int i = 0; i < 16; i++) {
            const int c = tid + i*256;
            const int sel = c >> 10;
            const int cc = c & 1023;
            if (sel < 2) {
                const int row = cc >> 4, col = cc & 15;
                const char* gp = (const char*)(sel ? kl : kh) + gk + (size_t)row*4096 + col*16;
                cp16(base + (sel ? KT_BYTES : 0) + row*RBQ + col*16, gp);
            } else {
                const int row = cc >> 3, col = cc & 7;
                const char* gp = (const char*)(sel == 3 ? vl : vh) + gv + (size_t)row*4096 + col*16;
                cp16(base + 2*KT_BYTES + (sel == 3 ? VT_BYTES : 0) + row*RBV + col*16, gp);
            }
        }
        CP_COMMIT();
    };

    load_stage(0);
    load_stage(1);

    float accO[16][4];
    #pragma unroll
    for (int nt = 0; nt < 16; nt++)
        #pragma unroll
        for (int e = 0; e < 4; e++) accO[nt][e] = 0.f;
    float m0 = -INFINITY, m1 = -INFINITY, l0 = 0.f, l1 = 0.f;

    const int row0 = wid * 16;
    const int qrow0 = qt*128 + row0 + g;

    for (int s = 0; s < ntiles; s++) {
        if (s + 1 < ntiles) { CP_WAIT(1); } else { CP_WAIT(0); }
        __syncthreads();
        const char* stg = sm + 2*QT_BYTES + (size_t)(s & 1) * STAGE_B;

        float accS[8][4];
        #pragma unroll
        for (int nt = 0; nt < 8; nt++)
            #pragma unroll
            for (int e = 0; e < 4; e++) accS[nt][e] = 0.f;

        #pragma unroll
        for (int ks = 0; ks < 8; ks++) {
            const int kb = ks*32 + tig*4;
            uint32_t ah[4], al[4], bh2[8][2], bl2[8][2];
            const char* ra = sm + (row0 + g)*RBQ + kb;
            ah[0] = *(const uint32_t*)(ra);
            ah[1] = *(const uint32_t*)(ra + 8*RBQ);
            ah[2] = *(const uint32_t*)(ra + 16);
            ah[3] = *(const uint32_t*)(ra + 8*RBQ + 16);
            al[0] = *(const uint32_t*)(ra + QT_BYTES);
            al[1] = *(const uint32_t*)(ra + QT_BYTES + 8*RBQ);
            al[2] = *(const uint32_t*)(ra + QT_BYTES + 16);
            al[3] = *(const uint32_t*)(ra + QT_BYTES + 8*RBQ + 16);
            #pragma unroll
            for (int nt = 0; nt < 8; nt++) {
                const char* rb = stg + (nt*8 + g)*RBQ + kb;
                bh2[nt][0] = *(const uint32_t*)(rb);
                bh2[nt][1] = *(const uint32_t*)(rb + 16);
                bl2[nt][0] = *(const uint32_t*)(rb + KT_BYTES);
                bl2[nt][1] = *(const uint32_t*)(rb + KT_BYTES + 16);
            }
            #pragma unroll
            for (int nt = 0; nt < 8; nt++) mma_bf16(accS[nt], ah, bh2[nt]);
            #pragma unroll
            for (int nt = 0; nt < 8; nt++) mma_bf16(accS[nt], ah, bl2[nt]);
            #pragma unroll
            for (int nt = 0; nt < 8; nt++) mma_bf16(accS[nt], al, bh2[nt]);
        }

        if (s >= ntiles - 2) {
            #pragma unroll
            for (int nt = 0; nt < 8; nt++) {
                const int col = s*64 + nt*8 + tig*2;
                if (col     > qrow0)     accS[nt][0] = -INFINITY;
                if (col + 1 > qrow0)     accS[nt][1] = -INFINITY;
                if (col     > qrow0 + 8) accS[nt][2] = -INFINITY;
                if (col + 1 > qrow0 + 8) accS[nt][3] = -INFINITY;
            }
        }

        float mt0 = -INFINITY, mt1 = -INFINITY;
        #pragma unroll
        for (int nt = 0; nt < 8; nt++) {
            mt0 = fmaxf(mt0, fmaxf(accS[nt][0], accS[nt][1]));
            mt1 = fmaxf(mt1, fmaxf(accS[nt][2], accS[nt][3]));
        }
        mt0 = fmaxf(mt0, __shfl_xor_sync(0xffffffffu, mt0, 1));
        mt0 = fmaxf(mt0, __shfl_xor_sync(0xffffffffu, mt0, 2));
        mt1 = fmaxf(mt1, __shfl_xor_sync(0xffffffffu, mt1, 1));
        mt1 = fmaxf(mt1, __shfl_xor_sync(0xffffffffu, mt1, 2));

        const float mn0 = fmaxf(m0, mt0), mn1 = fmaxf(m1, mt1);
        const float sc0 = __expf(m0 - mn0), sc1 = __expf(m1 - mn1);
        m0 = mn0; m1 = mn1;

        float rs0 = 0.f, rs1 = 0.f;
        #pragma unroll
        for (int nt = 0; nt < 8; nt++) {
            accS[nt][0] = __expf(accS[nt][0] - mn0);
            accS[nt][1] = __expf(accS[nt][1] - mn0);
            accS[nt][2] = __expf(accS[nt][2] - mn1);
            accS[nt][3] = __expf(accS[nt][3] - mn1);
            rs0 += accS[nt][0] + accS[nt][1];
            rs1 += accS[nt][2] + accS[nt][3];
        }
        rs0 += __shfl_xor_sync(0xffffffffu, rs0, 1);
        rs0 += __shfl_xor_sync(0xffffffffu, rs0, 2);
        rs1 += __shfl_xor_sync(0xffffffffu, rs1, 1);
        rs1 += __shfl_xor_sync(0xffffffffu, rs1, 2);
        l0 = l0*sc0 + rs0;
        l1 = l1*sc1 + rs1;

        #pragma unroll
        for (int nt = 0; nt < 16; nt++) {
            accO[nt][0] *= sc0; accO[nt][1] *= sc0;
            accO[nt][2] *= sc1; accO[nt][3] *= sc1;
        }

        #pragma unroll
        for (int kk = 0; kk < 4; kk++) {
            uint32_t ph[4], pl[4];
            split2(accS[2*kk][0],   accS[2*kk][1],   ph[0], pl[0]);
            split2(accS[2*kk][2],   accS[2*kk][3],   ph[1], pl[1]);
            split2(accS[2*kk+1][0], accS[2*kk+1][1], ph[2], pl[2]);
            split2(accS[2*kk+1][2], accS[2*kk+1][3], ph[3], pl[3]);
            const int kb = kk*32 + tig*4;
            #pragma unroll
            for (int nt = 0; nt < 16; nt++) {
                const char* rv = stg + 2*KT_BYTES + (nt*8 + g)*RBV + kb;
                uint32_t vbh[2], vbl[2];
                vbh[0] = *(const uint32_t*)(rv);
                vbh[1] = *(const uint32_t*)(rv + 16);
                vbl[0] = *(const uint32_t*)(rv + VT_BYTES);
                vbl[1] = *(const uint32_t*)(rv + VT_BYTES + 16);
                mma_bf16(accO[nt], ph, vbh);
                mma_bf16(accO[nt], ph, vbl);
                mma_bf16(accO[nt], pl, vbh);
            }
        }

        __syncthreads();
        if (s + 2 < ntiles) load_stage(s + 2);
    }

    const float inv0 = 1.f / l0, inv1 = 1.f / l1;
    const size_t ob = ((size_t)(b*2048 + qt*128 + row0 + g)) * 2048 + h*128;
    #pragma unroll
    for (int nt = 0; nt < 16; nt++) {
        const int c = nt*8 + tig*2;
        uint32_t h0, l0u, h1, l1u;
        split2(accO[nt][0]*inv0, accO[nt][1]*inv0, h0, l0u);
        split2(accO[nt][2]*inv1, accO[nt][3]*inv1, h1, l1u);
        *(uint32_t*)(Oh + ob + c)           = h0;
        *(uint32_t*)(Ol + ob + c)           = l0u;
        *(uint32_t*)(Oh + ob + 8*2048 + c)  = h1;
        *(uint32_t*)(Ol + ob + 8*2048 + c)  = l1u;
    }
}

// ======================= batched weight transpose + split ====================
struct TCJob  { const float* W; __nv_bfloat16* Th; __nv_bfloat16* Tl; int rowOff; };
struct TCJobs { TCJob j[4]; };

__global__ void transconv64_k(TCJobs jobs, int K, int N, int rowStride)
{
    const TCJob jb = jobs.j[blockIdx.z];
    __shared__ float t[64][65];
    const int n0 = blockIdx.x * 64, k0 = blockIdx.y * 64;
    const int tx = threadIdx.x, ty = threadIdx.y;   // (32, 8)
    #pragma unroll
    for (int r = ty; r < 64; r += 8) {
        const float2 v = *(const float2*)(jb.W + (size_t)(k0 + r) * N + n0 + 2*tx);
        t[r][2*tx]   = v.x;
        t[r][2*tx+1] = v.y;
    }
    __syncthreads();
    #pragma unroll
    for (int i = ty; i < 64; i += 8) {
        uint32_t hi, lo;
        split2(t[2*tx][i], t[2*tx+1][i], hi, lo);
        const size_t o = ((size_t)(n0 + i) * rowStride + jb.rowOff) * K + k0 + 2*tx;
        *(uint32_t*)(jb.Th + o) = hi;
        *(uint32_t*)(jb.Tl + o) = lo;
    }
}

// ======================= V transpose (64x64, u32 I/O) ========================
__global__ void vtrans64_k(const __nv_bfloat16* __restrict__ Vh,
                           const __nv_bfloat16* __restrict__ Vl,
                           __nv_bfloat16* __restrict__ Th, __nv_bfloat16* __restrict__ Tl)
{
    __shared__ __nv_bfloat16 th[64][66], tl[64][66];
    const int kv0 = blockIdx.x * 64, hd0 = blockIdx.y * 64, bh = blockIdx.z;
    const int b = bh >> 4, h = bh & 15;
    const int tx = threadIdx.x, ty = threadIdx.y;      // (32, 8)
    #pragma unroll
    for (int r = ty; r < 64; r += 8) {
        const size_t src = (size_t)(b*2048 + kv0 + r) * 2048 + h*128 + hd0 + 2*tx;
        *(uint32_t*)&th[r][2*tx] = *(const uint32_t*)(Vh + src);
        *(uint32_t*)&tl[r][2*tx] = *(const uint32_t*)(Vl + src);
    }
    __syncthreads();
    #pragma unroll
    for (int i = ty; i < 64; i += 8) {
        __nv_bfloat162 ph, pl;
        ph.x = th[2*tx][i]; ph.y = th[2*tx+1][i];
        pl.x = tl[2*tx][i]; pl.y = tl[2*tx+1][i];
        const size_t o = ((size_t)(bh*128 + hd0 + i)) * 2048 + kv0 + 2*tx;
        *(uint32_t*)(Th + o) = *(uint32_t*)&ph;
        *(uint32_t*)(Tl + o) = *(uint32_t*)&pl;
    }
}

// ======================= RMSNorm: warp-per-row, barrier-free ================
__global__ __launch_bounds__(256) void rmsnorm_warp_k(
    const float* __restrict__ x, const float* __restrict__ w,
    __nv_bfloat16* __restrict__ yh, __nv_bfloat16* __restrict__ yl)
{
    const int row  = blockIdx.x * 8 + (threadIdx.x >> 5);
    const int lane = threadIdx.x & 31;
    const float4* xr = (const float4*)(x + (size_t)row * HID);
    const float4* w4 = (const float4*)w;

    float ss = 0.f;
    #pragma unroll
    for (int i = 0; i < 16; i++) {
        const float4 v = xr[i*32 + lane];
        ss += v.x*v.x + v.y*v.y + v.z*v.z + v.w*v.w;
    }
    #pragma unroll
    for (int off = 16; off > 0; off >>= 1)
        ss += __shfl_xor_sync(0xffffffffu, ss, off);
    const float inv = rsqrtf(ss * (1.f / (float)HID) + 1e-6f);

    #pragma unroll
    for (int i = 0; i < 16; i++) {
        const float4 v = xr[i*32 + lane];
        const float4 ww = w4[i*32 + lane];
        const float o0 = v.x*inv*ww.x, o1 = v.y*inv*ww.y;
        const float o2 = v.z*inv*ww.z, o3 = v.w*inv*ww.w;
        uint32_t h0, l0, h1, l1;
        split2(o0, o1, h0, l0);
        split2(o2, o3, h1, l1);
        const size_t base = (size_t)row * HID + (size_t)(i*32 + lane) * 4;
        uint2 vh = make_uint2(h0, h1), vl = make_uint2(l0, l1);
        *(uint2*)(yh + base) = vh;
        *(uint2*)(yl + base) = vl;
    }
}

// ======================= launch =============================================
extern "C" void kernel_launch(void* const* d_in, const int* in_sizes, int n_in,
                              void* d_out, int out_size)
{
    const float* hidden = (const float*)d_in[0];
    const float* wq  = (const float*)d_in[1];
    const float* wk  = (const float*)d_in[2];
    const float* wv  = (const float*)d_in[3];
    const float* wo  = (const float*)d_in[4];
    const float* wg  = (const float*)d_in[5];
    const float* wu  = (const float*)d_in[6];
    const float* wd  = (const float*)d_in[7];
    const float* ln1 = (const float*)d_in[8];
    const float* ln2 = (const float*)d_in[9];

    __nv_bfloat16 *pwq_h,*pwq_l,*pwk_h,*pwk_l,*pwv_h,*pwv_l,*pwo_h,*pwo_l;
    __nv_bfloat16 *pwgu_h,*pwgu_l,*pwd_h,*pwd_l;
    __nv_bfloat16 *px_h,*px_l,*pat_h,*pat_l,*pm_h,*pm_l;
    __nv_bfloat16 *pq_h,*pq_l,*pk_h,*pk_l,*pv_h,*pv_l,*pvt_h,*pvt_l;
    float *h1;
    cudaGetSymbolAddress((void**)&pwq_h, w_q_hi); cudaGetSymbolAddress((void**)&pwq_l, w_q_lo);
    cudaGetSymbolAddress((void**)&pwk_h, w_k_hi); cudaGetSymbolAddress((void**)&pwk_l, w_k_lo);
    cudaGetSymbolAddress((void**)&pwv_h, w_v_hi); cudaGetSymbolAddress((void**)&pwv_l, w_v_lo);
    cudaGetSymbolAddress((void**)&pwo_h, w_o_hi); cudaGetSymbolAddress((void**)&pwo_l, w_o_lo);
    cudaGetSymbolAddress((void**)&pwgu_h, w_gu_hi); cudaGetSymbolAddress((void**)&pwgu_l, w_gu_lo);
    cudaGetSymbolAddress((void**)&pwd_h, w_d_hi); cudaGetSymbolAddress((void**)&pwd_l, w_d_lo);
    cudaGetSymbolAddress((void**)&px_h,  a_x_hi); cudaGetSymbolAddress((void**)&px_l,  a_x_lo);
    cudaGetSymbolAddress((void**)&pat_h, a_at_hi);cudaGetSymbolAddress((void**)&pat_l, a_at_lo);
    cudaGetSymbolAddress((void**)&pm_h,  a_m_hi); cudaGetSymbolAddress((void**)&pm_l,  a_m_lo);
    cudaGetSymbolAddress((void**)&pq_h,  q_bhi);  cudaGetSymbolAddress((void**)&pq_l,  q_blo);
    cudaGetSymbolAddress((void**)&pk_h,  k_bhi);  cudaGetSymbolAddress((void**)&pk_l,  k_blo);
    cudaGetSymbolAddress((void**)&pv_h,  v_bhi);  cudaGetSymbolAddress((void**)&pv_l,  v_blo);
    cudaGetSymbolAddress((void**)&pvt_h, vt_hi);  cudaGetSymbolAddress((void**)&pvt_l, vt_lo);
    cudaGetSymbolAddress((void**)&h1, s_h1);

    cudaFuncSetAttribute(gemm3bf<0>, cudaFuncAttributeMaxDynamicSharedMemorySize, GEMM_SMEM);
    cudaFuncSetAttribute(gemm3bf<1>, cudaFuncAttributeMaxDynamicSharedMemorySize, GEMM_SMEM);
    cudaFuncSetAttribute(gemm3bf<2>, cudaFuncAttributeMaxDynamicSharedMemorySize, GEMM_SMEM);
    cudaFuncSetAttribute(gemm3bf<3>, cudaFuncAttributeMaxDynamicSharedMemorySize, GEMM_SMEM);
    cudaFuncSetAttribute(attn_mma_k, cudaFuncAttributeMaxDynamicSharedMemorySize, ATTN_SMEM);

    // lazy-created streams/events (host objects; identical work every call)
    static cudaStream_t st1 = nullptr, st2 = nullptr;
    static cudaEvent_t evS, evW, evX, evQ, evK;
    if (st1 == nullptr) {
        cudaStreamCreateWithFlags(&st1, cudaStreamNonBlocking);
        cudaStreamCreateWithFlags(&st2, cudaStreamNonBlocking);
        cudaEventCreateWithFlags(&evS, cudaEventDisableTiming);
        cudaEventCreateWithFlags(&evW, cudaEventDisableTiming);
        cudaEventCreateWithFlags(&evX, cudaEventDisableTiming);
        cudaEventCreateWithFlags(&evQ, cudaEventDisableTiming);
        cudaEventCreateWithFlags(&evK, cudaEventDisableTiming);
    }

    dim3 tb(32, 8);
    const float sc = 0.08838834764831845f;
    dim3 gHH(HID/128, MTOK/256);   // (16, 16)

    // fork st1/st2 from the capture (legacy) stream
    cudaEventRecord(evS, 0);
    cudaStreamWaitEvent(st1, evS, 0);
    cudaStreamWaitEvent(st2, evS, 0);

    // --- legacy stream: weight transpose+split (3 launches)
    {
        TCJobs jqkvo;
        jqkvo.j[0] = { wq, pwq_h, pwq_l, 0 };
        jqkvo.j[1] = { wk, pwk_h, pwk_l, 0 };
        jqkvo.j[2] = { wv, pwv_h, pwv_l, 0 };
        jqkvo.j[3] = { wo, pwo_h, pwo_l, 0 };
        transconv64_k<<<dim3(HID/64, HID/64, 4), tb>>>(jqkvo, HID, HID, 1);

        TCJobs jgu;
        jgu.j[0] = { wg, pwgu_h, pwgu_l, 0 };
        jgu.j[1] = { wu, pwgu_h, pwgu_l, 1 };
        jgu.j[2] = jgu.j[0];
        jgu.j[3] = jgu.j[0];
        transconv64_k<<<dim3(INTER/64, HID/64, 2), tb>>>(jgu, HID, INTER, 2);

        TCJobs jd;
        jd.j[0] = { wd, pwd_h, pwd_l, 0 };
        jd.j[1] = jd.j[0]; jd.j[2] = jd.j[0]; jd.j[3] = jd.j[0];
        transconv64_k<<<dim3(HID/64, INTER/64, 1), tb>>>(jd, INTER, HID, 1);
    }
    cudaEventRecord(evW, 0);   // weights ready

    // --- st1: rmsnorm1 (overlaps transconv), then Q GEMM
    rmsnorm_warp_k<<<MTOK/8, 256, 0, st1>>>(hidden, ln1, px_h, px_l);
    cudaEventRecord(evX, st1); // x ready
    cudaStreamWaitEvent(st1, evW, 0);
    gemm3bf<2><<<gHH, 256, GEMM_SMEM, st1>>>(px_h, px_l, pwq_h, pwq_l, nullptr, nullptr,
                                             pq_h, pq_l, sc, MTOK, HID, HID);
    cudaEventRecord(evQ, st1);

    // --- st2: K GEMM (needs weights + x)
    cudaStreamWaitEvent(st2, evW, 0);
    cudaStreamWaitEvent(st2, evX, 0);
    gemm3bf<2><<<gHH, 256, GEMM_SMEM, st2>>>(px_h, px_l, pwk_h, pwk_l, nullptr, nullptr,
                                             pk_h, pk_l, 1.f, MTOK, HID, HID);
    cudaEventRecord(evK, st2);

    // --- legacy: V GEMM (weights already ordered on 0; needs x), vtrans
    cudaStreamWaitEvent(0, evX, 0);
    gemm3bf<2><<<gHH, 256, GEMM_SMEM>>>(px_h, px_l, pwv_h, pwv_l, nullptr, nullptr,
                                        pv_h, pv_l, 1.f, MTOK, HID, HID);
    vtrans64_k<<<dim3(32, 2, 32), tb>>>(pv_h, pv_l, pvt_h, pvt_l);

    // join Q and K back into legacy before attention
    cudaStreamWaitEvent(0, evQ, 0);
    cudaStreamWaitEvent(0, evK, 0);

    // 3) tensor-core attention -> bf16 hi/lo
    attn_mma_k<<<dim3(16, 16, 2), 256, ATTN_SMEM>>>(pq_h, pq_l, pk_h, pk_l,
                                                    pvt_h, pvt_l, pat_h, pat_l);

    // 4) O-proj + residual
    gemm3bf<1><<<gHH, 256, GEMM_SMEM>>>(pat_h, pat_l, pwo_h, pwo_l, hidden, h1,
                                        nullptr, nullptr, 1.f, MTOK, HID, HID);

    // 5) rmsnorm2 -> bf16 hi/lo
    rmsnorm_warp_k<<<MTOK/8, 256>>>(h1, ln2, px_h, px_l);

    // 6) fused gate+up GEMM with silu-mul epilogue -> m (bf16 hi/lo)
    gemm3bf<3><<<dim3(2*INTER/128, MTOK/256), 256, GEMM_SMEM>>>(
        px_h, px_l, pwgu_h, pwgu_l, nullptr, nullptr,
        pm_h, pm_l, 1.f, MTOK, 2*INTER, HID);

    // 7) down-proj + residual -> d_out
    gemm3bf<1><<<gHH, 256, GEMM_SMEM>>>(pm_h, pm_l, pwd_h, pwd_l, h1, (float*)d_out,
                                        nullptr, nullptr, 1.f, MTOK, HID, INTER);
}

// round 14
// speedup vs baseline: 1.0405x; 1.0247x over previous
#include <cuda_runtime.h>
#include <cuda_bf16.h>
#include <math.h>
#include <stdint.h>

#define MTOK 4096      // B*S
#define HID  2048
#define INTER 8192

// ======================= device scratch (no allocations) ====================
__device__ __nv_bfloat16 w_q_hi[HID*HID],  w_q_lo[HID*HID];
__device__ __nv_bfloat16 w_k_hi[HID*HID],  w_k_lo[HID*HID];
__device__ __nv_bfloat16 w_v_hi[HID*HID],  w_v_lo[HID*HID];
__device__ __nv_bfloat16 w_o_hi[HID*HID],  w_o_lo[HID*HID];
__device__ __nv_bfloat16 w_gu_hi[(size_t)2*INTER*HID], w_gu_lo[(size_t)2*INTER*HID]; // interleaved
__device__ __nv_bfloat16 w_d_hi[(size_t)HID*INTER], w_d_lo[(size_t)HID*INTER];
__device__ __nv_bfloat16 a_x_hi[MTOK*HID],  a_x_lo[MTOK*HID];
__device__ __nv_bfloat16 a_at_hi[MTOK*HID], a_at_lo[MTOK*HID];
__device__ __nv_bfloat16 a_m_hi[(size_t)MTOK*INTER], a_m_lo[(size_t)MTOK*INTER];
__device__ __nv_bfloat16 q_bhi[MTOK*HID], q_blo[MTOK*HID];
__device__ __nv_bfloat16 k_bhi[MTOK*HID], k_blo[MTOK*HID];
__device__ __nv_bfloat16 v_bhi[MTOK*HID], v_blo[MTOK*HID];
__device__ __nv_bfloat16 vt_hi[MTOK*HID], vt_lo[MTOK*HID];   // [b*16+h][hd][kv]
__device__ float s_h1[MTOK*HID];

// ======================= helpers ============================================
__device__ __forceinline__ uint32_t smem_u32(const void* p) {
    uint32_t a;
    asm("{ .reg .u64 t; cvta.to.shared.u64 t, %1; cvt.u32.u64 %0, t; }" : "=r"(a) : "l"(p));
    return a;
}
__device__ __forceinline__ void cp16(uint32_t s, const void* g) {
    asm volatile("cp.async.cg.shared.global [%0], [%1], 16;" :: "r"(s), "l"(g));
}
#define CP_COMMIT() asm volatile("cp.async.commit_group;")
#define CP_WAIT(N)  asm volatile("cp.async.wait_group %0;" :: "n"(N))

__device__ __forceinline__ void mma_bf16(float* c, const uint32_t* a, const uint32_t* b) {
    asm volatile(
        "mma.sync.aligned.m16n8k16.row.col.f32.bf16.bf16.f32 "
        "{%0,%1,%2,%3}, {%4,%5,%6,%7}, {%8,%9}, {%0,%1,%2,%3};"
        : "+f"(c[0]), "+f"(c[1]), "+f"(c[2]), "+f"(c[3])
        : "r"(a[0]), "r"(a[1]), "r"(a[2]), "r"(a[3]), "r"(b[0]), "r"(b[1]));
}
__device__ __forceinline__ void split2(float x, float y, uint32_t& hi, uint32_t& lo) {
    __nv_bfloat162 h;
    h.x = __float2bfloat16(x); h.y = __float2bfloat16(y);
    __nv_bfloat162 l;
    l.x = __float2bfloat16(x - __bfloat162float(h.x));
    l.y = __float2bfloat16(y - __bfloat162float(h.y));
    hi = *reinterpret_cast<uint32_t*>(&h);
    lo = *reinterpret_cast<uint32_t*>(&l);
}

// ======================= bf16x3 mma.sync GEMM (champion core) ===============
// OM: 0 = fp32 out, 1 = fp32 out + residual, 2 = bf16 hi/lo out (scaled),
//     3 = fused silu(even)*odd -> bf16 hi/lo out at column c/2 (Nout = N/2)
#define RB    144
#define ATILE (256*RB)
#define BTILE (128*RB)
#define STG   (2*ATILE + 2*BTILE)  // 110592
#define GEMM_SMEM (2*STG)          // 221184

template<int OM>
__global__ __launch_bounds__(256) void gemm3bf(
    const __nv_bfloat16* __restrict__ Ahi, const __nv_bfloat16* __restrict__ Alo,
    const __nv_bfloat16* __restrict__ Bhi, const __nv_bfloat16* __restrict__ Blo,
    const float* __restrict__ R, float* __restrict__ C,
    __nv_bfloat16* __restrict__ Ch, __nv_bfloat16* __restrict__ Cl,
    float scale, int M, int N, int K)
{
    extern __shared__ char sm[];
    const uint32_t sbase = smem_u32(sm);

    const int tid = threadIdx.x;
    const int lane = tid & 31;
    const int wid = tid >> 5;
    const int g = lane >> 2, tig = lane & 3;
    const int warp_m = wid & 3;
    const int warp_n = wid >> 2;
    const int bm = blockIdx.y * 256;
    const int bn = blockIdx.x * 128;

    const int crow = tid >> 3;
    const int ccolB = (tid & 7) * 16;

    const int S = K >> 6;

    auto load_stage = [&](int s) {
        const uint32_t b = sbase + (uint32_t)(s & 1) * STG;
        const int k0 = s << 6;
        const size_t ga = ((size_t)(bm + crow) * K + k0) * 2 + ccolB;
        const size_t gb = ((size_t)(bn + crow) * K + k0) * 2 + ccolB;
        const size_t rstep = (size_t)32 * K * 2;
        const char* pah = (const char*)Ahi + ga;
        const char* pal = (const char*)Alo + ga;
        const char* pbh = (const char*)Bhi + gb;
        const char* pbl = (const char*)Blo + gb;
        #pragma unroll
        for (int i = 0; i < 8; i++) {
            const uint32_t so = (uint32_t)((crow + 32*i) * RB + ccolB);
            cp16(b + so,         pah); pah += rstep;
            cp16(b + ATILE + so, pal); pal += rstep;
        }
        #pragma unroll
        for (int i = 0; i < 4; i++) {
            const uint32_t so = (uint32_t)((crow + 32*i) * RB + ccolB);
            cp16(b + 2*ATILE + so,         pbh); pbh += rstep;
            cp16(b + 2*ATILE + BTILE + so, pbl); pbl += rstep;
        }
        CP_COMMIT();
    };

    load_stage(0);
    if (S > 1) load_stage(1);

    float acc[4][8][4];
    #pragma unroll
    for (int mt = 0; mt < 4; mt++)
        #pragma unroll
        for (int nt = 0; nt < 8; nt++)
            #pragma unroll
            for (int e = 0; e < 4; e++) acc[mt][nt][e] = 0.f;

    const int arow0 = warp_m * 64 + g;
    const int brow0 = warp_n * 64 + g;

    for (int s = 0; s < S; ++s) {
        if (s + 1 < S) { CP_WAIT(1); } else { CP_WAIT(0); }
        __syncthreads();
        const char* b = sm + (size_t)(s & 1) * STG;

        #pragma unroll
        for (int ks = 0; ks < 4; ++ks) {
            const int kb = ks * 32 + tig * 4;

            uint32_t bhf[8][2], blf[8][2];
            #pragma unroll
            for (int nt = 0; nt < 8; nt++) {
                const char* rb = b + 2*ATILE + (brow0 + nt*8) * RB + kb;
                bhf[nt][0] = *(const uint32_t*)(rb);
                bhf[nt][1] = *(const uint32_t*)(rb + 16);
                blf[nt][0] = *(const uint32_t*)(rb + BTILE);
                blf[nt][1] = *(const uint32_t*)(rb + BTILE + 16);
            }

            #pragma unroll
            for (int mt = 0; mt < 4; mt++) {
                uint32_t ah[4], al[4];
                const char* ra = b + (arow0 + mt*16) * RB + kb;
                ah[0] = *(const uint32_t*)(ra);
                ah[1] = *(const uint32_t*)(ra + 8*RB);
                ah[2] = *(const uint32_t*)(ra + 16);
                ah[3] = *(const uint32_t*)(ra + 8*RB + 16);
                al[0] = *(const uint32_t*)(ra + ATILE);
                al[1] = *(const uint32_t*)(ra + ATILE + 8*RB);
                al[2] = *(const uint32_t*)(ra + ATILE + 16);
                al[3] = *(const uint32_t*)(ra + ATILE + 8*RB + 16);

                #pragma unroll
                for (int nt = 0; nt < 8; nt++)
                    mma_bf16(acc[mt][nt], ah, bhf[nt]);
                #pragma unroll
                for (int nt = 0; nt < 8; nt++)
                    mma_bf16(acc[mt][nt], ah, blf[nt]);
                #pragma unroll
                for (int nt = 0; nt < 8; nt++)
                    mma_bf16(acc[mt][nt], al, bhf[nt]);
            }
        }
        __syncthreads();
        if (s + 2 < S) load_stage(s + 2);
    }

    const int row0 = bm + warp_m*64 + g;
    const int col0 = bn + warp_n*64 + tig*2;
    #pragma unroll
    for (int mt = 0; mt < 4; mt++) {
        #pragma unroll
        for (int nt = 0; nt < 8; nt++) {
            const int r = row0 + mt*16;
            const int c = col0 + nt*8;
            if (OM == 3) {
                const int Nout = N >> 1;
                const int cc = c >> 1;
                const float g0 = acc[mt][nt][0], u0 = acc[mt][nt][1];
                const float g1 = acc[mt][nt][2], u1 = acc[mt][nt][3];
                const float r0 = g0 / (1.f + __expf(-g0)) * u0;
                const float r1 = g1 / (1.f + __expf(-g1)) * u1;
                const __nv_bfloat16 h0 = __float2bfloat16(r0);
                const __nv_bfloat16 h1 = __float2bfloat16(r1);
                Ch[(size_t)r * Nout + cc]     = h0;
                Cl[(size_t)r * Nout + cc]     = __float2bfloat16(r0 - __bfloat162float(h0));
                Ch[(size_t)(r+8) * Nout + cc] = h1;
                Cl[(size_t)(r+8) * Nout + cc] = __float2bfloat16(r1 - __bfloat162float(h1));
            } else if (OM == 2) {
                uint32_t h0, l0u, h1, l1u;
                split2(acc[mt][nt][0]*scale, acc[mt][nt][1]*scale, h0, l0u);
                split2(acc[mt][nt][2]*scale, acc[mt][nt][3]*scale, h1, l1u);
                *(uint32_t*)(Ch + (size_t)r * N + c)     = h0;
                *(uint32_t*)(Cl + (size_t)r * N + c)     = l0u;
                *(uint32_t*)(Ch + (size_t)(r+8) * N + c) = h1;
                *(uint32_t*)(Cl + (size_t)(r+8) * N + c) = l1u;
            } else {
                float2 v0 = make_float2(acc[mt][nt][0], acc[mt][nt][1]);
                float2 v1 = make_float2(acc[mt][nt][2], acc[mt][nt][3]);
                if (OM == 1) {
                    const float2 r0 = *(const float2*)(R + (size_t)r * N + c);
                    const float2 r1 = *(const float2*)(R + (size_t)(r+8) * N + c);
                    v0.x += r0.x; v0.y += r0.y;
                    v1.x += r1.x; v1.y += r1.y;
                }
                *(float2*)(C + (size_t)r * N + c)     = v0;
                *(float2*)(C + (size_t)(r+8) * N + c) = v1;
            }
        }
    }
}

// ======================= tensor-core causal flash attention =================
// (verbatim champion)
#define RBQ 272
#define RBV 144
#define QT_BYTES (128*RBQ)
#define KT_BYTES (64*RBQ)
#define VT_BYTES (128*RBV)
#define STAGE_B  (2*KT_BYTES + 2*VT_BYTES)
#define ATTN_SMEM (2*QT_BYTES + 2*STAGE_B)

__global__ __launch_bounds__(256) void attn_mma_k(
    const __nv_bfloat16* __restrict__ qh, const __nv_bfloat16* __restrict__ ql,
    const __nv_bfloat16* __restrict__ kh, const __nv_bfloat16* __restrict__ kl,
    const __nv_bfloat16* __restrict__ vh, const __nv_bfloat16* __restrict__ vl,
    __nv_bfloat16* __restrict__ Oh, __nv_bfloat16* __restrict__ Ol)
{
    extern __shared__ char sm[];
    const uint32_t sb = smem_u32(sm);

    const int tid = threadIdx.x, lane = tid & 31, wid = tid >> 5;
    const int g = lane >> 2, tig = lane & 3;
    const int qt = 15 - blockIdx.x, h = blockIdx.y, b = blockIdx.z;
    const int ntiles = 2 * (qt + 1);

    {
        const size_t gq = ((size_t)(b*2048 + qt*128) * 2048 + h*128) * 2;
        #pragma unroll
        for (int i = 0; i < 16; i++) {
            const int c = tid + i*256;
            const int t = c >> 11;
            const int cc = c & 2047;
            const int row = cc >> 4, col = cc & 15;
            const char* gp = (const char*)(t ? ql : qh) + gq + (size_t)row*4096 + col*16;
            cp16(sb + (t ? QT_BYTES : 0) + row*RBQ + col*16, gp);
        }
        CP_COMMIT();
    }

    auto load_stage = [&](int kt) {
        const uint32_t base = sb + 2*QT_BYTES + (uint32_t)(kt & 1) * STAGE_B;
        const size_t gk = ((size_t)(b*2048 + kt*64) * 2048 + h*128) * 2;
        const size_t gv = (((size_t)((b*16 + h)*128)) * 2048 + kt*64) * 2;
        #pragma unroll
        for (int i = 0; i < 16; i++) {
            const int c = tid + i*256;
            const int sel = c >> 10;
            const int cc = c & 1023;
            if (sel < 2) {
                const int row = cc >> 4, col = cc & 15;
                const char* gp = (const char*)(sel ? kl : kh) + gk + (size_t)row*4096 + col*16;
                cp16(base + (sel ? KT_BYTES : 0) + row*RBQ + col*16, gp);
            } else {
                const int row = cc >> 3, col = cc & 7;
                const char* gp = (const char*)(sel == 3 ? vl : vh) + gv + (size_t)row*4096 + col*16;
                cp16(base + 2*KT_BYTES + (sel == 3 ? VT_BYTES : 0) + row*RBV + col*16, gp);
            }
        }
        CP_COMMIT();
    };

    load_stage(0);
    load_stage(1);

    float accO[16][4];
    #pragma unroll
    for (int nt = 0; nt < 16; nt++)
        #pragma unroll
        for (int e = 0; e < 4; e++) accO[nt][e] = 0.f;
    float m0 = -INFINITY, m1 = -INFINITY, l0 = 0.f, l1 = 0.f;

    const int row0 = wid * 16;
    const int qrow0 = qt*128 + row0 + g;

    for (int s = 0; s < ntiles; s++) {
        if (s + 1 < ntiles) { CP_WAIT(1); } else { CP_WAIT(0); }
        __syncthreads();
        const char* stg = sm + 2*QT_BYTES + (size_t)(s & 1) * STAGE_B;

        float accS[8][4];
        #pragma unroll
        for (int nt = 0; nt < 8; nt++)
            #pragma unroll
            for (int e = 0; e < 4; e++) accS[nt][e] = 0.f;

        #pragma unroll
        for (int ks = 0; ks < 8; ks++) {
            const int kb = ks*32 + tig*4;
            uint32_t ah[4], al[4], bh2[8][2], bl2[8][2];
            const char* ra = sm + (row0 + g)*RBQ + kb;
            ah[0] = *(const uint32_t*)(ra);
            ah[1] = *(const uint32_t*)(ra + 8*RBQ);
            ah[2] = *(const uint32_t*)(ra + 16);
            ah[3] = *(const uint32_t*)(ra + 8*RBQ + 16);
            al[0] = *(const uint32_t*)(ra + QT_BYTES);
            al[1] = *(const uint32_t*)(ra + QT_BYTES + 8*RBQ);
            al[2] = *(const uint32_t*)(ra + QT_BYTES + 16);
            al[3] = *(const uint32_t*)(ra + QT_BYTES + 8*RBQ + 16);
            #pragma unroll
            for (int nt = 0; nt < 8; nt++) {
                const char* rb = stg + (nt*8 + g)*RBQ + kb;
                bh2[nt][0] = *(const uint32_t*)(rb);
                bh2[nt][1] = *(const uint32_t*)(rb + 16);
                bl2[nt][0] = *(const uint32_t*)(rb + KT_BYTES);
                bl2[nt][1] = *(const uint32_t*)(rb + KT_BYTES + 16);
            }
            #pragma unroll
            for (int nt = 0; nt < 8; nt++) mma_bf16(accS[nt], ah, bh2[nt]);
            #pragma unroll
            for (int nt = 0; nt < 8; nt++) mma_bf16(accS[nt], ah, bl2[nt]);
            #pragma unroll
            for (int nt = 0; nt < 8; nt++) mma_bf16(accS[nt], al, bh2[nt]);
        }

        if (s >= ntiles - 2) {
            #pragma unroll
            for (int nt = 0; nt < 8; nt++) {
                const int col = s*64 + nt*8 + tig*2;
                if (col     > qrow0)     accS[nt][0] = -INFINITY;
                if (col + 1 > qrow0)     accS[nt][1] = -INFINITY;
                if (col     > qrow0 + 8) accS[nt][2] = -INFINITY;
                if (col + 1 > qrow0 + 8) accS[nt][3] = -INFINITY;
            }
        }

        float mt0 = -INFINITY, mt1 = -INFINITY;
        #pragma unroll
        for (int nt = 0; nt < 8; nt++) {
            mt0 = fmaxf(mt0, fmaxf(accS[nt][0], accS[nt][1]));
            mt1 = fmaxf(mt1, fmaxf(accS[nt][2], accS[nt][3]));
        }
        mt0 = fmaxf(mt0, __shfl_xor_sync(0xffffffffu, mt0, 1));
        mt0 = fmaxf(mt0, __shfl_xor_sync(0xffffffffu, mt0, 2));
        mt1 = fmaxf(mt1, __shfl_xor_sync(0xffffffffu, mt1, 1));
        mt1 = fmaxf(mt1, __shfl_xor_sync(0xffffffffu, mt1, 2));

        const float mn0 = fmaxf(m0, mt0), mn1 = fmaxf(m1, mt1);
        const float sc0 = __expf(m0 - mn0), sc1 = __expf(m1 - mn1);
        m0 = mn0; m1 = mn1;

        float rs0 = 0.f, rs1 = 0.f;
        #pragma unroll
        for (int nt = 0; nt < 8; nt++) {
            accS[nt][0] = __expf(accS[nt][0] - mn0);
            accS[nt][1] = __expf(accS[nt][1] - mn0);
            accS[nt][2] = __expf(accS[nt][2] - mn1);
            accS[nt][3] = __expf(accS[nt][3] - mn1);
            rs0 += accS[nt][0] + accS[nt][1];
            rs1 += accS[nt][2] + accS[nt][3];
        }
        rs0 += __shfl_xor_sync(0xffffffffu, rs0, 1);
        rs0 += __shfl_xor_sync(0xffffffffu, rs0, 2);
        rs1 += __shfl_xor_sync(0xffffffffu, rs1, 1);
        rs1 += __shfl_xor_sync(0xffffffffu, rs1, 2);
        l0 = l0*sc0 + rs0;
        l1 = l1*sc1 + rs1;

        #pragma unroll
        for (int nt = 0; nt < 16; nt++) {
            accO[nt][0] *= sc0; accO[nt][1] *= sc0;
            accO[nt][2] *= sc1; accO[nt][3] *= sc1;
        }

        #pragma unroll
        for (int kk = 0; kk < 4; kk++) {
            uint32_t ph[4], pl[4];
            split2(accS[2*kk][0],   accS[2*kk][1],   ph[0], pl[0]);
            split2(accS[2*kk][2],   accS[2*kk][3],   ph[1], pl[1]);
            split2(accS[2*kk+1][0], accS[2*kk+1][1], ph[2], pl[2]);
            split2(accS[2*kk+1][2], accS[2*kk+1][3], ph[3], pl[3]);
            const int kb = kk*32 + tig*4;
            #pragma unroll
            for (int nt = 0; nt < 16; nt++) {
                const char* rv = stg + 2*KT_BYTES + (nt*8 + g)*RBV + kb;
                uint32_t vbh[2], vbl[2];
                vbh[0] = *(const uint32_t*)(rv);
                vbh[1] = *(const uint32_t*)(rv + 16);
                vbl[0] = *(const uint32_t*)(rv + VT_BYTES);
                vbl[1] = *(const uint32_t*)(rv + VT_BYTES + 16);
                mma_bf16(accO[nt], ph, vbh);
                mma_bf16(accO[nt], ph, vbl);
                mma_bf16(accO[nt], pl, vbh);
            }
        }

        __syncthreads();
        if (s + 2 < ntiles) load_stage(s + 2);
    }

    const float inv0 = 1.f / l0, inv1 = 1.f / l1;
    const size_t ob = ((size_t)(b*2048 + qt*128 + row0 + g)) * 2048 + h*128;
    #pragma unroll
    for (int nt = 0; nt < 16; nt++) {
        const int c = nt*8 + tig*2;
        uint32_t h0, l0u, h1, l1u;
        split2(accO[nt][0]*inv0, accO[nt][1]*inv0, h0, l0u);
        split2(accO[nt][2]*inv1, accO[nt][3]*inv1, h1, l1u);
        *(uint32_t*)(Oh + ob + c)           = h0;
        *(uint32_t*)(Ol + ob + c)           = l0u;
        *(uint32_t*)(Oh + ob + 8*2048 + c)  = h1;
        *(uint32_t*)(Ol + ob + 8*2048 + c)  = l1u;
    }
}

// ======================= batched weight transpose + split ====================
struct TCJob  { const float* W; __nv_bfloat16* Th; __nv_bfloat16* Tl; int rowOff; };
struct TCJobs { TCJob j[4]; };

__global__ void transconv64_k(TCJobs jobs, int K, int N, int rowStride)
{
    const TCJob jb = jobs.j[blockIdx.z];
    __shared__ float t[64][65];
    const int n0 = blockIdx.x * 64, k0 = blockIdx.y * 64;
    const int tx = threadIdx.x, ty = threadIdx.y;   // (32, 8)
    #pragma unroll
    for (int r = ty; r < 64; r += 8) {
        const float2 v = *(const float2*)(jb.W + (size_t)(k0 + r) * N + n0 + 2*tx);
        t[r][2*tx]   = v.x;
        t[r][2*tx+1] = v.y;
    }
    __syncthreads();
    #pragma unroll
    for (int i = ty; i < 64; i += 8) {
        uint32_t hi, lo;
        split2(t[2*tx][i], t[2*tx+1][i], hi, lo);
        const size_t o = ((size_t)(n0 + i) * rowStride + jb.rowOff) * K + k0 + 2*tx;
        *(uint32_t*)(jb.Th + o) = hi;
        *(uint32_t*)(jb.Tl + o) = lo;
    }
}

// ======================= V transpose (64x64, u32 I/O) ========================
__global__ void vtrans64_k(const __nv_bfloat16* __restrict__ Vh,
                           const __nv_bfloat16* __restrict__ Vl,
                           __nv_bfloat16* __restrict__ Th, __nv_bfloat16* __restrict__ Tl)
{
    __shared__ __nv_bfloat16 th[64][66], tl[64][66];
    const int kv0 = blockIdx.x * 64, hd0 = blockIdx.y * 64, bh = blockIdx.z;
    const int b = bh >> 4, h = bh & 15;
    const int tx = threadIdx.x, ty = threadIdx.y;      // (32, 8)
    #pragma unroll
    for (int r = ty; r < 64; r += 8) {
        const size_t src = (size_t)(b*2048 + kv0 + r) * 2048 + h*128 + hd0 + 2*tx;
        *(uint32_t*)&th[r][2*tx] = *(const uint32_t*)(Vh + src);
        *(uint32_t*)&tl[r][2*tx] = *(const uint32_t*)(Vl + src);
    }
    __syncthreads();
    #pragma unroll
    for (int i = ty; i < 64; i += 8) {
        __nv_bfloat162 ph, pl;
        ph.x = th[2*tx][i]; ph.y = th[2*tx+1][i];
        pl.x = tl[2*tx][i]; pl.y = tl[2*tx+1][i];
        const size_t o = ((size_t)(bh*128 + hd0 + i)) * 2048 + kv0 + 2*tx;
        *(uint32_t*)(Th + o) = *(uint32_t*)&ph;
        *(uint32_t*)(Tl + o) = *(uint32_t*)&pl;
    }
}

// ======================= RMSNorm: warp-per-row, barrier-free ================
__global__ __launch_bounds__(256) void rmsnorm_warp_k(
    const float* __restrict__ x, const float* __restrict__ w,
    __nv_bfloat16* __restrict__ yh, __nv_bfloat16* __restrict__ yl)
{
    const int row  = blockIdx.x * 8 + (threadIdx.x >> 5);
    const int lane = threadIdx.x & 31;
    const float4* xr = (const float4*)(x + (size_t)row * HID);
    const float4* w4 = (const float4*)w;

    float ss = 0.f;
    #pragma unroll
    for (int i = 0; i < 16; i++) {
        const float4 v = xr[i*32 + lane];
        ss += v.x*v.x + v.y*v.y + v.z*v.z + v.w*v.w;
    }
    #pragma unroll
    for (int off = 16; off > 0; off >>= 1)
        ss += __shfl_xor_sync(0xffffffffu, ss, off);
    const float inv = rsqrtf(ss * (1.f / (float)HID) + 1e-6f);

    #pragma unroll
    for (int i = 0; i < 16; i++) {
        const float4 v = xr[i*32 + lane];
        const float4 ww = w4[i*32 + lane];
        const float o0 = v.x*inv*ww.x, o1 = v.y*inv*ww.y;
        const float o2 = v.z*inv*ww.z, o3 = v.w*inv*ww.w;
        uint32_t h0, l0, h1, l1;
        split2(o0, o1, h0, l0);
        split2(o2, o3, h1, l1);
        const size_t base = (size_t)row * HID + (size_t)(i*32 + lane) * 4;
        uint2 vh = make_uint2(h0, h1), vl = make_uint2(l0, l1);
        *(uint2*)(yh + base) = vh;
        *(uint2*)(yl + base) = vl;
    }
}

// ======================= launch =============================================
extern "C" void kernel_launch(void* const* d_in, const int* in_sizes, int n_in,
                              void* d_out, int out_size)
{
    const float* hidden = (const float*)d_in[0];
    const float* wq  = (const float*)d_in[1];
    const float* wk  = (const float*)d_in[2];
    const float* wv  = (const float*)d_in[3];
    const float* wo  = (const float*)d_in[4];
    const float* wg  = (const float*)d_in[5];
    const float* wu  = (const float*)d_in[6];
    const float* wd  = (const float*)d_in[7];
    const float* ln1 = (const float*)d_in[8];
    const float* ln2 = (const float*)d_in[9];

    __nv_bfloat16 *pwq_h,*pwq_l,*pwk_h,*pwk_l,*pwv_h,*pwv_l,*pwo_h,*pwo_l;
    __nv_bfloat16 *pwgu_h,*pwgu_l,*pwd_h,*pwd_l;
    __nv_bfloat16 *px_h,*px_l,*pat_h,*pat_l,*pm_h,*pm_l;
    __nv_bfloat16 *pq_h,*pq_l,*pk_h,*pk_l,*pv_h,*pv_l,*pvt_h,*pvt_l;
    float *h1;
    cudaGetSymbolAddress((void**)&pwq_h, w_q_hi); cudaGetSymbolAddress((void**)&pwq_l, w_q_lo);
    cudaGetSymbolAddress((void**)&pwk_h, w_k_hi); cudaGetSymbolAddress((void**)&pwk_l, w_k_lo);
    cudaGetSymbolAddress((void**)&pwv_h, w_v_hi); cudaGetSymbolAddress((void**)&pwv_l, w_v_lo);
    cudaGetSymbolAddress((void**)&pwo_h, w_o_hi); cudaGetSymbolAddress((void**)&pwo_l, w_o_lo);
    cudaGetSymbolAddress((void**)&pwgu_h, w_gu_hi); cudaGetSymbolAddress((void**)&pwgu_l, w_gu_lo);
    cudaGetSymbolAddress((void**)&pwd_h, w_d_hi); cudaGetSymbolAddress((void**)&pwd_l, w_d_lo);
    cudaGetSymbolAddress((void**)&px_h,  a_x_hi); cudaGetSymbolAddress((void**)&px_l,  a_x_lo);
    cudaGetSymbolAddress((void**)&pat_h, a_at_hi);cudaGetSymbolAddress((void**)&pat_l, a_at_lo);
    cudaGetSymbolAddress((void**)&pm_h,  a_m_hi); cudaGetSymbolAddress((void**)&pm_l,  a_m_lo);
    cudaGetSymbolAddress((void**)&pq_h,  q_bhi);  cudaGetSymbolAddress((void**)&pq_l,  q_blo);
    cudaGetSymbolAddress((void**)&pk_h,  k_bhi);  cudaGetSymbolAddress((void**)&pk_l,  k_blo);
    cudaGetSymbolAddress((void**)&pv_h,  v_bhi);  cudaGetSymbolAddress((void**)&pv_l,  v_blo);
    cudaGetSymbolAddress((void**)&pvt_h, vt_hi);  cudaGetSymbolAddress((void**)&pvt_l, vt_lo);
    cudaGetSymbolAddress((void**)&h1, s_h1);

    cudaFuncSetAttribute(gemm3bf<0>, cudaFuncAttributeMaxDynamicSharedMemorySize, GEMM_SMEM);
    cudaFuncSetAttribute(gemm3bf<1>, cudaFuncAttributeMaxDynamicSharedMemorySize, GEMM_SMEM);
    cudaFuncSetAttribute(gemm3bf<2>, cudaFuncAttributeMaxDynamicSharedMemorySize, GEMM_SMEM);
    cudaFuncSetAttribute(gemm3bf<3>, cudaFuncAttributeMaxDynamicSharedMemorySize, GEMM_SMEM);
    cudaFuncSetAttribute(attn_mma_k, cudaFuncAttributeMaxDynamicSharedMemorySize, ATTN_SMEM);

    // lazy-created streams/events (host objects; identical work every call)
    static cudaStream_t st1 = nullptr, st2 = nullptr;
    static cudaEvent_t evS, evW1, evW2, evX, evQ, evK;
    if (st1 == nullptr) {
        cudaStreamCreateWithFlags(&st1, cudaStreamNonBlocking);
        cudaStreamCreateWithFlags(&st2, cudaStreamNonBlocking);
        cudaEventCreateWithFlags(&evS,  cudaEventDisableTiming);
        cudaEventCreateWithFlags(&evW1, cudaEventDisableTiming);
        cudaEventCreateWithFlags(&evW2, cudaEventDisableTiming);
        cudaEventCreateWithFlags(&evX,  cudaEventDisableTiming);
        cudaEventCreateWithFlags(&evQ,  cudaEventDisableTiming);
        cudaEventCreateWithFlags(&evK,  cudaEventDisableTiming);
    }

    dim3 tb(32, 8);
    const float sc = 0.08838834764831845f;
    dim3 gHH(HID/128, MTOK/256);   // (16, 16)

    // fork st1/st2 from the capture (legacy) stream
    cudaEventRecord(evS, 0);
    cudaStreamWaitEvent(st1, evS, 0);
    cudaStreamWaitEvent(st2, evS, 0);

    // --- legacy: convert ONLY wq/wk/wv (needed first)
    {
        TCJobs jqkv;
        jqkv.j[0] = { wq, pwq_h, pwq_l, 0 };
        jqkv.j[1] = { wk, pwk_h, pwk_l, 0 };
        jqkv.j[2] = { wv, pwv_h, pwv_l, 0 };
        jqkv.j[3] = jqkv.j[0];
        transconv64_k<<<dim3(HID/64, HID/64, 3), tb>>>(jqkv, HID, HID, 1);
    }
    cudaEventRecord(evW1, 0);   // qkv weights ready

    // --- st1: rmsnorm1 (overlaps qkv transconv), then Q GEMM
    rmsnorm_warp_k<<<MTOK/8, 256, 0, st1>>>(hidden, ln1, px_h, px_l);
    cudaEventRecord(evX, st1); // x ready
    cudaStreamWaitEvent(st1, evW1, 0);
    gemm3bf<2><<<gHH, 256, GEMM_SMEM, st1>>>(px_h, px_l, pwq_h, pwq_l, nullptr, nullptr,
                                             pq_h, pq_l, sc, MTOK, HID, HID);
    cudaEventRecord(evQ, st1);

    // --- st2: K GEMM, then the remaining weight conversions (hide in attention)
    cudaStreamWaitEvent(st2, evW1, 0);
    cudaStreamWaitEvent(st2, evX, 0);
    gemm3bf<2><<<gHH, 256, GEMM_SMEM, st2>>>(px_h, px_l, pwk_h, pwk_l, nullptr, nullptr,
                                             pk_h, pk_l, 1.f, MTOK, HID, HID);
    cudaEventRecord(evK, st2);
    {
        TCJobs jo;
        jo.j[0] = { wo, pwo_h, pwo_l, 0 };
        jo.j[1] = jo.j[0]; jo.j[2] = jo.j[0]; jo.j[3] = jo.j[0];
        transconv64_k<<<dim3(HID/64, HID/64, 1), tb, 0, st2>>>(jo, HID, HID, 1);

        TCJobs jgu;
        jgu.j[0] = { wg, pwgu_h, pwgu_l, 0 };
        jgu.j[1] = { wu, pwgu_h, pwgu_l, 1 };
        jgu.j[2] = jgu.j[0]; jgu.j[3] = jgu.j[0];
        transconv64_k<<<dim3(INTER/64, HID/64, 2), tb, 0, st2>>>(jgu, HID, INTER, 2);

        TCJobs jd;
        jd.j[0] = { wd, pwd_h, pwd_l, 0 };
        jd.j[1] = jd.j[0]; jd.j[2] = jd.j[0]; jd.j[3] = jd.j[0];
        transconv64_k<<<dim3(HID/64, INTER/64, 1), tb, 0, st2>>>(jd, INTER, HID, 1);
    }
    cudaEventRecord(evW2, st2);   // wo/wgu/wd ready

    // --- legacy: V GEMM (needs x + wv), vtrans
    cudaStreamWaitEvent(0, evX, 0);
    gemm3bf<2><<<gHH, 256, GEMM_SMEM>>>(px_h, px_l, pwv_h, pwv_l, nullptr, nullptr,
                                        pv_h, pv_l, 1.f, MTOK, HID, HID);
    vtrans64_k<<<dim3(32, 2, 32), tb>>>(pv_h, pv_l, pvt_h, pvt_l);

    // join Q and K before attention
    cudaStreamWaitEvent(0, evQ, 0);
    cudaStreamWaitEvent(0, evK, 0);

    // 3) tensor-core attention -> bf16 hi/lo (wo/wgu/wd converting concurrently on st2)
    attn_mma_k<<<dim3(16, 16, 2), 256, ATTN_SMEM>>>(pq_h, pq_l, pk_h, pk_l,
                                                    pvt_h, pvt_l, pat_h, pat_l);

    // join remaining weight conversions before O-proj
    cudaStreamWaitEvent(0, evW2, 0);

    // 4) O-proj + residual
    gemm3bf<1><<<gHH, 256, GEMM_SMEM>>>(pat_h, pat_l, pwo_h, pwo_l, hidden, h1,
                                        nullptr, nullptr, 1.f, MTOK, HID, HID);

    // 5) rmsnorm2 -> bf16 hi/lo
    rmsnorm_warp_k<<<MTOK/8, 256>>>(h1, ln2, px_h, px_l);

    // 6) fused gate+up GEMM with silu-mul epilogue -> m (bf16 hi/lo)
    gemm3bf<3><<<dim3(2*INTER/128, MTOK/256), 256, GEMM_SMEM>>>(
        px_h, px_l, pwgu_h, pwgu_l, nullptr, nullptr,
        pm_h, pm_l, 1.f, MTOK, 2*INTER, HID);

    // 7) down-proj + residual -> d_out
    gemm3bf<1><<<gHH, 256, GEMM_SMEM>>>(pm_h, pm_l, pwd_h, pwd_l, h1, (float*)d_out,
                                        nullptr, nullptr, 1.f, MTOK, HID, INTER);
}

// round 15
// speedup vs baseline: 1.0474x; 1.0067x over previous
#include <cuda_runtime.h>
#include <cuda_bf16.h>
#include <math.h>
#include <stdint.h>

#define MTOK 4096      // B*S
#define HID  2048
#define INTER 8192

// ======================= device scratch (no allocations) ====================
__device__ __nv_bfloat16 w_q_hi[HID*HID],  w_q_lo[HID*HID];
__device__ __nv_bfloat16 w_k_hi[HID*HID],  w_k_lo[HID*HID];
__device__ __nv_bfloat16 w_v_hi[HID*HID],  w_v_lo[HID*HID];
__device__ __nv_bfloat16 w_o_hi[HID*HID],  w_o_lo[HID*HID];
__device__ __nv_bfloat16 w_gu_hi[(size_t)2*INTER*HID], w_gu_lo[(size_t)2*INTER*HID]; // interleaved
__device__ __nv_bfloat16 w_d_hi[(size_t)HID*INTER], w_d_lo[(size_t)HID*INTER];
__device__ __nv_bfloat16 a_x_hi[MTOK*HID],  a_x_lo[MTOK*HID];
__device__ __nv_bfloat16 a_at_hi[MTOK*HID], a_at_lo[MTOK*HID];
__device__ __nv_bfloat16 a_m_hi[(size_t)MTOK*INTER], a_m_lo[(size_t)MTOK*INTER];
__device__ __nv_bfloat16 q_bhi[MTOK*HID], q_blo[MTOK*HID];
__device__ __nv_bfloat16 k_bhi[MTOK*HID], k_blo[MTOK*HID];
__device__ __nv_bfloat16 v_bhi[MTOK*HID], v_blo[MTOK*HID];
__device__ __nv_bfloat16 vt_hi[MTOK*HID], vt_lo[MTOK*HID];   // [b*16+h][hd][kv]
__device__ float s_h1[MTOK*HID];

// ======================= helpers ============================================
__device__ __forceinline__ uint32_t smem_u32(const void* p) {
    uint32_t a;
    asm("{ .reg .u64 t; cvta.to.shared.u64 t, %1; cvt.u32.u64 %0, t; }" : "=r"(a) : "l"(p));
    return a;
}
__device__ __forceinline__ void cp16(uint32_t s, const void* g) {
    asm volatile("cp.async.cg.shared.global [%0], [%1], 16;" :: "r"(s), "l"(g));
}
#define CP_COMMIT() asm volatile("cp.async.commit_group;")
#define CP_WAIT(N)  asm volatile("cp.async.wait_group %0;" :: "n"(N))

__device__ __forceinline__ void mma_bf16(float* c, const uint32_t* a, const uint32_t* b) {
    asm volatile(
        "mma.sync.aligned.m16n8k16.row.col.f32.bf16.bf16.f32 "
        "{%0,%1,%2,%3}, {%4,%5,%6,%7}, {%8,%9}, {%0,%1,%2,%3};"
        : "+f"(c[0]), "+f"(c[1]), "+f"(c[2]), "+f"(c[3])
        : "r"(a[0]), "r"(a[1]), "r"(a[2]), "r"(a[3]), "r"(b[0]), "r"(b[1]));
}
__device__ __forceinline__ void split2(float x, float y, uint32_t& hi, uint32_t& lo) {
    __nv_bfloat162 h;
    h.x = __float2bfloat16(x); h.y = __float2bfloat16(y);
    __nv_bfloat162 l;
    l.x = __float2bfloat16(x - __bfloat162float(h.x));
    l.y = __float2bfloat16(y - __bfloat162float(h.y));
    hi = *reinterpret_cast<uint32_t*>(&h);
    lo = *reinterpret_cast<uint32_t*>(&l);
}

// ======================= bf16x3 mma.sync GEMM (champion core) ===============
// OM: 0 = fp32 out, 1 = fp32 out + residual, 2 = bf16 hi/lo out (scaled),
//     3 = fused silu(even)*odd -> bf16 hi/lo out at column c/2 (Nout = N/2)
#define RB    144
#define ATILE (256*RB)
#define BTILE (128*RB)
#define STG   (2*ATILE + 2*BTILE)  // 110592
#define GEMM_SMEM (2*STG)          // 221184

template<int OM>
__global__ __launch_bounds__(256) void gemm3bf(
    const __nv_bfloat16* __restrict__ Ahi, const __nv_bfloat16* __restrict__ Alo,
    const __nv_bfloat16* __restrict__ Bhi, const __nv_bfloat16* __restrict__ Blo,
    const float* __restrict__ R, float* __restrict__ C,
    __nv_bfloat16* __restrict__ Ch, __nv_bfloat16* __restrict__ Cl,
    float scale, int M, int N, int K)
{
    extern __shared__ char sm[];
    const uint32_t sbase = smem_u32(sm);

    const int tid = threadIdx.x;
    const int lane = tid & 31;
    const int wid = tid >> 5;
    const int g = lane >> 2, tig = lane & 3;
    const int warp_m = wid & 3;
    const int warp_n = wid >> 2;
    const int bm = blockIdx.y * 256;
    const int bn = blockIdx.x * 128;

    const int crow = tid >> 3;
    const int ccolB = (tid & 7) * 16;

    const int S = K >> 6;

    auto load_stage = [&](int s) {
        const uint32_t b = sbase + (uint32_t)(s & 1) * STG;
        const int k0 = s << 6;
        const size_t ga = ((size_t)(bm + crow) * K + k0) * 2 + ccolB;
        const size_t gb = ((size_t)(bn + crow) * K + k0) * 2 + ccolB;
        const size_t rstep = (size_t)32 * K * 2;
        const char* pah = (const char*)Ahi + ga;
        const char* pal = (const char*)Alo + ga;
        const char* pbh = (const char*)Bhi + gb;
        const char* pbl = (const char*)Blo + gb;
        #pragma unroll
        for (int i = 0; i < 8; i++) {
            const uint32_t so = (uint32_t)((crow + 32*i) * RB + ccolB);
            cp16(b + so,         pah); pah += rstep;
            cp16(b + ATILE + so, pal); pal += rstep;
        }
        #pragma unroll
        for (int i = 0; i < 4; i++) {
            const uint32_t so = (uint32_t)((crow + 32*i) * RB + ccolB);
            cp16(b + 2*ATILE + so,         pbh); pbh += rstep;
            cp16(b + 2*ATILE + BTILE + so, pbl); pbl += rstep;
        }
        CP_COMMIT();
    };

    load_stage(0);
    if (S > 1) load_stage(1);

    float acc[4][8][4];
    #pragma unroll
    for (int mt = 0; mt < 4; mt++)
        #pragma unroll
        for (int nt = 0; nt < 8; nt++)
            #pragma unroll
            for (int e = 0; e < 4; e++) acc[mt][nt][e] = 0.f;

    const int arow0 = warp_m * 64 + g;
    const int brow0 = warp_n * 64 + g;

    for (int s = 0; s < S; ++s) {
        if (s + 1 < S) { CP_WAIT(1); } else { CP_WAIT(0); }
        __syncthreads();
        const char* b = sm + (size_t)(s & 1) * STG;

        #pragma unroll
        for (int ks = 0; ks < 4; ++ks) {
            const int kb = ks * 32 + tig * 4;

            uint32_t bhf[8][2], blf[8][2];
            #pragma unroll
            for (int nt = 0; nt < 8; nt++) {
                const char* rb = b + 2*ATILE + (brow0 + nt*8) * RB + kb;
                bhf[nt][0] = *(const uint32_t*)(rb);
                bhf[nt][1] = *(const uint32_t*)(rb + 16);
                blf[nt][0] = *(const uint32_t*)(rb + BTILE);
                blf[nt][1] = *(const uint32_t*)(rb + BTILE + 16);
            }

            #pragma unroll
            for (int mt = 0; mt < 4; mt++) {
                uint32_t ah[4], al[4];
                const char* ra = b + (arow0 + mt*16) * RB + kb;
                ah[0] = *(const uint32_t*)(ra);
                ah[1] = *(const uint32_t*)(ra + 8*RB);
                ah[2] = *(const uint32_t*)(ra + 16);
                ah[3] = *(const uint32_t*)(ra + 8*RB + 16);
                al[0] = *(const uint32_t*)(ra + ATILE);
                al[1] = *(const uint32_t*)(ra + ATILE + 8*RB);
                al[2] = *(const uint32_t*)(ra + ATILE + 16);
                al[3] = *(const uint32_t*)(ra + ATILE + 8*RB + 16);

                #pragma unroll
                for (int nt = 0; nt < 8; nt++)
                    mma_bf16(acc[mt][nt], ah, bhf[nt]);
                #pragma unroll
                for (int nt = 0; nt < 8; nt++)
                    mma_bf16(acc[mt][nt], ah, blf[nt]);
                #pragma unroll
                for (int nt = 0; nt < 8; nt++)
                    mma_bf16(acc[mt][nt], al, bhf[nt]);
            }
        }
        __syncthreads();
        if (s + 2 < S) load_stage(s + 2);
    }

    const int row0 = bm + warp_m*64 + g;
    const int col0 = bn + warp_n*64 + tig*2;
    #pragma unroll
    for (int mt = 0; mt < 4; mt++) {
        #pragma unroll
        for (int nt = 0; nt < 8; nt++) {
            const int r = row0 + mt*16;
            const int c = col0 + nt*8;
            if (OM == 3) {
                const int Nout = N >> 1;
                const int cc = c >> 1;
                const float g0 = acc[mt][nt][0], u0 = acc[mt][nt][1];
                const float g1 = acc[mt][nt][2], u1 = acc[mt][nt][3];
                const float r0 = g0 / (1.f + __expf(-g0)) * u0;
                const float r1 = g1 / (1.f + __expf(-g1)) * u1;
                const __nv_bfloat16 h0 = __float2bfloat16(r0);
                const __nv_bfloat16 h1 = __float2bfloat16(r1);
                Ch[(size_t)r * Nout + cc]     = h0;
                Cl[(size_t)r * Nout + cc]     = __float2bfloat16(r0 - __bfloat162float(h0));
                Ch[(size_t)(r+8) * Nout + cc] = h1;
                Cl[(size_t)(r+8) * Nout + cc] = __float2bfloat16(r1 - __bfloat162float(h1));
            } else if (OM == 2) {
                uint32_t h0, l0u, h1, l1u;
                split2(acc[mt][nt][0]*scale, acc[mt][nt][1]*scale, h0, l0u);
                split2(acc[mt][nt][2]*scale, acc[mt][nt][3]*scale, h1, l1u);
                *(uint32_t*)(Ch + (size_t)r * N + c)     = h0;
                *(uint32_t*)(Cl + (size_t)r * N + c)     = l0u;
                *(uint32_t*)(Ch + (size_t)(r+8) * N + c) = h1;
                *(uint32_t*)(Cl + (size_t)(r+8) * N + c) = l1u;
            } else {
                float2 v0 = make_float2(acc[mt][nt][0], acc[mt][nt][1]);
                float2 v1 = make_float2(acc[mt][nt][2], acc[mt][nt][3]);
                if (OM == 1) {
                    const float2 r0 = *(const float2*)(R + (size_t)r * N + c);
                    const float2 r1 = *(const float2*)(R + (size_t)(r+8) * N + c);
                    v0.x += r0.x; v0.y += r0.y;
                    v1.x += r1.x; v1.y += r1.y;
                }
                *(float2*)(C + (size_t)r * N + c)     = v0;
                *(float2*)(C + (size_t)(r+8) * N + c) = v1;
            }
        }
    }
}

// ======================= tensor-core causal flash attention =================
// (champion core + hOff head-group parameter)
#define RBQ 272
#define RBV 144
#define QT_BYTES (128*RBQ)
#define KT_BYTES (64*RBQ)
#define VT_BYTES (128*RBV)
#define STAGE_B  (2*KT_BYTES + 2*VT_BYTES)
#define ATTN_SMEM (2*QT_BYTES + 2*STAGE_B)

__global__ __launch_bounds__(256) void attn_mma_k(
    const __nv_bfloat16* __restrict__ qh, const __nv_bfloat16* __restrict__ ql,
    const __nv_bfloat16* __restrict__ kh, const __nv_bfloat16* __restrict__ kl,
    const __nv_bfloat16* __restrict__ vh, const __nv_bfloat16* __restrict__ vl,
    __nv_bfloat16* __restrict__ Oh, __nv_bfloat16* __restrict__ Ol, int hOff)
{
    extern __shared__ char sm[];
    const uint32_t sb = smem_u32(sm);

    const int tid = threadIdx.x, lane = tid & 31, wid = tid >> 5;
    const int g = lane >> 2, tig = lane & 3;
    const int qt = 15 - blockIdx.x, h = blockIdx.y + hOff, b = blockIdx.z;
    const int ntiles = 2 * (qt + 1);

    {
        const size_t gq = ((size_t)(b*2048 + qt*128) * 2048 + h*128) * 2;
        #pragma unroll
        for (int i = 0; i < 16; i++) {
            const int c = tid + i*256;
            const int t = c >> 11;
            const int cc = c & 2047;
            const int row = cc >> 4, col = cc & 15;
            const char* gp = (const char*)(t ? ql : qh) + gq + (size_t)row*4096 + col*16;
            cp16(sb + (t ? QT_BYTES : 0) + row*RBQ + col*16, gp);
        }
        CP_COMMIT();
    }

    auto load_stage = [&](int kt) {
        const uint32_t base = sb + 2*QT_BYTES + (uint32_t)(kt & 1) * STAGE_B;
        const size_t gk = ((size_t)(b*2048 + kt*64) * 2048 + h*128) * 2;
        const size_t gv = (((size_t)((b*16 + h)*128)) * 2048 + kt*64) * 2;
        #pragma unroll
        for (int i = 0; i < 16; i++) {
            const int c = tid + i*256;
            const int sel = c >> 10;
            const int cc = c & 1023;
            if (sel < 2) {
                const int row = cc >> 4, col = cc & 15;
                const char* gp = (const char*)(sel ? kl : kh) + gk + (size_t)row*4096 + col*16;
                cp16(base + (sel ? KT_BYTES : 0) + row*RBQ + col*16, gp);
            } else {
                const int row = cc >> 3, col = cc & 7;
                const char* gp = (const char*)(sel == 3 ? vl : vh) + gv + (size_t)row*4096 + col*16;
                cp16(base + 2*KT_BYTES + (sel == 3 ? VT_BYTES : 0) + row*RBV + col*16, gp);
            }
        }
        CP_COMMIT();
    };

    load_stage(0);
    load_stage(1);

    float accO[16][4];
    #pragma unroll
    for (int nt = 0; nt < 16; nt++)
        #pragma unroll
        for (int e = 0; e < 4; e++) accO[nt][e] = 0.f;
    float m0 = -INFINITY, m1 = -INFINITY, l0 = 0.f, l1 = 0.f;

    const int row0 = wid * 16;
    const int qrow0 = qt*128 + row0 + g;

    for (int s = 0; s < ntiles; s++) {
        if (s + 1 < ntiles) { CP_WAIT(1); } else { CP_WAIT(0); }
        __syncthreads();
        const char* stg = sm + 2*QT_BYTES + (size_t)(s & 1) * STAGE_B;

        float accS[8][4];
        #pragma unroll
        for (int nt = 0; nt < 8; nt++)
            #pragma unroll
            for (int e = 0; e < 4; e++) accS[nt][e] = 0.f;

        #pragma unroll
        for (int ks = 0; ks < 8; ks++) {
            const int kb = ks*32 + tig*4;
            uint32_t ah[4], al[4], bh2[8][2], bl2[8][2];
            const char* ra = sm + (row0 + g)*RBQ + kb;
            ah[0] = *(const uint32_t*)(ra);
            ah[1] = *(const uint32_t*)(ra + 8*RBQ);
            ah[2] = *(const uint32_t*)(ra + 16);
            ah[3] = *(const uint32_t*)(ra + 8*RBQ + 16);
            al[0] = *(const uint32_t*)(ra + QT_BYTES);
            al[1] = *(const uint32_t*)(ra + QT_BYTES + 8*RBQ);
            al[2] = *(const uint32_t*)(ra + QT_BYTES + 16);
            al[3] = *(const uint32_t*)(ra + QT_BYTES + 8*RBQ + 16);
            #pragma unroll
            for (int nt = 0; nt < 8; nt++) {
                const char* rb = stg + (nt*8 + g)*RBQ + kb;
                bh2[nt][0] = *(const uint32_t*)(rb);
                bh2[nt][1] = *(const uint32_t*)(rb + 16);
                bl2[nt][0] = *(const uint32_t*)(rb + KT_BYTES);
                bl2[nt][1] = *(const uint32_t*)(rb + KT_BYTES + 16);
            }
            #pragma unroll
            for (int nt = 0; nt < 8; nt++) mma_bf16(accS[nt], ah, bh2[nt]);
            #pragma unroll
            for (int nt = 0; nt < 8; nt++) mma_bf16(accS[nt], ah, bl2[nt]);
            #pragma unroll
            for (int nt = 0; nt < 8; nt++) mma_bf16(accS[nt], al, bh2[nt]);
        }

        if (s >= ntiles - 2) {
            #pragma unroll
            for (int nt = 0; nt < 8; nt++) {
                const int col = s*64 + nt*8 + tig*2;
                if (col     > qrow0)     accS[nt][0] = -INFINITY;
                if (col + 1 > qrow0)     accS[nt][1] = -INFINITY;
                if (col     > qrow0 + 8) accS[nt][2] = -INFINITY;
                if (col + 1 > qrow0 + 8) accS[nt][3] = -INFINITY;
            }
        }

        float mt0 = -INFINITY, mt1 = -INFINITY;
        #pragma unroll
        for (int nt = 0; nt < 8; nt++) {
            mt0 = fmaxf(mt0, fmaxf(accS[nt][0], accS[nt][1]));
            mt1 = fmaxf(mt1, fmaxf(accS[nt][2], accS[nt][3]));
        }
        mt0 = fmaxf(mt0, __shfl_xor_sync(0xffffffffu, mt0, 1));
        mt0 = fmaxf(mt0, __shfl_xor_sync(0xffffffffu, mt0, 2));
        mt1 = fmaxf(mt1, __shfl_xor_sync(0xffffffffu, mt1, 1));
        mt1 = fmaxf(mt1, __shfl_xor_sync(0xffffffffu, mt1, 2));

        const float mn0 = fmaxf(m0, mt0), mn1 = fmaxf(m1, mt1);
        const float sc0 = __expf(m0 - mn0), sc1 = __expf(m1 - mn1);
        m0 = mn0; m1 = mn1;

        float rs0 = 0.f, rs1 = 0.f;
        #pragma unroll
        for (int nt = 0; nt < 8; nt++) {
            accS[nt][0] = __expf(accS[nt][0] - mn0);
            accS[nt][1] = __expf(accS[nt][1] - mn0);
            accS[nt][2] = __expf(accS[nt][2] - mn1);
            accS[nt][3] = __expf(accS[nt][3] - mn1);
            rs0 += accS[nt][0] + accS[nt][1];
            rs1 += accS[nt][2] + accS[nt][3];
        }
        rs0 += __shfl_xor_sync(0xffffffffu, rs0, 1);
        rs0 += __shfl_xor_sync(0xffffffffu, rs0, 2);
        rs1 += __shfl_xor_sync(0xffffffffu, rs1, 1);
        rs1 += __shfl_xor_sync(0xffffffffu, rs1, 2);
        l0 = l0*sc0 + rs0;
        l1 = l1*sc1 + rs1;

        #pragma unroll
        for (int nt = 0; nt < 16; nt++) {
            accO[nt][0] *= sc0; accO[nt][1] *= sc0;
            accO[nt][2] *= sc1; accO[nt][3] *= sc1;
        }

        #pragma unroll
        for (int kk = 0; kk < 4; kk++) {
            uint32_t ph[4], pl[4];
            split2(accS[2*kk][0],   accS[2*kk][1],   ph[0], pl[0]);
            split2(accS[2*kk][2],   accS[2*kk][3],   ph[1], pl[1]);
            split2(accS[2*kk+1][0], accS[2*kk+1][1], ph[2], pl[2]);
            split2(accS[2*kk+1][2], accS[2*kk+1][3], ph[3], pl[3]);
            const int kb = kk*32 + tig*4;
            #pragma unroll
            for (int nt = 0; nt < 16; nt++) {
                const char* rv = stg + 2*KT_BYTES + (nt*8 + g)*RBV + kb;
                uint32_t vbh[2], vbl[2];
                vbh[0] = *(const uint32_t*)(rv);
                vbh[1] = *(const uint32_t*)(rv + 16);
                vbl[0] = *(const uint32_t*)(rv + VT_BYTES);
                vbl[1] = *(const uint32_t*)(rv + VT_BYTES + 16);
                mma_bf16(accO[nt], ph, vbh);
                mma_bf16(accO[nt], ph, vbl);
                mma_bf16(accO[nt], pl, vbh);
            }
        }

        __syncthreads();
        if (s + 2 < ntiles) load_stage(s + 2);
    }

    const float inv0 = 1.f / l0, inv1 = 1.f / l1;
    const size_t ob = ((size_t)(b*2048 + qt*128 + row0 + g)) * 2048 + h*128;
    #pragma unroll
    for (int nt = 0; nt < 16; nt++) {
        const int c = nt*8 + tig*2;
        uint32_t h0, l0u, h1, l1u;
        split2(accO[nt][0]*inv0, accO[nt][1]*inv0, h0, l0u);
        split2(accO[nt][2]*inv1, accO[nt][3]*inv1, h1, l1u);
        *(uint32_t*)(Oh + ob + c)           = h0;
        *(uint32_t*)(Ol + ob + c)           = l0u;
        *(uint32_t*)(Oh + ob + 8*2048 + c)  = h1;
        *(uint32_t*)(Ol + ob + 8*2048 + c)  = l1u;
    }
}

// ======================= batched weight transpose + split ====================
struct TCJob  { const float* W; __nv_bfloat16* Th; __nv_bfloat16* Tl; int rowOff; };
struct TCJobs { TCJob j[4]; };

__global__ void transconv64_k(TCJobs jobs, int K, int N, int rowStride)
{
    const TCJob jb = jobs.j[blockIdx.z];
    __shared__ float t[64][65];
    const int n0 = blockIdx.x * 64, k0 = blockIdx.y * 64;
    const int tx = threadIdx.x, ty = threadIdx.y;   // (32, 8)
    #pragma unroll
    for (int r = ty; r < 64; r += 8) {
        const float2 v = *(const float2*)(jb.W + (size_t)(k0 + r) * N + n0 + 2*tx);
        t[r][2*tx]   = v.x;
        t[r][2*tx+1] = v.y;
    }
    __syncthreads();
    #pragma unroll
    for (int i = ty; i < 64; i += 8) {
        uint32_t hi, lo;
        split2(t[2*tx][i], t[2*tx+1][i], hi, lo);
        const size_t o = ((size_t)(n0 + i) * rowStride + jb.rowOff) * K + k0 + 2*tx;
        *(uint32_t*)(jb.Th + o) = hi;
        *(uint32_t*)(jb.Tl + o) = lo;
    }
}

// ======================= V transpose (64x64, u32 I/O, head-group) ===========
__global__ void vtrans64_k(const __nv_bfloat16* __restrict__ Vh,
                           const __nv_bfloat16* __restrict__ Vl,
                           __nv_bfloat16* __restrict__ Th, __nv_bfloat16* __restrict__ Tl,
                           int hOff)
{
    __shared__ __nv_bfloat16 th[64][66], tl[64][66];
    const int kv0 = blockIdx.x * 64, hd0 = blockIdx.y * 64;
    const int b = blockIdx.z >> 3, h = (blockIdx.z & 7) + hOff;
    const int bh = b*16 + h;
    const int tx = threadIdx.x, ty = threadIdx.y;      // (32, 8)
    #pragma unroll
    for (int r = ty; r < 64; r += 8) {
        const size_t src = (size_t)(b*2048 + kv0 + r) * 2048 + h*128 + hd0 + 2*tx;
        *(uint32_t*)&th[r][2*tx] = *(const uint32_t*)(Vh + src);
        *(uint32_t*)&tl[r][2*tx] = *(const uint32_t*)(Vl + src);
    }
    __syncthreads();
    #pragma unroll
    for (int i = ty; i < 64; i += 8) {
        __nv_bfloat162 ph, pl;
        ph.x = th[2*tx][i]; ph.y = th[2*tx+1][i];
        pl.x = tl[2*tx][i]; pl.y = tl[2*tx+1][i];
        const size_t o = ((size_t)(bh*128 + hd0 + i)) * 2048 + kv0 + 2*tx;
        *(uint32_t*)(Th + o) = *(uint32_t*)&ph;
        *(uint32_t*)(Tl + o) = *(uint32_t*)&pl;
    }
}

// ======================= RMSNorm: warp-per-row, barrier-free ================
__global__ __launch_bounds__(256) void rmsnorm_warp_k(
    const float* __restrict__ x, const float* __restrict__ w,
    __nv_bfloat16* __restrict__ yh, __nv_bfloat16* __restrict__ yl)
{
    const int row  = blockIdx.x * 8 + (threadIdx.x >> 5);
    const int lane = threadIdx.x & 31;
    const float4* xr = (const float4*)(x + (size_t)row * HID);
    const float4* w4 = (const float4*)w;

    float ss = 0.f;
    #pragma unroll
    for (int i = 0; i < 16; i++) {
        const float4 v = xr[i*32 + lane];
        ss += v.x*v.x + v.y*v.y + v.z*v.z + v.w*v.w;
    }
    #pragma unroll
    for (int off = 16; off > 0; off >>= 1)
        ss += __shfl_xor_sync(0xffffffffu, ss, off);
    const float inv = rsqrtf(ss * (1.f / (float)HID) + 1e-6f);

    #pragma unroll
    for (int i = 0; i < 16; i++) {
        const float4 v = xr[i*32 + lane];
        const float4 ww = w4[i*32 + lane];
        const float o0 = v.x*inv*ww.x, o1 = v.y*inv*ww.y;
        const float o2 = v.z*inv*ww.z, o3 = v.w*inv*ww.w;
        uint32_t h0, l0, h1, l1;
        split2(o0, o1, h0, l0);
        split2(o2, o3, h1, l1);
        const size_t base = (size_t)row * HID + (size_t)(i*32 + lane) * 4;
        uint2 vh = make_uint2(h0, h1), vl = make_uint2(l0, l1);
        *(uint2*)(yh + base) = vh;
        *(uint2*)(yl + base) = vl;
    }
}

// ======================= launch =============================================
extern "C" void kernel_launch(void* const* d_in, const int* in_sizes, int n_in,
                              void* d_out, int out_size)
{
    const float* hidden = (const float*)d_in[0];
    const float* wq  = (const float*)d_in[1];
    const float* wk  = (const float*)d_in[2];
    const float* wv  = (const float*)d_in[3];
    const float* wo  = (const float*)d_in[4];
    const float* wg  = (const float*)d_in[5];
    const float* wu  = (const float*)d_in[6];
    const float* wd  = (const float*)d_in[7];
    const float* ln1 = (const float*)d_in[8];
    const float* ln2 = (const float*)d_in[9];

    __nv_bfloat16 *pwq_h,*pwq_l,*pwk_h,*pwk_l,*pwv_h,*pwv_l,*pwo_h,*pwo_l;
    __nv_bfloat16 *pwgu_h,*pwgu_l,*pwd_h,*pwd_l;
    __nv_bfloat16 *px_h,*px_l,*pat_h,*pat_l,*pm_h,*pm_l;
    __nv_bfloat16 *pq_h,*pq_l,*pk_h,*pk_l,*pv_h,*pv_l,*pvt_h,*pvt_l;
    float *h1;
    cudaGetSymbolAddress((void**)&pwq_h, w_q_hi); cudaGetSymbolAddress((void**)&pwq_l, w_q_lo);
    cudaGetSymbolAddress((void**)&pwk_h, w_k_hi); cudaGetSymbolAddress((void**)&pwk_l, w_k_lo);
    cudaGetSymbolAddress((void**)&pwv_h, w_v_hi); cudaGetSymbolAddress((void**)&pwv_l, w_v_lo);
    cudaGetSymbolAddress((void**)&pwo_h, w_o_hi); cudaGetSymbolAddress((void**)&pwo_l, w_o_lo);
    cudaGetSymbolAddress((void**)&pwgu_h, w_gu_hi); cudaGetSymbolAddress((void**)&pwgu_l, w_gu_lo);
    cudaGetSymbolAddress((void**)&pwd_h, w_d_hi); cudaGetSymbolAddress((void**)&pwd_l, w_d_lo);
    cudaGetSymbolAddress((void**)&px_h,  a_x_hi); cudaGetSymbolAddress((void**)&px_l,  a_x_lo);
    cudaGetSymbolAddress((void**)&pat_h, a_at_hi);cudaGetSymbolAddress((void**)&pat_l, a_at_lo);
    cudaGetSymbolAddress((void**)&pm_h,  a_m_hi); cudaGetSymbolAddress((void**)&pm_l,  a_m_lo);
    cudaGetSymbolAddress((void**)&pq_h,  q_bhi);  cudaGetSymbolAddress((void**)&pq_l,  q_blo);
    cudaGetSymbolAddress((void**)&pk_h,  k_bhi);  cudaGetSymbolAddress((void**)&pk_l,  k_blo);
    cudaGetSymbolAddress((void**)&pv_h,  v_bhi);  cudaGetSymbolAddress((void**)&pv_l,  v_blo);
    cudaGetSymbolAddress((void**)&pvt_h, vt_hi);  cudaGetSymbolAddress((void**)&pvt_l, vt_lo);
    cudaGetSymbolAddress((void**)&h1, s_h1);

    cudaFuncSetAttribute(gemm3bf<0>, cudaFuncAttributeMaxDynamicSharedMemorySize, GEMM_SMEM);
    cudaFuncSetAttribute(gemm3bf<1>, cudaFuncAttributeMaxDynamicSharedMemorySize, GEMM_SMEM);
    cudaFuncSetAttribute(gemm3bf<2>, cudaFuncAttributeMaxDynamicSharedMemorySize, GEMM_SMEM);
    cudaFuncSetAttribute(gemm3bf<3>, cudaFuncAttributeMaxDynamicSharedMemorySize, GEMM_SMEM);
    cudaFuncSetAttribute(attn_mma_k, cudaFuncAttributeMaxDynamicSharedMemorySize, ATTN_SMEM);

    static cudaStream_t st1 = nullptr, st2 = nullptr;
    static cudaEvent_t evS, evW1, evW2, evX, evQA, evQB, evKA, evKB, evVB, evAB;
    if (st1 == nullptr) {
        cudaStreamCreateWithFlags(&st1, cudaStreamNonBlocking);
        cudaStreamCreateWithFlags(&st2, cudaStreamNonBlocking);
        cudaEventCreateWithFlags(&evS,  cudaEventDisableTiming);
        cudaEventCreateWithFlags(&evW1, cudaEventDisableTiming);
        cudaEventCreateWithFlags(&evW2, cudaEventDisableTiming);
        cudaEventCreateWithFlags(&evX,  cudaEventDisableTiming);
        cudaEventCreateWithFlags(&evQA, cudaEventDisableTiming);
        cudaEventCreateWithFlags(&evQB, cudaEventDisableTiming);
        cudaEventCreateWithFlags(&evKA, cudaEventDisableTiming);
        cudaEventCreateWithFlags(&evKB, cudaEventDisableTiming);
        cudaEventCreateWithFlags(&evVB, cudaEventDisableTiming);
        cudaEventCreateWithFlags(&evAB, cudaEventDisableTiming);
    }

    dim3 tb(32, 8);
    const float sc = 0.08838834764831845f;
    const dim3 gHalf(8, MTOK/256);      // half-N projection grid (1024 cols)
    const dim3 gHH(HID/128, MTOK/256);  // full-N grid
    const size_t wHalf = (size_t)1024 * HID;   // B-row offset for heads 8-15

    // fork
    cudaEventRecord(evS, 0);
    cudaStreamWaitEvent(st1, evS, 0);
    cudaStreamWaitEvent(st2, evS, 0);

    // --- legacy: convert wq/wk/wv
    {
        TCJobs jqkv;
        jqkv.j[0] = { wq, pwq_h, pwq_l, 0 };
        jqkv.j[1] = { wk, pwk_h, pwk_l, 0 };
        jqkv.j[2] = { wv, pwv_h, pwv_l, 0 };
        jqkv.j[3] = jqkv.j[0];
        transconv64_k<<<dim3(HID/64, HID/64, 3), tb>>>(jqkv, HID, HID, 1);
    }
    cudaEventRecord(evW1, 0);

    // --- st1: rmsnorm1, Q halves, V-B + vtrans-B, then deferred weight convs
    rmsnorm_warp_k<<<MTOK/8, 256, 0, st1>>>(hidden, ln1, px_h, px_l);
    cudaEventRecord(evX, st1);
    cudaStreamWaitEvent(st1, evW1, 0);
    gemm3bf<2><<<gHalf, 256, GEMM_SMEM, st1>>>(px_h, px_l, pwq_h, pwq_l, nullptr, nullptr,
                                               pq_h, pq_l, sc, MTOK, HID, HID);
    cudaEventRecord(evQA, st1);
    gemm3bf<2><<<gHalf, 256, GEMM_SMEM, st1>>>(px_h, px_l, pwq_h + wHalf, pwq_l + wHalf,
                                               nullptr, nullptr,
                                               pq_h + 1024, pq_l + 1024, sc, MTOK, HID, HID);
    cudaEventRecord(evQB, st1);
    gemm3bf<2><<<gHalf, 256, GEMM_SMEM, st1>>>(px_h, px_l, pwv_h + wHalf, pwv_l + wHalf,
                                               nullptr, nullptr,
                                               pv_h + 1024, pv_l + 1024, 1.f, MTOK, HID, HID);
    vtrans64_k<<<dim3(32, 2, 16), tb, 0, st1>>>(pv_h, pv_l, pvt_h, pvt_l, 8);
    cudaEventRecord(evVB, st1);
    {
        TCJobs jo;
        jo.j[0] = { wo, pwo_h, pwo_l, 0 };
        jo.j[1] = jo.j[0]; jo.j[2] = jo.j[0]; jo.j[3] = jo.j[0];
        transconv64_k<<<dim3(HID/64, HID/64, 1), tb, 0, st1>>>(jo, HID, HID, 1);

        TCJobs jgu;
        jgu.j[0] = { wg, pwgu_h, pwgu_l, 0 };
        jgu.j[1] = { wu, pwgu_h, pwgu_l, 1 };
        jgu.j[2] = jgu.j[0]; jgu.j[3] = jgu.j[0];
        transconv64_k<<<dim3(INTER/64, HID/64, 2), tb, 0, st1>>>(jgu, HID, INTER, 2);

        TCJobs jd;
        jd.j[0] = { wd, pwd_h, pwd_l, 0 };
        jd.j[1] = jd.j[0]; jd.j[2] = jd.j[0]; jd.j[3] = jd.j[0];
        transconv64_k<<<dim3(HID/64, INTER/64, 1), tb, 0, st1>>>(jd, INTER, HID, 1);
    }
    cudaEventRecord(evW2, st1);

    // --- st2: K halves, then attn-B when its inputs are ready
    cudaStreamWaitEvent(st2, evW1, 0);
    cudaStreamWaitEvent(st2, evX, 0);
    gemm3bf<2><<<gHalf, 256, GEMM_SMEM, st2>>>(px_h, px_l, pwk_h, pwk_l, nullptr, nullptr,
                                               pk_h, pk_l, 1.f, MTOK, HID, HID);
    cudaEventRecord(evKA, st2);
    gemm3bf<2><<<gHalf, 256, GEMM_SMEM, st2>>>(px_h, px_l, pwk_h + wHalf, pwk_l + wHalf,
                                               nullptr, nullptr,
                                               pk_h + 1024, pk_l + 1024, 1.f, MTOK, HID, HID);
    cudaStreamWaitEvent(st2, evQB, 0);
    cudaStreamWaitEvent(st2, evVB, 0);
    attn_mma_k<<<dim3(16, 8, 2), 256, ATTN_SMEM, st2>>>(pq_h, pq_l, pk_h, pk_l,
                                                        pvt_h, pvt_l, pat_h, pat_l, 8);
    cudaEventRecord(evAB, st2);

    // --- legacy: V-A, vtrans-A, attn-A
    cudaStreamWaitEvent(0, evX, 0);
    gemm3bf<2><<<gHalf, 256, GEMM_SMEM>>>(px_h, px_l, pwv_h, pwv_l, nullptr, nullptr,
                                          pv_h, pv_l, 1.f, MTOK, HID, HID);
    vtrans64_k<<<dim3(32, 2, 16), tb>>>(pv_h, pv_l, pvt_h, pvt_l, 0);
    cudaStreamWaitEvent(0, evQA, 0);
    cudaStreamWaitEvent(0, evKA, 0);
    attn_mma_k<<<dim3(16, 8, 2), 256, ATTN_SMEM>>>(pq_h, pq_l, pk_h, pk_l,
                                                   pvt_h, pvt_l, pat_h, pat_l, 0);

    // join attn-B + remaining weights before O-proj
    cudaStreamWaitEvent(0, evAB, 0);
    cudaStreamWaitEvent(0, evW2, 0);

    // 4) O-proj + residual
    gemm3bf<1><<<gHH, 256, GEMM_SMEM>>>(pat_h, pat_l, pwo_h, pwo_l, hidden, h1,
                                        nullptr, nullptr, 1.f, MTOK, HID, HID);

    // 5) rmsnorm2 -> bf16 hi/lo
    rmsnorm_warp_k<<<MTOK/8, 256>>>(h1, ln2, px_h, px_l);

    // 6) fused gate+up GEMM with silu-mul epilogue -> m (bf16 hi/lo)
    gemm3bf<3><<<dim3(2*INTER/128, MTOK/256), 256, GEMM_SMEM>>>(
        px_h, px_l, pwgu_h, pwgu_l, nullptr, nullptr,
        pm_h, pm_l, 1.f, MTOK, 2*INTER, HID);

    // 7) down-proj + residual -> d_out
    gemm3bf<1><<<gHH, 256, GEMM_SMEM>>>(pm_h, pm_l, pwd_h, pwd_l, h1, (float*)d_out,
                                        nullptr, nullptr, 1.f, MTOK, HID, INTER);
}

// round 16
// speedup vs baseline: 1.0788x; 1.0300x over previous
#include <cuda_runtime.h>
#include <cuda_bf16.h>
#include <math.h>
#include <stdint.h>

#define MTOK 4096      // B*S
#define HID  2048
#define INTER 8192

// ======================= device scratch (no allocations) ====================
__device__ __nv_bfloat16 w_q_hi[HID*HID],  w_q_lo[HID*HID];
__device__ __nv_bfloat16 w_k_hi[HID*HID],  w_k_lo[HID*HID];
__device__ __nv_bfloat16 w_v_hi[HID*HID],  w_v_lo[HID*HID];
__device__ __nv_bfloat16 w_o_hi[HID*HID],  w_o_lo[HID*HID];
__device__ __nv_bfloat16 w_gu_hi[(size_t)2*INTER*HID], w_gu_lo[(size_t)2*INTER*HID]; // interleaved
__device__ __nv_bfloat16 w_d_hi[(size_t)HID*INTER], w_d_lo[(size_t)HID*INTER];
__device__ __nv_bfloat16 a_x_hi[MTOK*HID],  a_x_lo[MTOK*HID];
__device__ __nv_bfloat16 a_at_hi[MTOK*HID], a_at_lo[MTOK*HID];
__device__ __nv_bfloat16 a_m_hi[(size_t)MTOK*INTER], a_m_lo[(size_t)MTOK*INTER];
__device__ __nv_bfloat16 q_bhi[MTOK*HID], q_blo[MTOK*HID];
__device__ __nv_bfloat16 k_bhi[MTOK*HID], k_blo[MTOK*HID];
__device__ __nv_bfloat16 v_bhi[MTOK*HID], v_blo[MTOK*HID];
__device__ __nv_bfloat16 vt_hi[MTOK*HID], vt_lo[MTOK*HID];   // [b*16+h][hd][kv]
__device__ float s_h1[MTOK*HID];

// ======================= helpers ============================================
__device__ __forceinline__ uint32_t smem_u32(const void* p) {
    uint32_t a;
    asm("{ .reg .u64 t; cvta.to.shared.u64 t, %1; cvt.u32.u64 %0, t; }" : "=r"(a) : "l"(p));
    return a;
}
__device__ __forceinline__ void cp16(uint32_t s, const void* g) {
    asm volatile("cp.async.cg.shared.global [%0], [%1], 16;" :: "r"(s), "l"(g));
}
#define CP_COMMIT() asm volatile("cp.async.commit_group;")
#define CP_WAIT(N)  asm volatile("cp.async.wait_group %0;" :: "n"(N))

__device__ __forceinline__ void mma_bf16(float* c, const uint32_t* a, const uint32_t* b) {
    asm volatile(
        "mma.sync.aligned.m16n8k16.row.col.f32.bf16.bf16.f32 "
        "{%0,%1,%2,%3}, {%4,%5,%6,%7}, {%8,%9}, {%0,%1,%2,%3};"
        : "+f"(c[0]), "+f"(c[1]), "+f"(c[2]), "+f"(c[3])
        : "r"(a[0]), "r"(a[1]), "r"(a[2]), "r"(a[3]), "r"(b[0]), "r"(b[1]));
}
__device__ __forceinline__ void split2(float x, float y, uint32_t& hi, uint32_t& lo) {
    __nv_bfloat162 h;
    h.x = __float2bfloat16(x); h.y = __float2bfloat16(y);
    __nv_bfloat162 l;
    l.x = __float2bfloat16(x - __bfloat162float(h.x));
    l.y = __float2bfloat16(y - __bfloat162float(h.y));
    hi = *reinterpret_cast<uint32_t*>(&h);
    lo = *reinterpret_cast<uint32_t*>(&l);
}

// ======================= bf16x3 mma.sync GEMM (champion core) ===============
// OM: 0 = fp32 out, 1 = fp32 out + residual, 2 = bf16 hi/lo out (scaled),
//     3 = fused silu(even)*odd -> bf16 hi/lo out at column c/2 (Nout = N/2)
#define RB    144
#define ATILE (256*RB)
#define BTILE (128*RB)
#define STG   (2*ATILE + 2*BTILE)  // 110592
#define GEMM_SMEM (2*STG)          // 221184

template<int OM>
__global__ __launch_bounds__(256) void gemm3bf(
    const __nv_bfloat16* __restrict__ Ahi, const __nv_bfloat16* __restrict__ Alo,
    const __nv_bfloat16* __restrict__ Bhi, const __nv_bfloat16* __restrict__ Blo,
    const float* __restrict__ R, float* __restrict__ C,
    __nv_bfloat16* __restrict__ Ch, __nv_bfloat16* __restrict__ Cl,
    float scale, int M, int N, int K)
{
    extern __shared__ char sm[];
    const uint32_t sbase = smem_u32(sm);

    const int tid = threadIdx.x;
    const int lane = tid & 31;
    const int wid = tid >> 5;
    const int g = lane >> 2, tig = lane & 3;
    const int warp_m = wid & 3;
    const int warp_n = wid >> 2;
    const int bm = blockIdx.y * 256;
    const int bn = blockIdx.x * 128;

    const int crow = tid >> 3;
    const int ccolB = (tid & 7) * 16;

    const int S = K >> 6;

    auto load_stage = [&](int s) {
        const uint32_t b = sbase + (uint32_t)(s & 1) * STG;
        const int k0 = s << 6;
        const size_t ga = ((size_t)(bm + crow) * K + k0) * 2 + ccolB;
        const size_t gb = ((size_t)(bn + crow) * K + k0) * 2 + ccolB;
        const size_t rstep = (size_t)32 * K * 2;
        const char* pah = (const char*)Ahi + ga;
        const char* pal = (const char*)Alo + ga;
        const char* pbh = (const char*)Bhi + gb;
        const char* pbl = (const char*)Blo + gb;
        #pragma unroll
        for (int i = 0; i < 8; i++) {
            const uint32_t so = (uint32_t)((crow + 32*i) * RB + ccolB);
            cp16(b + so,         pah); pah += rstep;
            cp16(b + ATILE + so, pal); pal += rstep;
        }
        #pragma unroll
        for (int i = 0; i < 4; i++) {
            const uint32_t so = (uint32_t)((crow + 32*i) * RB + ccolB);
            cp16(b + 2*ATILE + so,         pbh); pbh += rstep;
            cp16(b + 2*ATILE + BTILE + so, pbl); pbl += rstep;
        }
        CP_COMMIT();
    };

    load_stage(0);
    if (S > 1) load_stage(1);

    float acc[4][8][4];
    #pragma unroll
    for (int mt = 0; mt < 4; mt++)
        #pragma unroll
        for (int nt = 0; nt < 8; nt++)
            #pragma unroll
            for (int e = 0; e < 4; e++) acc[mt][nt][e] = 0.f;

    const int arow0 = warp_m * 64 + g;
    const int brow0 = warp_n * 64 + g;

    for (int s = 0; s < S; ++s) {
        if (s + 1 < S) { CP_WAIT(1); } else { CP_WAIT(0); }
        __syncthreads();
        const char* b = sm + (size_t)(s & 1) * STG;

        #pragma unroll
        for (int ks = 0; ks < 4; ++ks) {
            const int kb = ks * 32 + tig * 4;

            uint32_t bhf[8][2], blf[8][2];
            #pragma unroll
            for (int nt = 0; nt < 8; nt++) {
                const char* rb = b + 2*ATILE + (brow0 + nt*8) * RB + kb;
                bhf[nt][0] = *(const uint32_t*)(rb);
                bhf[nt][1] = *(const uint32_t*)(rb + 16);
                blf[nt][0] = *(const uint32_t*)(rb + BTILE);
                blf[nt][1] = *(const uint32_t*)(rb + BTILE + 16);
            }

            #pragma unroll
            for (int mt = 0; mt < 4; mt++) {
                uint32_t ah[4], al[4];
                const char* ra = b + (arow0 + mt*16) * RB + kb;
                ah[0] = *(const uint32_t*)(ra);
                ah[1] = *(const uint32_t*)(ra + 8*RB);
                ah[2] = *(const uint32_t*)(ra + 16);
                ah[3] = *(const uint32_t*)(ra + 8*RB + 16);
                al[0] = *(const uint32_t*)(ra + ATILE);
                al[1] = *(const uint32_t*)(ra + ATILE + 8*RB);
                al[2] = *(const uint32_t*)(ra + ATILE + 16);
                al[3] = *(const uint32_t*)(ra + ATILE + 8*RB + 16);

                #pragma unroll
                for (int nt = 0; nt < 8; nt++)
                    mma_bf16(acc[mt][nt], ah, bhf[nt]);
                #pragma unroll
                for (int nt = 0; nt < 8; nt++)
                    mma_bf16(acc[mt][nt], ah, blf[nt]);
                #pragma unroll
                for (int nt = 0; nt < 8; nt++)
                    mma_bf16(acc[mt][nt], al, bhf[nt]);
            }
        }
        __syncthreads();
        if (s + 2 < S) load_stage(s + 2);
    }

    const int row0 = bm + warp_m*64 + g;
    const int col0 = bn + warp_n*64 + tig*2;
    #pragma unroll
    for (int mt = 0; mt < 4; mt++) {
        #pragma unroll
        for (int nt = 0; nt < 8; nt++) {
            const int r = row0 + mt*16;
            const int c = col0 + nt*8;
            if (OM == 3) {
                const int Nout = N >> 1;
                const int cc = c >> 1;
                const float g0 = acc[mt][nt][0], u0 = acc[mt][nt][1];
                const float g1 = acc[mt][nt][2], u1 = acc[mt][nt][3];
                const float r0 = g0 / (1.f + __expf(-g0)) * u0;
                const float r1 = g1 / (1.f + __expf(-g1)) * u1;
                const __nv_bfloat16 h0 = __float2bfloat16(r0);
                const __nv_bfloat16 h1 = __float2bfloat16(r1);
                Ch[(size_t)r * Nout + cc]     = h0;
                Cl[(size_t)r * Nout + cc]     = __float2bfloat16(r0 - __bfloat162float(h0));
                Ch[(size_t)(r+8) * Nout + cc] = h1;
                Cl[(size_t)(r+8) * Nout + cc] = __float2bfloat16(r1 - __bfloat162float(h1));
            } else if (OM == 2) {
                uint32_t h0, l0u, h1, l1u;
                split2(acc[mt][nt][0]*scale, acc[mt][nt][1]*scale, h0, l0u);
                split2(acc[mt][nt][2]*scale, acc[mt][nt][3]*scale, h1, l1u);
                *(uint32_t*)(Ch + (size_t)r * N + c)     = h0;
                *(uint32_t*)(Cl + (size_t)r * N + c)     = l0u;
                *(uint32_t*)(Ch + (size_t)(r+8) * N + c) = h1;
                *(uint32_t*)(Cl + (size_t)(r+8) * N + c) = l1u;
            } else {
                float2 v0 = make_float2(acc[mt][nt][0], acc[mt][nt][1]);
                float2 v1 = make_float2(acc[mt][nt][2], acc[mt][nt][3]);
                if (OM == 1) {
                    const float2 r0 = *(const float2*)(R + (size_t)r * N + c);
                    const float2 r1 = *(const float2*)(R + (size_t)(r+8) * N + c);
                    v0.x += r0.x; v0.y += r0.y;
                    v1.x += r1.x; v1.y += r1.y;
                }
                *(float2*)(C + (size_t)r * N + c)     = v0;
                *(float2*)(C + (size_t)(r+8) * N + c) = v1;
            }
        }
    }
}

// ======================= tensor-core causal flash attention =================
#define RBQ 272
#define RBV 144
#define QT_BYTES (128*RBQ)
#define KT_BYTES (64*RBQ)
#define VT_BYTES (128*RBV)
#define STAGE_B  (2*KT_BYTES + 2*VT_BYTES)
#define ATTN_SMEM (2*QT_BYTES + 2*STAGE_B)

__global__ __launch_bounds__(256) void attn_mma_k(
    const __nv_bfloat16* __restrict__ qh, const __nv_bfloat16* __restrict__ ql,
    const __nv_bfloat16* __restrict__ kh, const __nv_bfloat16* __restrict__ kl,
    const __nv_bfloat16* __restrict__ vh, const __nv_bfloat16* __restrict__ vl,
    __nv_bfloat16* __restrict__ Oh, __nv_bfloat16* __restrict__ Ol, int hOff)
{
    extern __shared__ char sm[];
    const uint32_t sb = smem_u32(sm);

    const int tid = threadIdx.x, lane = tid & 31, wid = tid >> 5;
    const int g = lane >> 2, tig = lane & 3;
    const int qt = 15 - blockIdx.x, h = blockIdx.y + hOff, b = blockIdx.z;
    const int ntiles = 2 * (qt + 1);

    {
        const size_t gq = ((size_t)(b*2048 + qt*128) * 2048 + h*128) * 2;
        #pragma unroll
        for (int i = 0; i < 16; i++) {
            const int c = tid + i*256;
            const int t = c >> 11;
            const int cc = c & 2047;
            const int row = cc >> 4, col = cc & 15;
            const char* gp = (const char*)(t ? ql : qh) + gq + (size_t)row*4096 + col*16;
            cp16(sb + (t ? QT_BYTES : 0) + row*RBQ + col*16, gp);
        }
        CP_COMMIT();
    }

    auto load_stage = [&](int kt) {
        const uint32_t base = sb + 2*QT_BYTES + (uint32_t)(kt & 1) * STAGE_B;
        const size_t gk = ((size_t)(b*2048 + kt*64) * 2048 + h*128) * 2;
        const size_t gv = (((size_t)((b*16 + h)*128)) * 2048 + kt*64) * 2;
        #pragma unroll
        for (int i = 0; i < 16; i++) {
            const int c = tid + i*256;
            const int sel = c >> 10;
            const int cc = c & 1023;
            if (sel < 2) {
                const int row = cc >> 4, col = cc & 15;
                const char* gp = (const char*)(sel ? kl : kh) + gk + (size_t)row*4096 + col*16;
                cp16(base + (sel ? KT_BYTES : 0) + row*RBQ + col*16, gp);
            } else {
                const int row = cc >> 3, col = cc & 7;
                const char* gp = (const char*)(sel == 3 ? vl : vh) + gv + (size_t)row*4096 + col*16;
                cp16(base + 2*KT_BYTES + (sel == 3 ? VT_BYTES : 0) + row*RBV + col*16, gp);
            }
        }
        CP_COMMIT();
    };

    load_stage(0);
    load_stage(1);

    float accO[16][4];
    #pragma unroll
    for (int nt = 0; nt < 16; nt++)
        #pragma unroll
        for (int e = 0; e < 4; e++) accO[nt][e] = 0.f;
    float m0 = -INFINITY, m1 = -INFINITY, l0 = 0.f, l1 = 0.f;

    const int row0 = wid * 16;
    const int qrow0 = qt*128 + row0 + g;

    for (int s = 0; s < ntiles; s++) {
        if (s + 1 < ntiles) { CP_WAIT(1); } else { CP_WAIT(0); }
        __syncthreads();
        const char* stg = sm + 2*QT_BYTES + (size_t)(s & 1) * STAGE_B;

        float accS[8][4];
        #pragma unroll
        for (int nt = 0; nt < 8; nt++)
            #pragma unroll
            for (int e = 0; e < 4; e++) accS[nt][e] = 0.f;

        #pragma unroll
        for (int ks = 0; ks < 8; ks++) {
            const int kb = ks*32 + tig*4;
            uint32_t ah[4], al[4], bh2[8][2], bl2[8][2];
            const char* ra = sm + (row0 + g)*RBQ + kb;
            ah[0] = *(const uint32_t*)(ra);
            ah[1] = *(const uint32_t*)(ra + 8*RBQ);
            ah[2] = *(const uint32_t*)(ra + 16);
            ah[3] = *(const uint32_t*)(ra + 8*RBQ + 16);
            al[0] = *(const uint32_t*)(ra + QT_BYTES);
            al[1] = *(const uint32_t*)(ra + QT_BYTES + 8*RBQ);
            al[2] = *(const uint32_t*)(ra + QT_BYTES + 16);
            al[3] = *(const uint32_t*)(ra + QT_BYTES + 8*RBQ + 16);
            #pragma unroll
            for (int nt = 0; nt < 8; nt++) {
                const char* rb = stg + (nt*8 + g)*RBQ + kb;
                bh2[nt][0] = *(const uint32_t*)(rb);
                bh2[nt][1] = *(const uint32_t*)(rb + 16);
                bl2[nt][0] = *(const uint32_t*)(rb + KT_BYTES);
                bl2[nt][1] = *(const uint32_t*)(rb + KT_BYTES + 16);
            }
            #pragma unroll
            for (int nt = 0; nt < 8; nt++) mma_bf16(accS[nt], ah, bh2[nt]);
            #pragma unroll
            for (int nt = 0; nt < 8; nt++) mma_bf16(accS[nt], ah, bl2[nt]);
            #pragma unroll
            for (int nt = 0; nt < 8; nt++) mma_bf16(accS[nt], al, bh2[nt]);
        }

        if (s >= ntiles - 2) {
            #pragma unroll
            for (int nt = 0; nt < 8; nt++) {
                const int col = s*64 + nt*8 + tig*2;
                if (col     > qrow0)     accS[nt][0] = -INFINITY;
                if (col + 1 > qrow0)     accS[nt][1] = -INFINITY;
                if (col     > qrow0 + 8) accS[nt][2] = -INFINITY;
                if (col + 1 > qrow0 + 8) accS[nt][3] = -INFINITY;
            }
        }

        float mt0 = -INFINITY, mt1 = -INFINITY;
        #pragma unroll
        for (int nt = 0; nt < 8; nt++) {
            mt0 = fmaxf(mt0, fmaxf(accS[nt][0], accS[nt][1]));
            mt1 = fmaxf(mt1, fmaxf(accS[nt][2], accS[nt][3]));
        }
        mt0 = fmaxf(mt0, __shfl_xor_sync(0xffffffffu, mt0, 1));
        mt0 = fmaxf(mt0, __shfl_xor_sync(0xffffffffu, mt0, 2));
        mt1 = fmaxf(mt1, __shfl_xor_sync(0xffffffffu, mt1, 1));
        mt1 = fmaxf(mt1, __shfl_xor_sync(0xffffffffu, mt1, 2));

        const float mn0 = fmaxf(m0, mt0), mn1 = fmaxf(m1, mt1);
        const float sc0 = __expf(m0 - mn0), sc1 = __expf(m1 - mn1);
        m0 = mn0; m1 = mn1;

        float rs0 = 0.f, rs1 = 0.f;
        #pragma unroll
        for (int nt = 0; nt < 8; nt++) {
            accS[nt][0] = __expf(accS[nt][0] - mn0);
            accS[nt][1] = __expf(accS[nt][1] - mn0);
            accS[nt][2] = __expf(accS[nt][2] - mn1);
            accS[nt][3] = __expf(accS[nt][3] - mn1);
            rs0 += accS[nt][0] + accS[nt][1];
            rs1 += accS[nt][2] + accS[nt][3];
        }
        rs0 += __shfl_xor_sync(0xffffffffu, rs0, 1);
        rs0 += __shfl_xor_sync(0xffffffffu, rs0, 2);
        rs1 += __shfl_xor_sync(0xffffffffu, rs1, 1);
        rs1 += __shfl_xor_sync(0xffffffffu, rs1, 2);
        l0 = l0*sc0 + rs0;
        l1 = l1*sc1 + rs1;

        #pragma unroll
        for (int nt = 0; nt < 16; nt++) {
            accO[nt][0] *= sc0; accO[nt][1] *= sc0;
            accO[nt][2] *= sc1; accO[nt][3] *= sc1;
        }

        #pragma unroll
        for (int kk = 0; kk < 4; kk++) {
            uint32_t ph[4], pl[4];
            split2(accS[2*kk][0],   accS[2*kk][1],   ph[0], pl[0]);
            split2(accS[2*kk][2],   accS[2*kk][3],   ph[1], pl[1]);
            split2(accS[2*kk+1][0], accS[2*kk+1][1], ph[2], pl[2]);
            split2(accS[2*kk+1][2], accS[2*kk+1][3], ph[3], pl[3]);
            const int kb = kk*32 + tig*4;
            #pragma unroll
            for (int nt = 0; nt < 16; nt++) {
                const char* rv = stg + 2*KT_BYTES + (nt*8 + g)*RBV + kb;
                uint32_t vbh[2], vbl[2];
                vbh[0] = *(const uint32_t*)(rv);
                vbh[1] = *(const uint32_t*)(rv + 16);
                vbl[0] = *(const uint32_t*)(rv + VT_BYTES);
                vbl[1] = *(const uint32_t*)(rv + VT_BYTES + 16);
                mma_bf16(accO[nt], ph, vbh);
                mma_bf16(accO[nt], ph, vbl);
                mma_bf16(accO[nt], pl, vbh);
            }
        }

        __syncthreads();
        if (s + 2 < ntiles) load_stage(s + 2);
    }

    const float inv0 = 1.f / l0, inv1 = 1.f / l1;
    const size_t ob = ((size_t)(b*2048 + qt*128 + row0 + g)) * 2048 + h*128;
    #pragma unroll
    for (int nt = 0; nt < 16; nt++) {
        const int c = nt*8 + tig*2;
        uint32_t h0, l0u, h1, l1u;
        split2(accO[nt][0]*inv0, accO[nt][1]*inv0, h0, l0u);
        split2(accO[nt][2]*inv1, accO[nt][3]*inv1, h1, l1u);
        *(uint32_t*)(Oh + ob + c)           = h0;
        *(uint32_t*)(Ol + ob + c)           = l0u;
        *(uint32_t*)(Oh + ob + 8*2048 + c)  = h1;
        *(uint32_t*)(Ol + ob + 8*2048 + c)  = l1u;
    }
}

// ======================= batched weight transpose + split ====================
struct TCJob  { const float* W; __nv_bfloat16* Th; __nv_bfloat16* Tl; int rowOff; };
struct TCJobs { TCJob j[4]; };

__global__ void transconv64_k(TCJobs jobs, int K, int N, int rowStride)
{
    const TCJob jb = jobs.j[blockIdx.z];
    __shared__ float t[64][65];
    const int n0 = blockIdx.x * 64, k0 = blockIdx.y * 64;
    const int tx = threadIdx.x, ty = threadIdx.y;   // (32, 8)
    #pragma unroll
    for (int r = ty; r < 64; r += 8) {
        const float2 v = *(const float2*)(jb.W + (size_t)(k0 + r) * N + n0 + 2*tx);
        t[r][2*tx]   = v.x;
        t[r][2*tx+1] = v.y;
    }
    __syncthreads();
    #pragma unroll
    for (int i = ty; i < 64; i += 8) {
        uint32_t hi, lo;
        split2(t[2*tx][i], t[2*tx+1][i], hi, lo);
        const size_t o = ((size_t)(n0 + i) * rowStride + jb.rowOff) * K + k0 + 2*tx;
        *(uint32_t*)(jb.Th + o) = hi;
        *(uint32_t*)(jb.Tl + o) = lo;
    }
}

// ======================= V transpose (64x64, u32 I/O, head-group) ===========
__global__ void vtrans64_k(const __nv_bfloat16* __restrict__ Vh,
                           const __nv_bfloat16* __restrict__ Vl,
                           __nv_bfloat16* __restrict__ Th, __nv_bfloat16* __restrict__ Tl,
                           int hOff)
{
    __shared__ __nv_bfloat16 th[64][66], tl[64][66];
    const int kv0 = blockIdx.x * 64, hd0 = blockIdx.y * 64;
    const int b = blockIdx.z >> 3, h = (blockIdx.z & 7) + hOff;
    const int bh = b*16 + h;
    const int tx = threadIdx.x, ty = threadIdx.y;      // (32, 8)
    #pragma unroll
    for (int r = ty; r < 64; r += 8) {
        const size_t src = (size_t)(b*2048 + kv0 + r) * 2048 + h*128 + hd0 + 2*tx;
        *(uint32_t*)&th[r][2*tx] = *(const uint32_t*)(Vh + src);
        *(uint32_t*)&tl[r][2*tx] = *(const uint32_t*)(Vl + src);
    }
    __syncthreads();
    #pragma unroll
    for (int i = ty; i < 64; i += 8) {
        __nv_bfloat162 ph, pl;
        ph.x = th[2*tx][i]; ph.y = th[2*tx+1][i];
        pl.x = tl[2*tx][i]; pl.y = tl[2*tx+1][i];
        const size_t o = ((size_t)(bh*128 + hd0 + i)) * 2048 + kv0 + 2*tx;
        *(uint32_t*)(Th + o) = *(uint32_t*)&ph;
        *(uint32_t*)(Tl + o) = *(uint32_t*)&pl;
    }
}

// ======================= RMSNorm: warp-per-row, barrier-free ================
__global__ __launch_bounds__(256) void rmsnorm_warp_k(
    const float* __restrict__ x, const float* __restrict__ w,
    __nv_bfloat16* __restrict__ yh, __nv_bfloat16* __restrict__ yl)
{
    const int row  = blockIdx.x * 8 + (threadIdx.x >> 5);
    const int lane = threadIdx.x & 31;
    const float4* xr = (const float4*)(x + (size_t)row * HID);
    const float4* w4 = (const float4*)w;

    float ss = 0.f;
    #pragma unroll
    for (int i = 0; i < 16; i++) {
        const float4 v = xr[i*32 + lane];
        ss += v.x*v.x + v.y*v.y + v.z*v.z + v.w*v.w;
    }
    #pragma unroll
    for (int off = 16; off > 0; off >>= 1)
        ss += __shfl_xor_sync(0xffffffffu, ss, off);
    const float inv = rsqrtf(ss * (1.f / (float)HID) + 1e-6f);

    #pragma unroll
    for (int i = 0; i < 16; i++) {
        const float4 v = xr[i*32 + lane];
        const float4 ww = w4[i*32 + lane];
        const float o0 = v.x*inv*ww.x, o1 = v.y*inv*ww.y;
        const float o2 = v.z*inv*ww.z, o3 = v.w*inv*ww.w;
        uint32_t h0, l0, h1, l1;
        split2(o0, o1, h0, l0);
        split2(o2, o3, h1, l1);
        const size_t base = (size_t)row * HID + (size_t)(i*32 + lane) * 4;
        uint2 vh = make_uint2(h0, h1), vl = make_uint2(l0, l1);
        *(uint2*)(yh + base) = vh;
        *(uint2*)(yl + base) = vl;
    }
}

// ======================= launch =============================================
extern "C" void kernel_launch(void* const* d_in, const int* in_sizes, int n_in,
                              void* d_out, int out_size)
{
    const float* hidden = (const float*)d_in[0];
    const float* wq  = (const float*)d_in[1];
    const float* wk  = (const float*)d_in[2];
    const float* wv  = (const float*)d_in[3];
    const float* wo  = (const float*)d_in[4];
    const float* wg  = (const float*)d_in[5];
    const float* wu  = (const float*)d_in[6];
    const float* wd  = (const float*)d_in[7];
    const float* ln1 = (const float*)d_in[8];
    const float* ln2 = (const float*)d_in[9];

    __nv_bfloat16 *pwq_h,*pwq_l,*pwk_h,*pwk_l,*pwv_h,*pwv_l,*pwo_h,*pwo_l;
    __nv_bfloat16 *pwgu_h,*pwgu_l,*pwd_h,*pwd_l;
    __nv_bfloat16 *px_h,*px_l,*pat_h,*pat_l,*pm_h,*pm_l;
    __nv_bfloat16 *pq_h,*pq_l,*pk_h,*pk_l,*pv_h,*pv_l,*pvt_h,*pvt_l;
    float *h1;
    cudaGetSymbolAddress((void**)&pwq_h, w_q_hi); cudaGetSymbolAddress((void**)&pwq_l, w_q_lo);
    cudaGetSymbolAddress((void**)&pwk_h, w_k_hi); cudaGetSymbolAddress((void**)&pwk_l, w_k_lo);
    cudaGetSymbolAddress((void**)&pwv_h, w_v_hi); cudaGetSymbolAddress((void**)&pwv_l, w_v_lo);
    cudaGetSymbolAddress((void**)&pwo_h, w_o_hi); cudaGetSymbolAddress((void**)&pwo_l, w_o_lo);
    cudaGetSymbolAddress((void**)&pwgu_h, w_gu_hi); cudaGetSymbolAddress((void**)&pwgu_l, w_gu_lo);
    cudaGetSymbolAddress((void**)&pwd_h, w_d_hi); cudaGetSymbolAddress((void**)&pwd_l, w_d_lo);
    cudaGetSymbolAddress((void**)&px_h,  a_x_hi); cudaGetSymbolAddress((void**)&px_l,  a_x_lo);
    cudaGetSymbolAddress((void**)&pat_h, a_at_hi);cudaGetSymbolAddress((void**)&pat_l, a_at_lo);
    cudaGetSymbolAddress((void**)&pm_h,  a_m_hi); cudaGetSymbolAddress((void**)&pm_l,  a_m_lo);
    cudaGetSymbolAddress((void**)&pq_h,  q_bhi);  cudaGetSymbolAddress((void**)&pq_l,  q_blo);
    cudaGetSymbolAddress((void**)&pk_h,  k_bhi);  cudaGetSymbolAddress((void**)&pk_l,  k_blo);
    cudaGetSymbolAddress((void**)&pv_h,  v_bhi);  cudaGetSymbolAddress((void**)&pv_l,  v_blo);
    cudaGetSymbolAddress((void**)&pvt_h, vt_hi);  cudaGetSymbolAddress((void**)&pvt_l, vt_lo);
    cudaGetSymbolAddress((void**)&h1, s_h1);

    cudaFuncSetAttribute(gemm3bf<0>, cudaFuncAttributeMaxDynamicSharedMemorySize, GEMM_SMEM);
    cudaFuncSetAttribute(gemm3bf<1>, cudaFuncAttributeMaxDynamicSharedMemorySize, GEMM_SMEM);
    cudaFuncSetAttribute(gemm3bf<2>, cudaFuncAttributeMaxDynamicSharedMemorySize, GEMM_SMEM);
    cudaFuncSetAttribute(gemm3bf<3>, cudaFuncAttributeMaxDynamicSharedMemorySize, GEMM_SMEM);
    cudaFuncSetAttribute(attn_mma_k, cudaFuncAttributeMaxDynamicSharedMemorySize, ATTN_SMEM);

    static cudaStream_t st1 = nullptr, st2 = nullptr;
    static cudaEvent_t evS, evW1, evW2, evX, evQA, evQB, evKA, evVB, evAA, evAB, evDB;
    if (st1 == nullptr) {
        cudaStreamCreateWithFlags(&st1, cudaStreamNonBlocking);
        cudaStreamCreateWithFlags(&st2, cudaStreamNonBlocking);
        cudaEventCreateWithFlags(&evS,  cudaEventDisableTiming);
        cudaEventCreateWithFlags(&evW1, cudaEventDisableTiming);
        cudaEventCreateWithFlags(&evW2, cudaEventDisableTiming);
        cudaEventCreateWithFlags(&evX,  cudaEventDisableTiming);
        cudaEventCreateWithFlags(&evQA, cudaEventDisableTiming);
        cudaEventCreateWithFlags(&evQB, cudaEventDisableTiming);
        cudaEventCreateWithFlags(&evKA, cudaEventDisableTiming);
        cudaEventCreateWithFlags(&evVB, cudaEventDisableTiming);
        cudaEventCreateWithFlags(&evAA, cudaEventDisableTiming);
        cudaEventCreateWithFlags(&evAB, cudaEventDisableTiming);
        cudaEventCreateWithFlags(&evDB, cudaEventDisableTiming);
    }

    dim3 tb(32, 8);
    const float sc = 0.08838834764831845f;
    const dim3 gHalf(8, MTOK/256);       // half-N projection grid
    const dim3 gMH(HID/128, 8);          // half-M, N=2048 grid
    const dim3 gMHgu(2*INTER/128, 8);    // half-M, N=16384 grid
    const size_t wHalf = (size_t)1024 * HID;
    const size_t mo = 2048;              // M-half row offset

    // fork
    cudaEventRecord(evS, 0);
    cudaStreamWaitEvent(st1, evS, 0);
    cudaStreamWaitEvent(st2, evS, 0);

    // --- legacy: convert wq/wk/wv
    {
        TCJobs jqkv;
        jqkv.j[0] = { wq, pwq_h, pwq_l, 0 };
        jqkv.j[1] = { wk, pwk_h, pwk_l, 0 };
        jqkv.j[2] = { wv, pwv_h, pwv_l, 0 };
        jqkv.j[3] = jqkv.j[0];
        transconv64_k<<<dim3(HID/64, HID/64, 3), tb>>>(jqkv, HID, HID, 1);
    }
    cudaEventRecord(evW1, 0);

    // --- st1: rmsnorm1, Q halves, V-B + vtrans-B, then deferred weight convs
    rmsnorm_warp_k<<<MTOK/8, 256, 0, st1>>>(hidden, ln1, px_h, px_l);
    cudaEventRecord(evX, st1);
    cudaStreamWaitEvent(st1, evW1, 0);
    gemm3bf<2><<<gHalf, 256, GEMM_SMEM, st1>>>(px_h, px_l, pwq_h, pwq_l, nullptr, nullptr,
                                               pq_h, pq_l, sc, MTOK, HID, HID);
    cudaEventRecord(evQA, st1);
    gemm3bf<2><<<gHalf, 256, GEMM_SMEM, st1>>>(px_h, px_l, pwq_h + wHalf, pwq_l + wHalf,
                                               nullptr, nullptr,
                                               pq_h + 1024, pq_l + 1024, sc, MTOK, HID, HID);
    cudaEventRecord(evQB, st1);
    gemm3bf<2><<<gHalf, 256, GEMM_SMEM, st1>>>(px_h, px_l, pwv_h + wHalf, pwv_l + wHalf,
                                               nullptr, nullptr,
                                               pv_h + 1024, pv_l + 1024, 1.f, MTOK, HID, HID);
    vtrans64_k<<<dim3(32, 2, 16), tb, 0, st1>>>(pv_h, pv_l, pvt_h, pvt_l, 8);
    cudaEventRecord(evVB, st1);
    {
        TCJobs jo;
        jo.j[0] = { wo, pwo_h, pwo_l, 0 };
        jo.j[1] = jo.j[0]; jo.j[2] = jo.j[0]; jo.j[3] = jo.j[0];
        transconv64_k<<<dim3(HID/64, HID/64, 1), tb, 0, st1>>>(jo, HID, HID, 1);

        TCJobs jgu;
        jgu.j[0] = { wg, pwgu_h, pwgu_l, 0 };
        jgu.j[1] = { wu, pwgu_h, pwgu_l, 1 };
        jgu.j[2] = jgu.j[0]; jgu.j[3] = jgu.j[0];
        transconv64_k<<<dim3(INTER/64, HID/64, 2), tb, 0, st1>>>(jgu, HID, INTER, 2);

        TCJobs jd;
        jd.j[0] = { wd, pwd_h, pwd_l, 0 };
        jd.j[1] = jd.j[0]; jd.j[2] = jd.j[0]; jd.j[3] = jd.j[0];
        transconv64_k<<<dim3(HID/64, INTER/64, 1), tb, 0, st1>>>(jd, INTER, HID, 1);
    }
    cudaEventRecord(evW2, st1);

    // --- st2: K halves, then attn-B when its inputs are ready
    cudaStreamWaitEvent(st2, evW1, 0);
    cudaStreamWaitEvent(st2, evX, 0);
    gemm3bf<2><<<gHalf, 256, GEMM_SMEM, st2>>>(px_h, px_l, pwk_h, pwk_l, nullptr, nullptr,
                                               pk_h, pk_l, 1.f, MTOK, HID, HID);
    cudaEventRecord(evKA, st2);
    gemm3bf<2><<<gHalf, 256, GEMM_SMEM, st2>>>(px_h, px_l, pwk_h + wHalf, pwk_l + wHalf,
                                               nullptr, nullptr,
                                               pk_h + 1024, pk_l + 1024, 1.f, MTOK, HID, HID);
    cudaStreamWaitEvent(st2, evQB, 0);
    cudaStreamWaitEvent(st2, evVB, 0);
    attn_mma_k<<<dim3(16, 8, 2), 256, ATTN_SMEM, st2>>>(pq_h, pq_l, pk_h, pk_l,
                                                        pvt_h, pvt_l, pat_h, pat_l, 8);
    cudaEventRecord(evAB, st2);

    // --- legacy: V-A, vtrans-A, attn-A
    cudaStreamWaitEvent(0, evX, 0);
    gemm3bf<2><<<gHalf, 256, GEMM_SMEM>>>(px_h, px_l, pwv_h, pwv_l, nullptr, nullptr,
                                          pv_h, pv_l, 1.f, MTOK, HID, HID);
    vtrans64_k<<<dim3(32, 2, 16), tb>>>(pv_h, pv_l, pvt_h, pvt_l, 0);
    cudaStreamWaitEvent(0, evQA, 0);
    cudaStreamWaitEvent(0, evKA, 0);
    attn_mma_k<<<dim3(16, 8, 2), 256, ATTN_SMEM>>>(pq_h, pq_l, pk_h, pk_l,
                                                   pvt_h, pvt_l, pat_h, pat_l, 0);
    cudaEventRecord(evAA, 0);

    // ================= M-split pipelined MLP tail =================
    // half-B chain on st2 (needs attn-A + attn-B + weights)
    cudaStreamWaitEvent(st2, evAA, 0);
    cudaStreamWaitEvent(st2, evW2, 0);
    gemm3bf<1><<<gMH, 256, GEMM_SMEM, st2>>>(
        pat_h + mo*HID, pat_l + mo*HID, pwo_h, pwo_l,
        hidden + mo*HID, h1 + mo*HID, nullptr, nullptr, 1.f, 2048, HID, HID);
    rmsnorm_warp_k<<<256, 256, 0, st2>>>(h1 + mo*HID, ln2, px_h + mo*HID, px_l + mo*HID);
    gemm3bf<3><<<gMHgu, 256, GEMM_SMEM, st2>>>(
        px_h + mo*HID, px_l + mo*HID, pwgu_h, pwgu_l, nullptr, nullptr,
        pm_h + mo*INTER, pm_l + mo*INTER, 1.f, 2048, 2*INTER, HID);
    gemm3bf<1><<<gMH, 256, GEMM_SMEM, st2>>>(
        pm_h + mo*INTER, pm_l + mo*INTER, pwd_h, pwd_l,
        h1 + mo*HID, (float*)d_out + mo*HID, nullptr, nullptr, 1.f, 2048, HID, INTER);
    cudaEventRecord(evDB, st2);

    // half-A chain on legacy (needs attn-B + weights)
    cudaStreamWaitEvent(0, evAB, 0);
    cudaStreamWaitEvent(0, evW2, 0);
    gemm3bf<1><<<gMH, 256, GEMM_SMEM>>>(
        pat_h, pat_l, pwo_h, pwo_l, hidden, h1,
        nullptr, nullptr, 1.f, 2048, HID, HID);
    rmsnorm_warp_k<<<256, 256>>>(h1, ln2, px_h, px_l);
    gemm3bf<3><<<gMHgu, 256, GEMM_SMEM>>>(
        px_h, px_l, pwgu_h, pwgu_l, nullptr, nullptr,
        pm_h, pm_l, 1.f, 2048, 2*INTER, HID);
    gemm3bf<1><<<gMH, 256, GEMM_SMEM>>>(
        pm_h, pm_l, pwd_h, pwd_l, h1, (float*)d_out,
        nullptr, nullptr, 1.f, 2048, HID, INTER);

    // join half-B before capture end
    cudaStreamWaitEvent(0, evDB, 0);
}